// round 1
// baseline (speedup 1.0000x reference)
#include <cuda_runtime.h>
#include <math.h>

// Problem dims
#define Dm    1024
#define Cm    2048
#define MLPm  4096
#define Hh    16
#define HDh   64
#define Bb    8
#define Nn    512
#define Ss    2048
#define INNER (Hh*HDh)   // 1024
#define EPSf  1e-6f

// ---------------- scratch (static device allocations; no runtime alloc) ---------
__device__ __align__(16) float d_mods  [3 * Bb * 3 * Dm];          // mod = cond@mw^T+mb, per norm
__device__ __align__(16) float d_normed[Bb * Nn * Dm];
__device__ __align__(16) float d_q     [Bb * Nn * INNER];
__device__ __align__(16) float d_k     [Bb * Ss * INNER];
__device__ __align__(16) float d_v     [Bb * Ss * INNER];
__device__ __align__(16) float d_scores[(size_t)Bb * Hh * Nn * Ss]; // 512 MB, reused SA/CA
__device__ __align__(16) float d_attno [Bb * Nn * INNER];
__device__ __align__(16) float d_x1    [Bb * Nn * Dm];
__device__ __align__(16) float d_x2    [Bb * Nn * Dm];
__device__ __align__(16) float d_gbuf  [Bb * Nn * MLPm];
__device__ __align__(16) float d_ubuf  [Bb * Nn * MLPm];
__device__ __align__(16) float d_hbuf  [Bb * Nn * MLPm];

// ---------------- generic tiled SGEMM ------------------------------------------
// C(M,N) = A(M,K) @ op(B) ; TB=true: B is (N,K) row-major (C=A@B^T), else B is (K,N).
// Batched via blockIdx.z: off = (z/nInner)*s?o + (z%nInner)*s?i.
// EPI==1: C = resid + gate[(row/rows_per_b)*gate_ld + col] * acc  (resid same geometry as C)
template<int BM,int BN,int BK,int TM,int TN,bool TB,int EPI>
__global__ void __launch_bounds__((BM/TM)*(BN/TN))
gemm_kernel(const float* __restrict__ A, const float* __restrict__ Bm, float* __restrict__ C,
            int M, int N, int K, int lda, int ldb, int ldc,
            long sAo, long sAi, long sBo, long sBi, long sCo, long sCi, int nInner,
            const float* __restrict__ resid, const float* __restrict__ gate,
            int gate_ld, int rows_per_b)
{
    int z  = blockIdx.z;
    int zo = z / nInner, zi = z - zo * nInner;
    A  += zo * sAo + zi * sAi;
    Bm += zo * sBo + zi * sBi;
    C  += zo * sCo + zi * sCi;

    __shared__ float As[BK][BM];
    __shared__ float Bs[BK][BN];

    int tid  = threadIdx.x;
    int tx   = tid % (BN/TN);
    int ty   = tid / (BN/TN);
    int row0 = blockIdx.y * BM;
    int col0 = blockIdx.x * BN;

    // A tile: BM x BK, one float4 per thread along K
    int aRow = tid / (BK/4);
    int aCol = (tid % (BK/4)) * 4;
    const float* Aptr = A + (size_t)(row0 + aRow) * lda + aCol;

    int bRow, bCol;
    const float* Bptr;
    if (TB) { bRow = tid / (BK/4); bCol = (tid % (BK/4)) * 4;
              Bptr = Bm + (size_t)(col0 + bRow) * ldb + bCol; }
    else    { bRow = tid / (BN/4); bCol = (tid % (BN/4)) * 4;
              Bptr = Bm + (size_t)bRow * ldb + col0 + bCol; }

    float acc[TM][TN];
    #pragma unroll
    for (int i = 0; i < TM; i++)
        #pragma unroll
        for (int j = 0; j < TN; j++) acc[i][j] = 0.f;

    for (int kt = 0; kt < K; kt += BK) {
        float4 av = *(const float4*)(Aptr + kt);
        As[aCol+0][aRow] = av.x; As[aCol+1][aRow] = av.y;
        As[aCol+2][aRow] = av.z; As[aCol+3][aRow] = av.w;
        if (TB) {
            float4 bv = *(const float4*)(Bptr + kt);
            Bs[bCol+0][bRow] = bv.x; Bs[bCol+1][bRow] = bv.y;
            Bs[bCol+2][bRow] = bv.z; Bs[bCol+3][bRow] = bv.w;
        } else {
            float4 bv = *(const float4*)(Bptr + (size_t)kt * ldb);
            *(float4*)&Bs[bRow][bCol] = bv;
        }
        __syncthreads();

        #pragma unroll
        for (int k = 0; k < BK; k++) {
            float ar[TM], br[TN];
            #pragma unroll
            for (int i = 0; i < TM; i += 4)
                *(float4*)&ar[i] = *(const float4*)&As[k][ty*TM + i];
            #pragma unroll
            for (int j = 0; j < TN; j += 4)
                *(float4*)&br[j] = *(const float4*)&Bs[k][tx*TN + j];
            #pragma unroll
            for (int i = 0; i < TM; i++)
                #pragma unroll
                for (int j = 0; j < TN; j++)
                    acc[i][j] = fmaf(ar[i], br[j], acc[i][j]);
        }
        __syncthreads();
    }

    #pragma unroll
    for (int i = 0; i < TM; i++) {
        int gm = row0 + ty*TM + i;
        #pragma unroll
        for (int j = 0; j < TN; j++) {
            int gn = col0 + tx*TN + j;
            float v = acc[i][j];
            if (EPI == 1)
                v = resid[(size_t)gm * ldc + gn]
                  + gate[(gm / rows_per_b) * gate_ld + gn] * v;
            C[(size_t)gm * ldc + gn] = v;
        }
    }
}

// ---------------- modulation: mods[norm][b][3D] = cond @ mw^T + mb --------------
__global__ void mod_kernel(const float* __restrict__ cond,
                           const float* __restrict__ mw0, const float* __restrict__ mb0,
                           const float* __restrict__ mw1, const float* __restrict__ mb1,
                           const float* __restrict__ mw2, const float* __restrict__ mb2,
                           float* __restrict__ mods)
{
    __shared__ float cs[Bb * Dm];                 // 32 KB
    for (int i = threadIdx.x; i < Bb * Dm; i += blockDim.x) cs[i] = cond[i];
    __syncthreads();

    int warp = threadIdx.x >> 5, lane = threadIdx.x & 31;
    int j = blockIdx.x * 8 + warp;                // 0 .. 3*3D-1
    int norm = j / (3*Dm), jj = j - norm * (3*Dm);
    const float* mw = (norm == 0) ? mw0 : (norm == 1) ? mw1 : mw2;
    const float* mb = (norm == 0) ? mb0 : (norm == 1) ? mb1 : mb2;

    float acc[Bb];
    #pragma unroll
    for (int b = 0; b < Bb; b++) acc[b] = 0.f;
    const float* wrow = mw + (size_t)jj * Dm;
    for (int d = lane; d < Dm; d += 32) {
        float w = wrow[d];
        #pragma unroll
        for (int b = 0; b < Bb; b++) acc[b] = fmaf(w, cs[b*Dm + d], acc[b]);
    }
    #pragma unroll
    for (int b = 0; b < Bb; b++)
        #pragma unroll
        for (int off = 16; off > 0; off >>= 1)
            acc[b] += __shfl_xor_sync(0xffffffff, acc[b], off);
    if (lane < Bb)
        mods[(size_t)norm * Bb * 3*Dm + lane * 3*Dm + jj] = acc[lane] + mb[jj];
}

// ---------------- adaRMS norm: out = x*rsqrt(mean(x^2)+eps)*w*(1+scale)+shift ---
__global__ void rmsnorm_kernel(const float* __restrict__ x, const float* __restrict__ w,
                               const float* __restrict__ mod_base,  // [B][3D], this norm
                               float* __restrict__ out)
{
    int row = blockIdx.x;                // b*N + n
    int b   = row / Nn;
    const float* xr = x + (size_t)row * Dm;
    const float* ms = mod_base + b * 3*Dm;

    float ss = 0.f;
    for (int i = threadIdx.x; i < Dm; i += blockDim.x) { float t = xr[i]; ss = fmaf(t,t,ss); }
    #pragma unroll
    for (int off = 16; off > 0; off >>= 1) ss += __shfl_xor_sync(0xffffffff, ss, off);
    __shared__ float red[8];
    if ((threadIdx.x & 31) == 0) red[threadIdx.x >> 5] = ss;
    __syncthreads();
    if (threadIdx.x < 8) {
        float v = red[threadIdx.x];
        #pragma unroll
        for (int off = 4; off > 0; off >>= 1) v += __shfl_xor_sync(0xff, v, off);
        if (threadIdx.x == 0) red[0] = v;
    }
    __syncthreads();
    float rn = rsqrtf(red[0] * (1.0f/Dm) + EPSf);

    float* orow = out + (size_t)row * Dm;
    for (int i = threadIdx.x; i < Dm; i += blockDim.x) {
        float scale = ms[i], shift = ms[Dm + i];
        orow[i] = xr[i] * rn * w[i] * (1.0f + scale) + shift;
    }
}

// ---------------- row softmax (in place, with pre-scale) ------------------------
__global__ void softmax_kernel(float* __restrict__ sc, int S, float scale)
{
    extern __shared__ float v[];
    float* p = sc + (size_t)blockIdx.x * S;
    int tid = threadIdx.x, nt = blockDim.x;
    __shared__ float red[8];

    float m = -1e30f;
    for (int i = tid; i < S; i += nt) { float x = p[i] * scale; v[i] = x; m = fmaxf(m, x); }
    #pragma unroll
    for (int off = 16; off > 0; off >>= 1) m = fmaxf(m, __shfl_xor_sync(0xffffffff, m, off));
    if ((tid & 31) == 0) red[tid >> 5] = m;
    __syncthreads();
    if (tid < 8) {
        float t = red[tid];
        #pragma unroll
        for (int off = 4; off > 0; off >>= 1) t = fmaxf(t, __shfl_xor_sync(0xff, t, off));
        if (tid == 0) red[0] = t;
    }
    __syncthreads();
    m = red[0];
    __syncthreads();

    float sum = 0.f;
    for (int i = tid; i < S; i += nt) { float e = __expf(v[i] - m); v[i] = e; sum += e; }
    #pragma unroll
    for (int off = 16; off > 0; off >>= 1) sum += __shfl_xor_sync(0xffffffff, sum, off);
    if ((tid & 31) == 0) red[tid >> 5] = sum;
    __syncthreads();
    if (tid < 8) {
        float t = red[tid];
        #pragma unroll
        for (int off = 4; off > 0; off >>= 1) t += __shfl_xor_sync(0xff, t, off);
        if (tid == 0) red[0] = t;
    }
    __syncthreads();
    float inv = 1.0f / red[0];
    for (int i = tid; i < S; i += nt) p[i] = v[i] * inv;
}

// ---------------- silu(g)*u -----------------------------------------------------
__global__ void silu_mul_kernel(const float* __restrict__ g, const float* __restrict__ u,
                                float* __restrict__ h, int n)
{
    int i = blockIdx.x * blockDim.x + threadIdx.x;
    if (i < n) {
        float x = g[i];
        h[i] = (x / (1.0f + __expf(-x))) * u[i];
    }
}

// ---------------- host orchestration -------------------------------------------
static float* sym(const void* s) { void* p = nullptr; cudaGetSymbolAddress(&p, s); return (float*)p; }

// C = A(M,K) @ W(N,K)^T
static void gemm_nt(const float* A, const float* W, float* C, int M, int N, int K,
                    const float* resid, const float* gate, int gate_ld, int rpb)
{
    dim3 grid(N/128, M/128, 1);
    if (resid)
        gemm_kernel<128,128,8,8,8,true,1><<<grid,256>>>(A,W,C,M,N,K,K,K,N,
            0,0,0,0,0,0,1, resid, gate, gate_ld, rpb);
    else
        gemm_kernel<128,128,8,8,8,true,0><<<grid,256>>>(A,W,C,M,N,K,K,K,N,
            0,0,0,0,0,0,1, nullptr, nullptr, 0, 1);
}

extern "C" void kernel_launch(void* const* d_in, const int* in_sizes, int n_in,
                              void* d_out, int out_size)
{
    const float* x       = (const float*)d_in[0];
    const float* context = (const float*)d_in[1];
    const float* cond    = (const float*)d_in[2];
    const float* n1_w  = (const float*)d_in[3];
    const float* n1_mw = (const float*)d_in[4];
    const float* n1_mb = (const float*)d_in[5];
    const float* n2_w  = (const float*)d_in[6];
    const float* n2_mw = (const float*)d_in[7];
    const float* n2_mb = (const float*)d_in[8];
    const float* n3_w  = (const float*)d_in[9];
    const float* n3_mw = (const float*)d_in[10];
    const float* n3_mb = (const float*)d_in[11];
    const float* sa_q  = (const float*)d_in[12];
    const float* sa_k  = (const float*)d_in[13];
    const float* sa_v  = (const float*)d_in[14];
    const float* sa_o  = (const float*)d_in[15];
    const float* ca_q  = (const float*)d_in[16];
    const float* ca_k  = (const float*)d_in[17];
    const float* ca_v  = (const float*)d_in[18];
    const float* ca_o  = (const float*)d_in[19];
    const float* ff_gate = (const float*)d_in[20];
    const float* ff_up   = (const float*)d_in[21];
    const float* ff_down = (const float*)d_in[22];
    float* out = (float*)d_out;

    float* mods   = sym(d_mods);
    float* normed = sym(d_normed);
    float* q      = sym(d_q);
    float* k      = sym(d_k);
    float* v      = sym(d_v);
    float* sc     = sym(d_scores);
    float* ao     = sym(d_attno);
    float* x1     = sym(d_x1);
    float* x2     = sym(d_x2);
    float* gb     = sym(d_gbuf);
    float* ub     = sym(d_ubuf);
    float* hb     = sym(d_hbuf);

    const int MQ = Bb * Nn;          // 4096 token rows
    const float sm_scale = 0.125f;   // HD^-0.5

    // 1. modulation for all three norms
    mod_kernel<<<(3*3*Dm)/8, 256>>>(cond, n1_mw, n1_mb, n2_mw, n2_mb, n3_mw, n3_mb, mods);

    // ===================== Self attention =====================
    rmsnorm_kernel<<<MQ, 256>>>(x, n1_w, mods + 0*Bb*3*Dm, normed);
    gemm_nt(normed, sa_q, q, MQ, INNER, Dm, nullptr, nullptr, 0, 1);
    gemm_nt(normed, sa_k, k, MQ, INNER, Dm, nullptr, nullptr, 0, 1);
    gemm_nt(normed, sa_v, v, MQ, INNER, Dm, nullptr, nullptr, 0, 1);

    // scores[b,h] = Q[b,:,h,:] @ K[b,:,h,:]^T    (M=512, N=512, K=64)
    gemm_kernel<128,128,8,8,8,true,0><<<dim3(Nn/128, Nn/128, Bb*Hh), 256>>>(
        q, k, sc, Nn, Nn, HDh, INNER, INNER, Nn,
        (long)Nn*INNER, HDh, (long)Nn*INNER, HDh, (long)Hh*Nn*Nn, (long)Nn*Nn, Hh,
        nullptr, nullptr, 0, 1);
    softmax_kernel<<<Bb*Hh*Nn, 256, Nn*sizeof(float)>>>(sc, Nn, sm_scale);
    // O = P @ V    (M=512, N=64, K=512), output to (b,n,h,hd)
    gemm_kernel<64,64,16,4,4,false,0><<<dim3(1, Nn/64, Bb*Hh), 256>>>(
        sc, v, ao, Nn, HDh, Nn, Nn, INNER, INNER,
        (long)Hh*Nn*Nn, (long)Nn*Nn, (long)Nn*INNER, HDh, (long)Nn*INNER, HDh, Hh,
        nullptr, nullptr, 0, 1);
    // x1 = x + gate1 * (O @ sa_o^T)
    gemm_nt(ao, sa_o, x1, MQ, Dm, INNER, x, mods + 0*Bb*3*Dm + 2*Dm, 3*Dm, Nn);

    // ===================== Cross attention =====================
    rmsnorm_kernel<<<MQ, 256>>>(x1, n2_w, mods + 1*Bb*3*Dm, normed);
    gemm_nt(normed, ca_q, q, MQ, INNER, Dm, nullptr, nullptr, 0, 1);
    gemm_nt(context, ca_k, k, Bb*Ss, INNER, Cm, nullptr, nullptr, 0, 1);
    gemm_nt(context, ca_v, v, Bb*Ss, INNER, Cm, nullptr, nullptr, 0, 1);

    gemm_kernel<128,128,8,8,8,true,0><<<dim3(Ss/128, Nn/128, Bb*Hh), 256>>>(
        q, k, sc, Nn, Ss, HDh, INNER, INNER, Ss,
        (long)Nn*INNER, HDh, (long)Ss*INNER, HDh, (long)Hh*Nn*Ss, (long)Nn*Ss, Hh,
        nullptr, nullptr, 0, 1);
    softmax_kernel<<<Bb*Hh*Nn, 256, Ss*sizeof(float)>>>(sc, Ss, sm_scale);
    gemm_kernel<64,64,16,4,4,false,0><<<dim3(1, Nn/64, Bb*Hh), 256>>>(
        sc, v, ao, Nn, HDh, Ss, Ss, INNER, INNER,
        (long)Hh*Nn*Ss, (long)Nn*Ss, (long)Ss*INNER, HDh, (long)Nn*INNER, HDh, Hh,
        nullptr, nullptr, 0, 1);
    gemm_nt(ao, ca_o, x2, MQ, Dm, INNER, x1, mods + 1*Bb*3*Dm + 2*Dm, 3*Dm, Nn);

    // ===================== FFN =====================
    rmsnorm_kernel<<<MQ, 256>>>(x2, n3_w, mods + 2*Bb*3*Dm, normed);
    gemm_nt(normed, ff_gate, gb, MQ, MLPm, Dm, nullptr, nullptr, 0, 1);
    gemm_nt(normed, ff_up,   ub, MQ, MLPm, Dm, nullptr, nullptr, 0, 1);
    silu_mul_kernel<<<(MQ*MLPm + 255)/256, 256>>>(gb, ub, hb, MQ*MLPm);
    // out = x2 + gate3 * (h @ ff_down^T)
    gemm_nt(hb, ff_down, out, MQ, Dm, MLPm, x2, mods + 2*Bb*3*Dm + 2*Dm, 3*Dm, Nn);
}

// round 2
// speedup vs baseline: 2.6939x; 2.6939x over previous
#include <cuda_runtime.h>
#include <math.h>
#include <stdint.h>

// Problem dims
#define Dm    1024
#define Cm    2048
#define MLPm  4096
#define Hh    16
#define HDh   64
#define Bb    8
#define Nn    512
#define Ss    2048
#define INNER (Hh*HDh)   // 1024
#define EPSf  1e-6f

// ---------------- scratch (static device allocations) ---------------------------
__device__ __align__(16) float d_mods  [3 * Bb * 3 * Dm];
__device__ __align__(16) float d_normed[Bb * Nn * Dm];
__device__ __align__(16) float d_q     [Bb * Nn * INNER];
__device__ __align__(16) float d_k     [Bb * Ss * INNER];
__device__ __align__(16) float d_v     [Bb * Ss * INNER];
__device__ __align__(16) float d_vt    [Bb * Ss * INNER];          // transposed V
__device__ __align__(16) float d_scores[(size_t)Bb * Hh * Nn * Ss]; // 512 MB
__device__ __align__(16) float d_attno [Bb * Nn * INNER];
__device__ __align__(16) float d_x1    [Bb * Nn * Dm];
__device__ __align__(16) float d_x2    [Bb * Nn * Dm];
__device__ __align__(16) float d_gbuf  [Bb * Nn * MLPm];
__device__ __align__(16) float d_ubuf  [Bb * Nn * MLPm];
__device__ __align__(16) float d_hbuf  [Bb * Nn * MLPm];

// ---------------- tf32 helpers ---------------------------------------------------
__device__ __forceinline__ uint32_t f2tf32(float f) {
    uint32_t o;
    asm("cvt.rna.tf32.f32 %0, %1;" : "=r"(o) : "f"(f));
    return o;
}

__device__ __forceinline__ void mma_tf32(float* c, const uint32_t* a, const uint32_t* b) {
    asm volatile(
        "mma.sync.aligned.m16n8k8.row.col.f32.tf32.tf32.f32 "
        "{%0,%1,%2,%3}, {%4,%5,%6,%7}, {%8,%9}, {%0,%1,%2,%3};\n"
        : "+f"(c[0]), "+f"(c[1]), "+f"(c[2]), "+f"(c[3])
        : "r"(a[0]), "r"(a[1]), "r"(a[2]), "r"(a[3]), "r"(b[0]), "r"(b[1]));
}

// ---------------- tensor-core NT GEMM -------------------------------------------
// C(M,N) = A(M,K) @ B(N,K)^T ; both operands K-major row-major.
// Batched via blockIdx.z: off = (z/nInner)*s?o + (z%nInner)*s?i.
// EPI==1: C = resid + gate[(row/rows_per_b)*gate_ld + col] * acc
template<int BM,int BN,int WM,int WN,int EPI>
__global__ void __launch_bounds__(256)
mma_nt_kernel(const float* __restrict__ A, const float* __restrict__ Bg, float* __restrict__ C,
              int M, int N, int K, int lda, int ldb, int ldc,
              long sAo, long sAi, long sBo, long sBi, long sCo, long sCi, int nInner,
              const float* __restrict__ resid, const float* __restrict__ gate,
              int gate_ld, int rows_per_b)
{
    constexpr int BK   = 32;
    constexpr int LDS  = BK + 4;          // 36: frag loads conflict-free
    constexpr int MT   = WM / 16;
    constexpr int NTJ  = WN / 8;
    constexpr int WMX  = BM / WM;         // warps along M

    __shared__ uint32_t As[BM][LDS];
    __shared__ uint32_t Bs[BN][LDS];

    int z  = blockIdx.z;
    int zo = z / nInner, zi = z - zo * nInner;
    A  += zo * sAo + zi * sAi;
    Bg += zo * sBo + zi * sBi;
    C  += zo * sCo + zi * sCi;

    const int tid  = threadIdx.x;
    const int wid  = tid >> 5;
    const int lane = tid & 31;
    const int g    = lane >> 2;
    const int c4   = lane & 3;
    const int wm   = wid % WMX;
    const int wn   = wid / WMX;
    const int row0 = blockIdx.y * BM;
    const int col0 = blockIdx.x * BN;

    const float* Ab = A + (size_t)row0 * lda;
    const float* Bb_ = Bg + (size_t)col0 * ldb;

    float acc[MT][NTJ][4];
    #pragma unroll
    for (int i = 0; i < MT; i++)
        #pragma unroll
        for (int j = 0; j < NTJ; j++)
            #pragma unroll
            for (int r = 0; r < 4; r++) acc[i][j][r] = 0.f;

    for (int kt = 0; kt < K; kt += BK) {
        // load A tile: BM x 32 floats, one float4 per thread per iter
        #pragma unroll
        for (int it = 0; it < (BM * 8) / 256; it++) {
            int idx = it * 256 + tid;
            int r = idx >> 3, q = (idx & 7) * 4;
            float4 av = *(const float4*)(Ab + (size_t)r * lda + kt + q);
            uint4 tv = make_uint4(f2tf32(av.x), f2tf32(av.y), f2tf32(av.z), f2tf32(av.w));
            *(uint4*)&As[r][q] = tv;
        }
        // load B tile: BN x 32
        #pragma unroll
        for (int it = 0; it < (BN * 8) / 256; it++) {
            int idx = it * 256 + tid;
            int r = idx >> 3, q = (idx & 7) * 4;
            float4 bv = *(const float4*)(Bb_ + (size_t)r * ldb + kt + q);
            uint4 tv = make_uint4(f2tf32(bv.x), f2tf32(bv.y), f2tf32(bv.z), f2tf32(bv.w));
            *(uint4*)&Bs[r][q] = tv;
        }
        __syncthreads();

        #pragma unroll
        for (int ks = 0; ks < BK / 8; ks++) {
            const int kk = ks * 8;
            uint32_t af[MT][4];
            uint32_t bf[NTJ][2];
            #pragma unroll
            for (int i = 0; i < MT; i++) {
                int m = wm * WM + 16 * i + g;
                af[i][0] = As[m    ][kk + c4];
                af[i][1] = As[m + 8][kk + c4];
                af[i][2] = As[m    ][kk + c4 + 4];
                af[i][3] = As[m + 8][kk + c4 + 4];
            }
            #pragma unroll
            for (int j = 0; j < NTJ; j++) {
                int n = wn * WN + 8 * j + g;
                bf[j][0] = Bs[n][kk + c4];
                bf[j][1] = Bs[n][kk + c4 + 4];
            }
            #pragma unroll
            for (int i = 0; i < MT; i++)
                #pragma unroll
                for (int j = 0; j < NTJ; j++)
                    mma_tf32(acc[i][j], af[i], bf[j]);
        }
        __syncthreads();
    }

    // epilogue
    #pragma unroll
    for (int i = 0; i < MT; i++) {
        #pragma unroll
        for (int j = 0; j < NTJ; j++) {
            int col = col0 + wn * WN + 8 * j + 2 * c4;
            #pragma unroll
            for (int half = 0; half < 2; half++) {
                int row = row0 + wm * WM + 16 * i + g + 8 * half;
                float v0 = acc[i][j][2 * half + 0];
                float v1 = acc[i][j][2 * half + 1];
                if (EPI == 1) {
                    const float* rr = resid + (size_t)row * ldc + col;
                    const float* gg = gate + (size_t)(row / rows_per_b) * gate_ld + col;
                    v0 = rr[0] + gg[0] * v0;
                    v1 = rr[1] + gg[1] * v1;
                }
                float2 o = make_float2(v0, v1);
                *(float2*)(C + (size_t)row * ldc + col) = o;
            }
        }
    }
}

// ---------------- per-batch transpose: in [b][R][Cc] -> out [b][Cc][R] ----------
__global__ void transpose_kernel(const float* __restrict__ in, float* __restrict__ out,
                                 int R, int Cc)
{
    __shared__ float t[32][33];
    int c0 = blockIdx.x * 32, r0 = blockIdx.y * 32;
    in  += (size_t)blockIdx.z * R * Cc;
    out += (size_t)blockIdx.z * R * Cc;
    int tx = threadIdx.x, ty = threadIdx.y;
    #pragma unroll
    for (int i = ty; i < 32; i += 8)
        t[i][tx] = in[(size_t)(r0 + i) * Cc + c0 + tx];
    __syncthreads();
    #pragma unroll
    for (int i = ty; i < 32; i += 8)
        out[(size_t)(c0 + i) * R + r0 + tx] = t[tx][i];
}

// ---------------- modulation: mods[norm][b][3D] = cond @ mw^T + mb --------------
__global__ void mod_kernel(const float* __restrict__ cond,
                           const float* __restrict__ mw0, const float* __restrict__ mb0,
                           const float* __restrict__ mw1, const float* __restrict__ mb1,
                           const float* __restrict__ mw2, const float* __restrict__ mb2,
                           float* __restrict__ mods)
{
    __shared__ float cs[Bb * Dm];
    for (int i = threadIdx.x; i < Bb * Dm; i += blockDim.x) cs[i] = cond[i];
    __syncthreads();

    int warp = threadIdx.x >> 5, lane = threadIdx.x & 31;
    int j = blockIdx.x * 8 + warp;
    int norm = j / (3*Dm), jj = j - norm * (3*Dm);
    const float* mw = (norm == 0) ? mw0 : (norm == 1) ? mw1 : mw2;
    const float* mb = (norm == 0) ? mb0 : (norm == 1) ? mb1 : mb2;

    float acc[Bb];
    #pragma unroll
    for (int b = 0; b < Bb; b++) acc[b] = 0.f;
    const float* wrow = mw + (size_t)jj * Dm;
    for (int d = lane; d < Dm; d += 32) {
        float w = wrow[d];
        #pragma unroll
        for (int b = 0; b < Bb; b++) acc[b] = fmaf(w, cs[b*Dm + d], acc[b]);
    }
    #pragma unroll
    for (int b = 0; b < Bb; b++)
        #pragma unroll
        for (int off = 16; off > 0; off >>= 1)
            acc[b] += __shfl_xor_sync(0xffffffff, acc[b], off);
    if (lane < Bb)
        mods[(size_t)norm * Bb * 3*Dm + lane * 3*Dm + jj] = acc[lane] + mb[jj];
}

// ---------------- adaRMS norm ----------------------------------------------------
__global__ void rmsnorm_kernel(const float* __restrict__ x, const float* __restrict__ w,
                               const float* __restrict__ mod_base,
                               float* __restrict__ out)
{
    int row = blockIdx.x;
    int b   = row / Nn;
    const float* xr = x + (size_t)row * Dm;
    const float* ms = mod_base + b * 3*Dm;

    float ss = 0.f;
    for (int i = threadIdx.x; i < Dm; i += blockDim.x) { float t = xr[i]; ss = fmaf(t,t,ss); }
    #pragma unroll
    for (int off = 16; off > 0; off >>= 1) ss += __shfl_xor_sync(0xffffffff, ss, off);
    __shared__ float red[8];
    if ((threadIdx.x & 31) == 0) red[threadIdx.x >> 5] = ss;
    __syncthreads();
    if (threadIdx.x < 8) {
        float v = red[threadIdx.x];
        #pragma unroll
        for (int off = 4; off > 0; off >>= 1) v += __shfl_xor_sync(0xff, v, off);
        if (threadIdx.x == 0) red[0] = v;
    }
    __syncthreads();
    float rn = rsqrtf(red[0] * (1.0f/Dm) + EPSf);

    float* orow = out + (size_t)row * Dm;
    for (int i = threadIdx.x; i < Dm; i += blockDim.x) {
        float scale = ms[i], shift = ms[Dm + i];
        orow[i] = xr[i] * rn * w[i] * (1.0f + scale) + shift;
    }
}

// ---------------- row softmax (in place, with pre-scale) ------------------------
__global__ void softmax_kernel(float* __restrict__ sc, int S, float scale)
{
    extern __shared__ float v[];
    float* p = sc + (size_t)blockIdx.x * S;
    int tid = threadIdx.x, nt = blockDim.x;
    __shared__ float red[8];

    float m = -1e30f;
    for (int i = tid; i < S; i += nt) { float x = p[i] * scale; v[i] = x; m = fmaxf(m, x); }
    #pragma unroll
    for (int off = 16; off > 0; off >>= 1) m = fmaxf(m, __shfl_xor_sync(0xffffffff, m, off));
    if ((tid & 31) == 0) red[tid >> 5] = m;
    __syncthreads();
    if (tid < 8) {
        float t = red[tid];
        #pragma unroll
        for (int off = 4; off > 0; off >>= 1) t = fmaxf(t, __shfl_xor_sync(0xff, t, off));
        if (tid == 0) red[0] = t;
    }
    __syncthreads();
    m = red[0];
    __syncthreads();

    float sum = 0.f;
    for (int i = tid; i < S; i += nt) { float e = __expf(v[i] - m); v[i] = e; sum += e; }
    #pragma unroll
    for (int off = 16; off > 0; off >>= 1) sum += __shfl_xor_sync(0xffffffff, sum, off);
    if ((tid & 31) == 0) red[tid >> 5] = sum;
    __syncthreads();
    if (tid < 8) {
        float t = red[tid];
        #pragma unroll
        for (int off = 4; off > 0; off >>= 1) t += __shfl_xor_sync(0xff, t, off);
        if (tid == 0) red[0] = t;
    }
    __syncthreads();
    float inv = 1.0f / red[0];
    for (int i = tid; i < S; i += nt) p[i] = v[i] * inv;
}

// ---------------- silu(g)*u -----------------------------------------------------
__global__ void silu_mul_kernel(const float* __restrict__ g, const float* __restrict__ u,
                                float* __restrict__ h, int n)
{
    int i = blockIdx.x * blockDim.x + threadIdx.x;
    if (i < n) {
        float x = g[i];
        h[i] = (x / (1.0f + __expf(-x))) * u[i];
    }
}

// ---------------- host orchestration -------------------------------------------
static float* sym(const void* s) { void* p = nullptr; cudaGetSymbolAddress(&p, s); return (float*)p; }

// C = A(M,K) @ W(N,K)^T  (plain projection)
static void gemm_nt(const float* A, const float* W, float* C, int M, int N, int K,
                    const float* resid, const float* gate, int gate_ld, int rpb)
{
    dim3 grid(N/128, M/128, 1);
    if (resid)
        mma_nt_kernel<128,128,64,32,1><<<grid,256>>>(A,W,C,M,N,K,K,K,N,
            0,0,0,0,0,0,1, resid, gate, gate_ld, rpb);
    else
        mma_nt_kernel<128,128,64,32,0><<<grid,256>>>(A,W,C,M,N,K,K,K,N,
            0,0,0,0,0,0,1, nullptr, nullptr, 0, 1);
}

extern "C" void kernel_launch(void* const* d_in, const int* in_sizes, int n_in,
                              void* d_out, int out_size)
{
    const float* x       = (const float*)d_in[0];
    const float* context = (const float*)d_in[1];
    const float* cond    = (const float*)d_in[2];
    const float* n1_w  = (const float*)d_in[3];
    const float* n1_mw = (const float*)d_in[4];
    const float* n1_mb = (const float*)d_in[5];
    const float* n2_w  = (const float*)d_in[6];
    const float* n2_mw = (const float*)d_in[7];
    const float* n2_mb = (const float*)d_in[8];
    const float* n3_w  = (const float*)d_in[9];
    const float* n3_mw = (const float*)d_in[10];
    const float* n3_mb = (const float*)d_in[11];
    const float* sa_q  = (const float*)d_in[12];
    const float* sa_k  = (const float*)d_in[13];
    const float* sa_v  = (const float*)d_in[14];
    const float* sa_o  = (const float*)d_in[15];
    const float* ca_q  = (const float*)d_in[16];
    const float* ca_k  = (const float*)d_in[17];
    const float* ca_v  = (const float*)d_in[18];
    const float* ca_o  = (const float*)d_in[19];
    const float* ff_gate = (const float*)d_in[20];
    const float* ff_up   = (const float*)d_in[21];
    const float* ff_down = (const float*)d_in[22];
    float* out = (float*)d_out;

    float* mods   = sym(d_mods);
    float* normed = sym(d_normed);
    float* q      = sym(d_q);
    float* k      = sym(d_k);
    float* v      = sym(d_v);
    float* vt     = sym(d_vt);
    float* sc     = sym(d_scores);
    float* ao     = sym(d_attno);
    float* x1     = sym(d_x1);
    float* x2     = sym(d_x2);
    float* gb     = sym(d_gbuf);
    float* ub     = sym(d_ubuf);
    float* hb     = sym(d_hbuf);

    const int MQ = Bb * Nn;          // 4096 token rows
    const float sm_scale = 0.125f;   // HD^-0.5

    mod_kernel<<<(3*3*Dm)/8, 256>>>(cond, n1_mw, n1_mb, n2_mw, n2_mb, n3_mw, n3_mb, mods);

    // ===================== Self attention =====================
    rmsnorm_kernel<<<MQ, 256>>>(x, n1_w, mods + 0*Bb*3*Dm, normed);
    gemm_nt(normed, sa_q, q, MQ, INNER, Dm, nullptr, nullptr, 0, 1);
    gemm_nt(normed, sa_k, k, MQ, INNER, Dm, nullptr, nullptr, 0, 1);
    gemm_nt(normed, sa_v, v, MQ, INNER, Dm, nullptr, nullptr, 0, 1);
    // Vt[b][d][n] = V[b][n][d]
    transpose_kernel<<<dim3(INNER/32, Nn/32, Bb), dim3(32,8)>>>(v, vt, Nn, INNER);

    // scores[b,h] = Q[b,:,h,:] @ K[b,:,h,:]^T    (M=512, N=512, K=64)
    mma_nt_kernel<128,128,64,32,0><<<dim3(Nn/128, Nn/128, Bb*Hh), 256>>>(
        q, k, sc, Nn, Nn, HDh, INNER, INNER, Nn,
        (long)Nn*INNER, HDh, (long)Nn*INNER, HDh, (long)Hh*Nn*Nn, (long)Nn*Nn, Hh,
        nullptr, nullptr, 0, 1);
    softmax_kernel<<<Bb*Hh*Nn, 256, Nn*sizeof(float)>>>(sc, Nn, sm_scale);
    // O = P @ Vt^T  (M=512, N=64, K=512)
    mma_nt_kernel<128,64,64,16,0><<<dim3(1, Nn/128, Bb*Hh), 256>>>(
        sc, vt, ao, Nn, HDh, Nn, Nn, Nn, INNER,
        (long)Hh*Nn*Nn, (long)Nn*Nn, (long)INNER*Nn, (long)HDh*Nn, (long)Nn*INNER, HDh, Hh,
        nullptr, nullptr, 0, 1);
    // x1 = x + gate1 * (O @ sa_o^T)
    gemm_nt(ao, sa_o, x1, MQ, Dm, INNER, x, mods + 0*Bb*3*Dm + 2*Dm, 3*Dm, Nn);

    // ===================== Cross attention =====================
    rmsnorm_kernel<<<MQ, 256>>>(x1, n2_w, mods + 1*Bb*3*Dm, normed);
    gemm_nt(normed, ca_q, q, MQ, INNER, Dm, nullptr, nullptr, 0, 1);
    gemm_nt(context, ca_k, k, Bb*Ss, INNER, Cm, nullptr, nullptr, 0, 1);
    gemm_nt(context, ca_v, v, Bb*Ss, INNER, Cm, nullptr, nullptr, 0, 1);
    transpose_kernel<<<dim3(INNER/32, Ss/32, Bb), dim3(32,8)>>>(v, vt, Ss, INNER);

    mma_nt_kernel<128,128,64,32,0><<<dim3(Ss/128, Nn/128, Bb*Hh), 256>>>(
        q, k, sc, Nn, Ss, HDh, INNER, INNER, Ss,
        (long)Nn*INNER, HDh, (long)Ss*INNER, HDh, (long)Hh*Nn*Ss, (long)Nn*Ss, Hh,
        nullptr, nullptr, 0, 1);
    softmax_kernel<<<Bb*Hh*Nn, 256, Ss*sizeof(float)>>>(sc, Ss, sm_scale);
    mma_nt_kernel<128,64,64,16,0><<<dim3(1, Nn/128, Bb*Hh), 256>>>(
        sc, vt, ao, Nn, HDh, Ss, Ss, Ss, INNER,
        (long)Hh*Nn*Ss, (long)Nn*Ss, (long)INNER*Ss, (long)HDh*Ss, (long)Nn*INNER, HDh, Hh,
        nullptr, nullptr, 0, 1);
    gemm_nt(ao, ca_o, x2, MQ, Dm, INNER, x1, mods + 1*Bb*3*Dm + 2*Dm, 3*Dm, Nn);

    // ===================== FFN =====================
    rmsnorm_kernel<<<MQ, 256>>>(x2, n3_w, mods + 2*Bb*3*Dm, normed);
    gemm_nt(normed, ff_gate, gb, MQ, MLPm, Dm, nullptr, nullptr, 0, 1);
    gemm_nt(normed, ff_up,   ub, MQ, MLPm, Dm, nullptr, nullptr, 0, 1);
    silu_mul_kernel<<<(MQ*MLPm + 255)/256, 256>>>(gb, ub, hb, MQ*MLPm);
    gemm_nt(hb, ff_down, out, MQ, Dm, MLPm, x2, mods + 2*Bb*3*Dm + 2*Dm, 3*Dm, Nn);
}

// round 3
// speedup vs baseline: 2.8876x; 1.0719x over previous
#include <cuda_runtime.h>
#include <math.h>
#include <stdint.h>

// Problem dims
#define Dm    1024
#define Cm    2048
#define MLPm  4096
#define Hh    16
#define HDh   64
#define Bb    8
#define Nn    512
#define Ss    2048
#define INNER (Hh*HDh)   // 1024
#define EPSf  1e-6f

// ---------------- scratch (static device allocations) ---------------------------
__device__ __align__(16) float d_mods  [3 * Bb * 3 * Dm];
__device__ __align__(16) float d_normed[Bb * Nn * Dm];
__device__ __align__(16) float d_q     [Bb * Nn * INNER];
__device__ __align__(16) float d_k     [Bb * Ss * INNER];
__device__ __align__(16) float d_v     [Bb * Ss * INNER];
__device__ __align__(16) float d_vt    [Bb * Ss * INNER];
__device__ __align__(16) float d_scores[(size_t)Bb * Hh * Nn * Ss];
__device__ __align__(16) float d_attno [Bb * Nn * INNER];
__device__ __align__(16) float d_x1    [Bb * Nn * Dm];
__device__ __align__(16) float d_x2    [Bb * Nn * Dm];
__device__ __align__(16) float d_gbuf  [Bb * Nn * MLPm];
__device__ __align__(16) float d_ubuf  [Bb * Nn * MLPm];
__device__ __align__(16) float d_hbuf  [Bb * Nn * MLPm];

// ---------------- tf32 helpers ---------------------------------------------------
__device__ __forceinline__ uint32_t f2tf32(float f) {
    uint32_t o;
    asm("cvt.rna.tf32.f32 %0, %1;" : "=r"(o) : "f"(f));
    return o;
}

__device__ __forceinline__ void mma_tf32(float* c, const uint32_t* a, const uint32_t* b) {
    asm volatile(
        "mma.sync.aligned.m16n8k8.row.col.f32.tf32.tf32.f32 "
        "{%0,%1,%2,%3}, {%4,%5,%6,%7}, {%8,%9}, {%0,%1,%2,%3};\n"
        : "+f"(c[0]), "+f"(c[1]), "+f"(c[2]), "+f"(c[3])
        : "r"(a[0]), "r"(a[1]), "r"(a[2]), "r"(a[3]), "r"(b[0]), "r"(b[1]));
}

// ---------------- pipelined tensor-core NT GEMM ---------------------------------
// C(M,N) = A(M,K) @ B(N,K)^T ; both K-major row-major. Double-buffered smem with
// register prefetch of the next K-tile. BK=32 fixed.
// Batched via blockIdx.z. EPI==1: C = resid + gate[(row/rows_per_b)*gate_ld+col]*acc
template<int BM,int BN,int WM,int WN,int EPI>
__global__ void __launch_bounds__(256)
mma_nt_kernel(const float* __restrict__ A, const float* __restrict__ Bg, float* __restrict__ C,
              int M, int N, int K, int lda, int ldb, int ldc,
              long sAo, long sAi, long sBo, long sBi, long sCo, long sCi, int nInner,
              const float* __restrict__ resid, const float* __restrict__ gate,
              int gate_ld, int rows_per_b)
{
    constexpr int BK   = 32;
    constexpr int LDS  = BK + 4;          // 36: frag loads conflict-free
    constexpr int MT   = WM / 16;
    constexpr int NTJ  = WN / 8;
    constexpr int WMX  = BM / WM;
    constexpr int AIT  = (BM * 8) / 256;  // float4 loads per thread for A tile
    constexpr int BIT  = (BN * 8) / 256;

    extern __shared__ uint32_t smem_u[];
    uint32_t* AsBase = smem_u;                    // 2 * BM * LDS
    uint32_t* BsBase = smem_u + 2 * BM * LDS;     // 2 * BN * LDS

    int z  = blockIdx.z;
    int zo = z / nInner, zi = z - zo * nInner;
    A  += zo * sAo + zi * sAi;
    Bg += zo * sBo + zi * sBi;
    C  += zo * sCo + zi * sCi;

    const int tid  = threadIdx.x;
    const int wid  = tid >> 5;
    const int lane = tid & 31;
    const int g    = lane >> 2;
    const int c4   = lane & 3;
    const int wm   = wid % WMX;
    const int wn   = wid / WMX;
    const int row0 = blockIdx.y * BM;
    const int col0 = blockIdx.x * BN;

    const float* Ab  = A + (size_t)row0 * lda;
    const float* Bb_ = Bg + (size_t)col0 * ldb;

    const int ldRow = tid >> 3;           // row within tile for loads
    const int ldCol = (tid & 7) * 4;      // k-offset within tile

    float acc[MT][NTJ][4];
    #pragma unroll
    for (int i = 0; i < MT; i++)
        #pragma unroll
        for (int j = 0; j < NTJ; j++)
            #pragma unroll
            for (int r = 0; r < 4; r++) acc[i][j][r] = 0.f;

    float4 pa[AIT], pb[BIT];

    // prologue: tile 0 -> regs -> smem buf 0
    #pragma unroll
    for (int it = 0; it < AIT; it++)
        pa[it] = *(const float4*)(Ab + (size_t)(it * 32 + ldRow) * lda + ldCol);
    #pragma unroll
    for (int it = 0; it < BIT; it++)
        pb[it] = *(const float4*)(Bb_ + (size_t)(it * 32 + ldRow) * ldb + ldCol);
    #pragma unroll
    for (int it = 0; it < AIT; it++) {
        uint4 tv = make_uint4(f2tf32(pa[it].x), f2tf32(pa[it].y), f2tf32(pa[it].z), f2tf32(pa[it].w));
        *(uint4*)&AsBase[(it * 32 + ldRow) * LDS + ldCol] = tv;
    }
    #pragma unroll
    for (int it = 0; it < BIT; it++) {
        uint4 tv = make_uint4(f2tf32(pb[it].x), f2tf32(pb[it].y), f2tf32(pb[it].z), f2tf32(pb[it].w));
        *(uint4*)&BsBase[(it * 32 + ldRow) * LDS + ldCol] = tv;
    }
    __syncthreads();

    const int nTiles = K / BK;
    int buf = 0;

    for (int t = 0; t < nTiles; t++) {
        // issue next tile's global loads first (latency hidden under compute)
        if (t + 1 < nTiles) {
            int kt = (t + 1) * BK;
            #pragma unroll
            for (int it = 0; it < AIT; it++)
                pa[it] = *(const float4*)(Ab + (size_t)(it * 32 + ldRow) * lda + kt + ldCol);
            #pragma unroll
            for (int it = 0; it < BIT; it++)
                pb[it] = *(const float4*)(Bb_ + (size_t)(it * 32 + ldRow) * ldb + kt + ldCol);
        }

        const uint32_t* Asb = AsBase + buf * BM * LDS;
        const uint32_t* Bsb = BsBase + buf * BN * LDS;

        #pragma unroll
        for (int ks = 0; ks < BK / 8; ks++) {
            const int kk = ks * 8;
            uint32_t af[MT][4];
            uint32_t bf[NTJ][2];
            #pragma unroll
            for (int i = 0; i < MT; i++) {
                int m = wm * WM + 16 * i + g;
                af[i][0] = Asb[(m    ) * LDS + kk + c4];
                af[i][1] = Asb[(m + 8) * LDS + kk + c4];
                af[i][2] = Asb[(m    ) * LDS + kk + c4 + 4];
                af[i][3] = Asb[(m + 8) * LDS + kk + c4 + 4];
            }
            #pragma unroll
            for (int j = 0; j < NTJ; j++) {
                int n = wn * WN + 8 * j + g;
                bf[j][0] = Bsb[n * LDS + kk + c4];
                bf[j][1] = Bsb[n * LDS + kk + c4 + 4];
            }
            #pragma unroll
            for (int i = 0; i < MT; i++)
                #pragma unroll
                for (int j = 0; j < NTJ; j++)
                    mma_tf32(acc[i][j], af[i], bf[j]);
        }

        if (t + 1 < nTiles) {
            uint32_t* Asn = AsBase + (buf ^ 1) * BM * LDS;
            uint32_t* Bsn = BsBase + (buf ^ 1) * BN * LDS;
            #pragma unroll
            for (int it = 0; it < AIT; it++) {
                uint4 tv = make_uint4(f2tf32(pa[it].x), f2tf32(pa[it].y), f2tf32(pa[it].z), f2tf32(pa[it].w));
                *(uint4*)&Asn[(it * 32 + ldRow) * LDS + ldCol] = tv;
            }
            #pragma unroll
            for (int it = 0; it < BIT; it++) {
                uint4 tv = make_uint4(f2tf32(pb[it].x), f2tf32(pb[it].y), f2tf32(pb[it].z), f2tf32(pb[it].w));
                *(uint4*)&Bsn[(it * 32 + ldRow) * LDS + ldCol] = tv;
            }
            __syncthreads();
            buf ^= 1;
        }
    }

    // epilogue
    #pragma unroll
    for (int i = 0; i < MT; i++) {
        #pragma unroll
        for (int j = 0; j < NTJ; j++) {
            int col = col0 + wn * WN + 8 * j + 2 * c4;
            #pragma unroll
            for (int half = 0; half < 2; half++) {
                int row = row0 + wm * WM + 16 * i + g + 8 * half;
                float v0 = acc[i][j][2 * half + 0];
                float v1 = acc[i][j][2 * half + 1];
                if (EPI == 1) {
                    const float* rr = resid + (size_t)row * ldc + col;
                    const float* gg = gate + (size_t)(row / rows_per_b) * gate_ld + col;
                    v0 = rr[0] + gg[0] * v0;
                    v1 = rr[1] + gg[1] * v1;
                }
                *(float2*)(C + (size_t)row * ldc + col) = make_float2(v0, v1);
            }
        }
    }
}

// ---------------- per-batch transpose: in [b][R][Cc] -> out [b][Cc][R] ----------
__global__ void transpose_kernel(const float* __restrict__ in, float* __restrict__ out,
                                 int R, int Cc)
{
    __shared__ float t[32][33];
    int c0 = blockIdx.x * 32, r0 = blockIdx.y * 32;
    in  += (size_t)blockIdx.z * R * Cc;
    out += (size_t)blockIdx.z * R * Cc;
    int tx = threadIdx.x, ty = threadIdx.y;
    #pragma unroll
    for (int i = ty; i < 32; i += 8)
        t[i][tx] = in[(size_t)(r0 + i) * Cc + c0 + tx];
    __syncthreads();
    #pragma unroll
    for (int i = ty; i < 32; i += 8)
        out[(size_t)(c0 + i) * R + r0 + tx] = t[tx][i];
}

// ---------------- modulation: mods[norm][b][3D] = cond @ mw^T + mb --------------
__global__ void mod_kernel(const float* __restrict__ cond,
                           const float* __restrict__ mw0, const float* __restrict__ mb0,
                           const float* __restrict__ mw1, const float* __restrict__ mb1,
                           const float* __restrict__ mw2, const float* __restrict__ mb2,
                           float* __restrict__ mods)
{
    __shared__ float cs[Bb * Dm];
    for (int i = threadIdx.x; i < Bb * Dm; i += blockDim.x) cs[i] = cond[i];
    __syncthreads();

    int warp = threadIdx.x >> 5, lane = threadIdx.x & 31;
    int j = blockIdx.x * 8 + warp;
    int norm = j / (3*Dm), jj = j - norm * (3*Dm);
    const float* mw = (norm == 0) ? mw0 : (norm == 1) ? mw1 : mw2;
    const float* mb = (norm == 0) ? mb0 : (norm == 1) ? mb1 : mb2;

    float acc[Bb];
    #pragma unroll
    for (int b = 0; b < Bb; b++) acc[b] = 0.f;
    const float* wrow = mw + (size_t)jj * Dm;
    for (int d = lane; d < Dm; d += 32) {
        float w = wrow[d];
        #pragma unroll
        for (int b = 0; b < Bb; b++) acc[b] = fmaf(w, cs[b*Dm + d], acc[b]);
    }
    #pragma unroll
    for (int b = 0; b < Bb; b++)
        #pragma unroll
        for (int off = 16; off > 0; off >>= 1)
            acc[b] += __shfl_xor_sync(0xffffffff, acc[b], off);
    if (lane < Bb)
        mods[(size_t)norm * Bb * 3*Dm + lane * 3*Dm + jj] = acc[lane] + mb[jj];
}

// ---------------- adaRMS norm ----------------------------------------------------
__global__ void rmsnorm_kernel(const float* __restrict__ x, const float* __restrict__ w,
                               const float* __restrict__ mod_base,
                               float* __restrict__ out)
{
    int row = blockIdx.x;
    int b   = row / Nn;
    const float* xr = x + (size_t)row * Dm;
    const float* ms = mod_base + b * 3*Dm;

    float ss = 0.f;
    for (int i = threadIdx.x; i < Dm; i += blockDim.x) { float t = xr[i]; ss = fmaf(t,t,ss); }
    #pragma unroll
    for (int off = 16; off > 0; off >>= 1) ss += __shfl_xor_sync(0xffffffff, ss, off);
    __shared__ float red[8];
    if ((threadIdx.x & 31) == 0) red[threadIdx.x >> 5] = ss;
    __syncthreads();
    if (threadIdx.x < 8) {
        float v = red[threadIdx.x];
        #pragma unroll
        for (int off = 4; off > 0; off >>= 1) v += __shfl_xor_sync(0xff, v, off);
        if (threadIdx.x == 0) red[0] = v;
    }
    __syncthreads();
    float rn = rsqrtf(red[0] * (1.0f/Dm) + EPSf);

    float* orow = out + (size_t)row * Dm;
    for (int i = threadIdx.x; i < Dm; i += blockDim.x) {
        float scale = ms[i], shift = ms[Dm + i];
        orow[i] = xr[i] * rn * w[i] * (1.0f + scale) + shift;
    }
}

// ---------------- row softmax (in place, with pre-scale) ------------------------
__global__ void softmax_kernel(float* __restrict__ sc, int S, float scale)
{
    extern __shared__ float v[];
    float* p = sc + (size_t)blockIdx.x * S;
    int tid = threadIdx.x, nt = blockDim.x;
    __shared__ float red[8];

    float m = -1e30f;
    for (int i = tid; i < S; i += nt) { float x = p[i] * scale; v[i] = x; m = fmaxf(m, x); }
    #pragma unroll
    for (int off = 16; off > 0; off >>= 1) m = fmaxf(m, __shfl_xor_sync(0xffffffff, m, off));
    if ((tid & 31) == 0) red[tid >> 5] = m;
    __syncthreads();
    if (tid < 8) {
        float t = red[tid];
        #pragma unroll
        for (int off = 4; off > 0; off >>= 1) t = fmaxf(t, __shfl_xor_sync(0xff, t, off));
        if (tid == 0) red[0] = t;
    }
    __syncthreads();
    m = red[0];
    __syncthreads();

    float sum = 0.f;
    for (int i = tid; i < S; i += nt) { float e = __expf(v[i] - m); v[i] = e; sum += e; }
    #pragma unroll
    for (int off = 16; off > 0; off >>= 1) sum += __shfl_xor_sync(0xffffffff, sum, off);
    if ((tid & 31) == 0) red[tid >> 5] = sum;
    __syncthreads();
    if (tid < 8) {
        float t = red[tid];
        #pragma unroll
        for (int off = 4; off > 0; off >>= 1) t += __shfl_xor_sync(0xff, t, off);
        if (tid == 0) red[0] = t;
    }
    __syncthreads();
    float inv = 1.0f / red[0];
    for (int i = tid; i < S; i += nt) p[i] = v[i] * inv;
}

// ---------------- silu(g)*u -----------------------------------------------------
__global__ void silu_mul_kernel(const float* __restrict__ g, const float* __restrict__ u,
                                float* __restrict__ h, int n)
{
    int i = blockIdx.x * blockDim.x + threadIdx.x;
    if (i < n) {
        float x = g[i];
        h[i] = (x / (1.0f + __expf(-x))) * u[i];
    }
}

// ---------------- host orchestration -------------------------------------------
static float* sym(const void* s) { void* p = nullptr; cudaGetSymbolAddress(&p, s); return (float*)p; }

template<int BM,int BN,int WM,int WN,int EPI>
static void launch_mma(dim3 grid,
                       const float* A, const float* Bg, float* C,
                       int M, int N, int K, int lda, int ldb, int ldc,
                       long sAo, long sAi, long sBo, long sBi, long sCo, long sCi, int nInner,
                       const float* resid, const float* gate, int gate_ld, int rpb)
{
    size_t sm = (size_t)2 * (BM + BN) * 36 * sizeof(uint32_t);
    cudaFuncSetAttribute(mma_nt_kernel<BM,BN,WM,WN,EPI>,
                         cudaFuncAttributeMaxDynamicSharedMemorySize, (int)sm);
    mma_nt_kernel<BM,BN,WM,WN,EPI><<<grid, 256, sm>>>(
        A, Bg, C, M, N, K, lda, ldb, ldc,
        sAo, sAi, sBo, sBi, sCo, sCi, nInner, resid, gate, gate_ld, rpb);
}

// C = A(M,K) @ W(N,K)^T
static void gemm_nt(const float* A, const float* W, float* C, int M, int N, int K,
                    const float* resid, const float* gate, int gate_ld, int rpb)
{
    dim3 grid(N/128, M/128, 1);
    if (resid)
        launch_mma<128,128,64,32,1>(grid, A, W, C, M, N, K, K, K, N,
            0,0,0,0,0,0,1, resid, gate, gate_ld, rpb);
    else
        launch_mma<128,128,64,32,0>(grid, A, W, C, M, N, K, K, K, N,
            0,0,0,0,0,0,1, nullptr, nullptr, 0, 1);
}

extern "C" void kernel_launch(void* const* d_in, const int* in_sizes, int n_in,
                              void* d_out, int out_size)
{
    const float* x       = (const float*)d_in[0];
    const float* context = (const float*)d_in[1];
    const float* cond    = (const float*)d_in[2];
    const float* n1_w  = (const float*)d_in[3];
    const float* n1_mw = (const float*)d_in[4];
    const float* n1_mb = (const float*)d_in[5];
    const float* n2_w  = (const float*)d_in[6];
    const float* n2_mw = (const float*)d_in[7];
    const float* n2_mb = (const float*)d_in[8];
    const float* n3_w  = (const float*)d_in[9];
    const float* n3_mw = (const float*)d_in[10];
    const float* n3_mb = (const float*)d_in[11];
    const float* sa_q  = (const float*)d_in[12];
    const float* sa_k  = (const float*)d_in[13];
    const float* sa_v  = (const float*)d_in[14];
    const float* sa_o  = (const float*)d_in[15];
    const float* ca_q  = (const float*)d_in[16];
    const float* ca_k  = (const float*)d_in[17];
    const float* ca_v  = (const float*)d_in[18];
    const float* ca_o  = (const float*)d_in[19];
    const float* ff_gate = (const float*)d_in[20];
    const float* ff_up   = (const float*)d_in[21];
    const float* ff_down = (const float*)d_in[22];
    float* out = (float*)d_out;

    float* mods   = sym(d_mods);
    float* normed = sym(d_normed);
    float* q      = sym(d_q);
    float* k      = sym(d_k);
    float* v      = sym(d_v);
    float* vt     = sym(d_vt);
    float* sc     = sym(d_scores);
    float* ao     = sym(d_attno);
    float* x1     = sym(d_x1);
    float* x2     = sym(d_x2);
    float* gb     = sym(d_gbuf);
    float* ub     = sym(d_ubuf);
    float* hb     = sym(d_hbuf);

    const int MQ = Bb * Nn;
    const float sm_scale = 0.125f;

    mod_kernel<<<(3*3*Dm)/8, 256>>>(cond, n1_mw, n1_mb, n2_mw, n2_mb, n3_mw, n3_mb, mods);

    // ===================== Self attention =====================
    rmsnorm_kernel<<<MQ, 256>>>(x, n1_w, mods + 0*Bb*3*Dm, normed);
    gemm_nt(normed, sa_q, q, MQ, INNER, Dm, nullptr, nullptr, 0, 1);
    gemm_nt(normed, sa_k, k, MQ, INNER, Dm, nullptr, nullptr, 0, 1);
    gemm_nt(normed, sa_v, v, MQ, INNER, Dm, nullptr, nullptr, 0, 1);
    transpose_kernel<<<dim3(INNER/32, Nn/32, Bb), dim3(32,8)>>>(v, vt, Nn, INNER);

    // scores[b,h] = Q[b,:,h,:] @ K[b,:,h,:]^T
    launch_mma<128,128,64,32,0>(dim3(Nn/128, Nn/128, Bb*Hh),
        q, k, sc, Nn, Nn, HDh, INNER, INNER, Nn,
        (long)Nn*INNER, HDh, (long)Nn*INNER, HDh, (long)Hh*Nn*Nn, (long)Nn*Nn, Hh,
        nullptr, nullptr, 0, 1);
    softmax_kernel<<<Bb*Hh*Nn, 256, Nn*sizeof(float)>>>(sc, Nn, sm_scale);
    // O = P @ Vt^T
    launch_mma<128,64,64,16,0>(dim3(1, Nn/128, Bb*Hh),
        sc, vt, ao, Nn, HDh, Nn, Nn, Nn, INNER,
        (long)Hh*Nn*Nn, (long)Nn*Nn, (long)INNER*Nn, (long)HDh*Nn, (long)Nn*INNER, HDh, Hh,
        nullptr, nullptr, 0, 1);
    gemm_nt(ao, sa_o, x1, MQ, Dm, INNER, x, mods + 0*Bb*3*Dm + 2*Dm, 3*Dm, Nn);

    // ===================== Cross attention =====================
    rmsnorm_kernel<<<MQ, 256>>>(x1, n2_w, mods + 1*Bb*3*Dm, normed);
    gemm_nt(normed, ca_q, q, MQ, INNER, Dm, nullptr, nullptr, 0, 1);
    gemm_nt(context, ca_k, k, Bb*Ss, INNER, Cm, nullptr, nullptr, 0, 1);
    gemm_nt(context, ca_v, v, Bb*Ss, INNER, Cm, nullptr, nullptr, 0, 1);
    transpose_kernel<<<dim3(INNER/32, Ss/32, Bb), dim3(32,8)>>>(v, vt, Ss, INNER);

    launch_mma<128,128,64,32,0>(dim3(Ss/128, Nn/128, Bb*Hh),
        q, k, sc, Nn, Ss, HDh, INNER, INNER, Ss,
        (long)Nn*INNER, HDh, (long)Ss*INNER, HDh, (long)Hh*Nn*Ss, (long)Nn*Ss, Hh,
        nullptr, nullptr, 0, 1);
    softmax_kernel<<<Bb*Hh*Nn, 256, Ss*sizeof(float)>>>(sc, Ss, sm_scale);
    launch_mma<128,64,64,16,0>(dim3(1, Nn/128, Bb*Hh),
        sc, vt, ao, Nn, HDh, Ss, Ss, Ss, INNER,
        (long)Hh*Nn*Ss, (long)Nn*Ss, (long)INNER*Ss, (long)HDh*Ss, (long)Nn*INNER, HDh, Hh,
        nullptr, nullptr, 0, 1);
    gemm_nt(ao, ca_o, x2, MQ, Dm, INNER, x1, mods + 1*Bb*3*Dm + 2*Dm, 3*Dm, Nn);

    // ===================== FFN =====================
    rmsnorm_kernel<<<MQ, 256>>>(x2, n3_w, mods + 2*Bb*3*Dm, normed);
    gemm_nt(normed, ff_gate, gb, MQ, MLPm, Dm, nullptr, nullptr, 0, 1);
    gemm_nt(normed, ff_up,   ub, MQ, MLPm, Dm, nullptr, nullptr, 0, 1);
    silu_mul_kernel<<<(MQ*MLPm + 255)/256, 256>>>(gb, ub, hb, MQ*MLPm);
    gemm_nt(hb, ff_down, out, MQ, Dm, MLPm, x2, mods + 2*Bb*3*Dm + 2*Dm, 3*Dm, Nn);
}

// round 4
// speedup vs baseline: 3.4425x; 1.1922x over previous
#include <cuda_runtime.h>
#include <math.h>
#include <stdint.h>

// Problem dims
#define Dm    1024
#define Cm    2048
#define MLPm  4096
#define Hh    16
#define HDh   64
#define Bb    8
#define Nn    512
#define Ss    2048
#define INNER (Hh*HDh)   // 1024
#define EPSf  1e-6f

// ---------------- scratch (static device allocations) ---------------------------
__device__ __align__(16) float d_mods  [3 * Bb * 3 * Dm];
__device__ __align__(16) float d_normed[Bb * Nn * Dm];
__device__ __align__(16) float d_q     [Bb * Nn * INNER];
__device__ __align__(16) float d_k     [Bb * Ss * INNER];
__device__ __align__(16) float d_v     [Bb * Ss * INNER];
__device__ __align__(16) float d_vt    [Bb * Ss * INNER];
__device__ __align__(16) float d_scores[(size_t)Bb * Hh * Nn * Ss];
__device__ __align__(16) float d_attno [Bb * Nn * INNER];
__device__ __align__(16) float d_x1    [Bb * Nn * Dm];
__device__ __align__(16) float d_x2    [Bb * Nn * Dm];
__device__ __align__(16) float d_gbuf  [Bb * Nn * MLPm];
__device__ __align__(16) float d_ubuf  [Bb * Nn * MLPm];
__device__ __align__(16) float d_hbuf  [Bb * Nn * MLPm];
__device__ __align__(16) float d_ctx   [(size_t)Bb * Ss * Cm];     // tf32-rounded context
__device__ __align__(16) float d_wrnd  [22 * 1024 * 1024];         // tf32-rounded weights

// weight offsets inside d_wrnd (in floats)
#define W_SAQ  (0)
#define W_SAK  (1*1024*1024)
#define W_SAV  (2*1024*1024)
#define W_SAO  (3*1024*1024)
#define W_CAQ  (4*1024*1024)
#define W_CAK  (5*1024*1024)   // 2M
#define W_CAV  (7*1024*1024)   // 2M
#define W_CAO  (9*1024*1024)
#define W_FFG  (10*1024*1024)  // 4M
#define W_FFU  (14*1024*1024)  // 4M
#define W_FFD  (18*1024*1024)  // 4M

// ---------------- tf32 helpers ---------------------------------------------------
__device__ __forceinline__ uint32_t f2tf32(float f) {
    uint32_t o;
    asm("cvt.rna.tf32.f32 %0, %1;" : "=r"(o) : "f"(f));
    return o;
}
__device__ __forceinline__ float rndtf32(float f) { return __uint_as_float(f2tf32(f)); }

__device__ __forceinline__ void mma_tf32(float* c, const uint32_t* a, const uint32_t* b) {
    asm volatile(
        "mma.sync.aligned.m16n8k8.row.col.f32.tf32.tf32.f32 "
        "{%0,%1,%2,%3}, {%4,%5,%6,%7}, {%8,%9}, {%0,%1,%2,%3};\n"
        : "+f"(c[0]), "+f"(c[1]), "+f"(c[2]), "+f"(c[3])
        : "r"(a[0]), "r"(a[1]), "r"(a[2]), "r"(a[3]), "r"(b[0]), "r"(b[1]));
}

__device__ __forceinline__ void cpasync16(uint32_t saddr, const void* gptr) {
    asm volatile("cp.async.cg.shared.global [%0], [%1], 16;\n" :: "r"(saddr), "l"(gptr));
}
__device__ __forceinline__ void cp_commit() { asm volatile("cp.async.commit_group;\n"); }
template<int n> __device__ __forceinline__ void cp_wait() {
    asm volatile("cp.async.wait_group %0;\n" :: "n"(n));
}

// ---------------- cp.async 3-stage pipelined tf32 NT GEMM -----------------------
// C(M,N) = A(M,K) @ B(N,K)^T ; both K-major row-major, values pre-rounded to tf32.
// Batched via blockIdx.z. EPI==1: C = resid + gate[(row/rows_per_b)*gate_ld+col]*acc
// RND==1: round output to tf32 (for tensors feeding another GEMM).
template<int BM,int BN,int WM,int WN,int EPI,int RND>
__global__ void __launch_bounds__(256)
mma_nt_cp(const float* __restrict__ A, const float* __restrict__ Bg, float* __restrict__ C,
          int K, int lda, int ldb, int ldc,
          long sAo, long sAi, long sBo, long sBi, long sCo, long sCi, int nInner,
          const float* __restrict__ resid, const float* __restrict__ gate,
          int gate_ld, int rows_per_b)
{
    constexpr int BK   = 32;
    constexpr int LDSW = BK + 4;          // 36 words: conflict-free frag loads
    constexpr int ST   = 3;
    constexpr int MT   = WM / 16;
    constexpr int NTJ  = WN / 8;
    constexpr int WMX  = BM / WM;
    constexpr int AIT  = (BM * 8) / 256;
    constexpr int BIT  = (BN * 8) / 256;

    extern __shared__ float smf[];
    float* As = smf;                          // ST * BM * LDSW
    float* Bs = smf + ST * BM * LDSW;         // ST * BN * LDSW

    int z  = blockIdx.z;
    int zo = z / nInner, zi = z - zo * nInner;
    A  += zo * sAo + zi * sAi;
    Bg += zo * sBo + zi * sBi;
    C  += zo * sCo + zi * sCi;

    const int tid  = threadIdx.x;
    const int wid  = tid >> 5;
    const int lane = tid & 31;
    const int g    = lane >> 2;
    const int c4   = lane & 3;
    const int wm   = wid % WMX;
    const int wn   = wid / WMX;
    const int row0 = blockIdx.y * BM;
    const int col0 = blockIdx.x * BN;

    const float* Ab  = A + (size_t)row0 * lda;
    const float* Bb_ = Bg + (size_t)col0 * ldb;
    const int ldRow = tid >> 3;
    const int ldCol = (tid & 7) * 4;

    const uint32_t sA = (uint32_t)__cvta_generic_to_shared(As);
    const uint32_t sB = (uint32_t)__cvta_generic_to_shared(Bs);

    const int nTiles = K / BK;

    // prologue: stage 0..ST-2
    #pragma unroll
    for (int s = 0; s < ST - 1; s++) {
        if (s < nTiles) {
            const int kt = s * BK;
            #pragma unroll
            for (int it = 0; it < AIT; it++)
                cpasync16(sA + (uint32_t)(((s * BM) + (it * 32 + ldRow)) * LDSW + ldCol) * 4,
                          Ab + (size_t)(it * 32 + ldRow) * lda + kt + ldCol);
            #pragma unroll
            for (int it = 0; it < BIT; it++)
                cpasync16(sB + (uint32_t)(((s * BN) + (it * 32 + ldRow)) * LDSW + ldCol) * 4,
                          Bb_ + (size_t)(it * 32 + ldRow) * ldb + kt + ldCol);
        }
        cp_commit();
    }
    cp_wait<ST - 2>();
    __syncthreads();

    float acc[MT][NTJ][4];
    #pragma unroll
    for (int i = 0; i < MT; i++)
        #pragma unroll
        for (int j = 0; j < NTJ; j++)
            #pragma unroll
            for (int r = 0; r < 4; r++) acc[i][j][r] = 0.f;

    for (int t = 0; t < nTiles; t++) {
        const uint32_t* Asb = (const uint32_t*)(As + (t % ST) * BM * LDSW);
        const uint32_t* Bsb = (const uint32_t*)(Bs + (t % ST) * BN * LDSW);

        uint32_t af[2][MT][4], bf[2][NTJ][2];

        auto loadfrag = [&](int ks, uint32_t (&afr)[MT][4], uint32_t (&bfr)[NTJ][2]) {
            const int kk = ks * 8;
            #pragma unroll
            for (int i = 0; i < MT; i++) {
                int m = wm * WM + 16 * i + g;
                afr[i][0] = Asb[(m    ) * LDSW + kk + c4];
                afr[i][1] = Asb[(m + 8) * LDSW + kk + c4];
                afr[i][2] = Asb[(m    ) * LDSW + kk + c4 + 4];
                afr[i][3] = Asb[(m + 8) * LDSW + kk + c4 + 4];
            }
            #pragma unroll
            for (int j = 0; j < NTJ; j++) {
                int n = wn * WN + 8 * j + g;
                bfr[j][0] = Bsb[n * LDSW + kk + c4];
                bfr[j][1] = Bsb[n * LDSW + kk + c4 + 4];
            }
        };

        loadfrag(0, af[0], bf[0]);
        #pragma unroll
        for (int ks = 0; ks < BK / 8; ks++) {
            const int cur = ks & 1;
            if (ks + 1 < BK / 8) loadfrag(ks + 1, af[cur ^ 1], bf[cur ^ 1]);
            #pragma unroll
            for (int i = 0; i < MT; i++)
                #pragma unroll
                for (int j = 0; j < NTJ; j++)
                    mma_tf32(acc[i][j], af[cur][i], bf[cur][j]);
        }

        // prefetch tile t+ST-1
        const int tn = t + ST - 1;
        if (tn < nTiles) {
            const int st = tn % ST;
            const int kt = tn * BK;
            #pragma unroll
            for (int it = 0; it < AIT; it++)
                cpasync16(sA + (uint32_t)(((st * BM) + (it * 32 + ldRow)) * LDSW + ldCol) * 4,
                          Ab + (size_t)(it * 32 + ldRow) * lda + kt + ldCol);
            #pragma unroll
            for (int it = 0; it < BIT; it++)
                cpasync16(sB + (uint32_t)(((st * BN) + (it * 32 + ldRow)) * LDSW + ldCol) * 4,
                          Bb_ + (size_t)(it * 32 + ldRow) * ldb + kt + ldCol);
        }
        cp_commit();
        cp_wait<ST - 2>();
        __syncthreads();
    }

    // epilogue
    #pragma unroll
    for (int i = 0; i < MT; i++) {
        #pragma unroll
        for (int j = 0; j < NTJ; j++) {
            int col = col0 + wn * WN + 8 * j + 2 * c4;
            #pragma unroll
            for (int half = 0; half < 2; half++) {
                int row = row0 + wm * WM + 16 * i + g + 8 * half;
                float v0 = acc[i][j][2 * half + 0];
                float v1 = acc[i][j][2 * half + 1];
                if (EPI == 1) {
                    const float* rr = resid + (size_t)row * ldc + col;
                    const float* gg = gate + (size_t)(row / rows_per_b) * gate_ld + col;
                    v0 = rr[0] + gg[0] * v0;
                    v1 = rr[1] + gg[1] * v1;
                }
                if (RND == 1) { v0 = rndtf32(v0); v1 = rndtf32(v1); }
                *(float2*)(C + (size_t)row * ldc + col) = make_float2(v0, v1);
            }
        }
    }
}

// ---------------- round-to-tf32 elementwise -------------------------------------
__global__ void round_tf32_kernel(const float4* __restrict__ in, float4* __restrict__ out, int n4)
{
    int i = blockIdx.x * blockDim.x + threadIdx.x;
    if (i < n4) {
        float4 t = in[i];
        out[i] = make_float4(rndtf32(t.x), rndtf32(t.y), rndtf32(t.z), rndtf32(t.w));
    }
}

// ---------------- per-batch transpose: in [b][R][Cc] -> out [b][Cc][R] ----------
__global__ void transpose_kernel(const float* __restrict__ in, float* __restrict__ out,
                                 int R, int Cc)
{
    __shared__ float t[32][33];
    int c0 = blockIdx.x * 32, r0 = blockIdx.y * 32;
    in  += (size_t)blockIdx.z * R * Cc;
    out += (size_t)blockIdx.z * R * Cc;
    int tx = threadIdx.x, ty = threadIdx.y;
    #pragma unroll
    for (int i = ty; i < 32; i += 8)
        t[i][tx] = in[(size_t)(r0 + i) * Cc + c0 + tx];
    __syncthreads();
    #pragma unroll
    for (int i = ty; i < 32; i += 8)
        out[(size_t)(c0 + i) * R + r0 + tx] = t[tx][i];
}

// ---------------- modulation: mods[norm][b][3D] = cond @ mw^T + mb --------------
__global__ void mod_kernel(const float* __restrict__ cond,
                           const float* __restrict__ mw0, const float* __restrict__ mb0,
                           const float* __restrict__ mw1, const float* __restrict__ mb1,
                           const float* __restrict__ mw2, const float* __restrict__ mb2,
                           float* __restrict__ mods)
{
    __shared__ float cs[Bb * Dm];
    for (int i = threadIdx.x; i < Bb * Dm; i += blockDim.x) cs[i] = cond[i];
    __syncthreads();

    int warp = threadIdx.x >> 5, lane = threadIdx.x & 31;
    int j = blockIdx.x * 8 + warp;
    int norm = j / (3*Dm), jj = j - norm * (3*Dm);
    const float* mw = (norm == 0) ? mw0 : (norm == 1) ? mw1 : mw2;
    const float* mb = (norm == 0) ? mb0 : (norm == 1) ? mb1 : mb2;

    float acc[Bb];
    #pragma unroll
    for (int b = 0; b < Bb; b++) acc[b] = 0.f;
    const float* wrow = mw + (size_t)jj * Dm;
    for (int d = lane; d < Dm; d += 32) {
        float w = wrow[d];
        #pragma unroll
        for (int b = 0; b < Bb; b++) acc[b] = fmaf(w, cs[b*Dm + d], acc[b]);
    }
    #pragma unroll
    for (int b = 0; b < Bb; b++)
        #pragma unroll
        for (int off = 16; off > 0; off >>= 1)
            acc[b] += __shfl_xor_sync(0xffffffff, acc[b], off);
    if (lane < Bb)
        mods[(size_t)norm * Bb * 3*Dm + lane * 3*Dm + jj] = acc[lane] + mb[jj];
}

// ---------------- adaRMS norm (tf32-rounded output: feeds GEMMs) ----------------
__global__ void rmsnorm_kernel(const float* __restrict__ x, const float* __restrict__ w,
                               const float* __restrict__ mod_base,
                               float* __restrict__ out)
{
    int row = blockIdx.x;
    int b   = row / Nn;
    const float* xr = x + (size_t)row * Dm;
    const float* ms = mod_base + b * 3*Dm;

    float ss = 0.f;
    for (int i = threadIdx.x; i < Dm; i += blockDim.x) { float t = xr[i]; ss = fmaf(t,t,ss); }
    #pragma unroll
    for (int off = 16; off > 0; off >>= 1) ss += __shfl_xor_sync(0xffffffff, ss, off);
    __shared__ float red[8];
    if ((threadIdx.x & 31) == 0) red[threadIdx.x >> 5] = ss;
    __syncthreads();
    if (threadIdx.x < 8) {
        float v = red[threadIdx.x];
        #pragma unroll
        for (int off = 4; off > 0; off >>= 1) v += __shfl_xor_sync(0xff, v, off);
        if (threadIdx.x == 0) red[0] = v;
    }
    __syncthreads();
    float rn = rsqrtf(red[0] * (1.0f/Dm) + EPSf);

    float* orow = out + (size_t)row * Dm;
    for (int i = threadIdx.x; i < Dm; i += blockDim.x) {
        float scale = ms[i], shift = ms[Dm + i];
        orow[i] = rndtf32(xr[i] * rn * w[i] * (1.0f + scale) + shift);
    }
}

// ---------------- row softmax (in place; tf32-rounded output feeds PV GEMM) -----
__global__ void softmax_kernel(float* __restrict__ sc, int S, float scale)
{
    extern __shared__ float v[];
    float* p = sc + (size_t)blockIdx.x * S;
    int tid = threadIdx.x, nt = blockDim.x;
    __shared__ float red[8];

    float m = -1e30f;
    for (int i = tid; i < S; i += nt) { float x = p[i] * scale; v[i] = x; m = fmaxf(m, x); }
    #pragma unroll
    for (int off = 16; off > 0; off >>= 1) m = fmaxf(m, __shfl_xor_sync(0xffffffff, m, off));
    if ((tid & 31) == 0) red[tid >> 5] = m;
    __syncthreads();
    if (tid < 8) {
        float t = red[tid];
        #pragma unroll
        for (int off = 4; off > 0; off >>= 1) t = fmaxf(t, __shfl_xor_sync(0xff, t, off));
        if (tid == 0) red[0] = t;
    }
    __syncthreads();
    m = red[0];
    __syncthreads();

    float sum = 0.f;
    for (int i = tid; i < S; i += nt) { float e = __expf(v[i] - m); v[i] = e; sum += e; }
    #pragma unroll
    for (int off = 16; off > 0; off >>= 1) sum += __shfl_xor_sync(0xffffffff, sum, off);
    if ((tid & 31) == 0) red[tid >> 5] = sum;
    __syncthreads();
    if (tid < 8) {
        float t = red[tid];
        #pragma unroll
        for (int off = 4; off > 0; off >>= 1) t += __shfl_xor_sync(0xff, t, off);
        if (tid == 0) red[0] = t;
    }
    __syncthreads();
    float inv = 1.0f / red[0];
    for (int i = tid; i < S; i += nt) p[i] = rndtf32(v[i] * inv);
}

// ---------------- silu(g)*u (tf32-rounded: feeds down-proj GEMM) -----------------
__global__ void silu_mul_kernel(const float* __restrict__ g, const float* __restrict__ u,
                                float* __restrict__ h, int n)
{
    int i = blockIdx.x * blockDim.x + threadIdx.x;
    if (i < n) {
        float x = g[i];
        h[i] = rndtf32((x / (1.0f + __expf(-x))) * u[i]);
    }
}

// ---------------- host orchestration -------------------------------------------
static float* sym(const void* s) { void* p = nullptr; cudaGetSymbolAddress(&p, s); return (float*)p; }

template<int BM,int BN,int WM,int WN,int EPI,int RND>
static void launch_mma(dim3 grid,
                       const float* A, const float* Bg, float* C,
                       int K, int lda, int ldb, int ldc,
                       long sAo, long sAi, long sBo, long sBi, long sCo, long sCi, int nInner,
                       const float* resid, const float* gate, int gate_ld, int rpb)
{
    size_t sm = (size_t)3 * (BM + BN) * 36 * sizeof(float);
    cudaFuncSetAttribute(mma_nt_cp<BM,BN,WM,WN,EPI,RND>,
                         cudaFuncAttributeMaxDynamicSharedMemorySize, (int)sm);
    mma_nt_cp<BM,BN,WM,WN,EPI,RND><<<grid, 256, sm>>>(
        A, Bg, C, K, lda, ldb, ldc,
        sAo, sAi, sBo, sBi, sCo, sCi, nInner, resid, gate, gate_ld, rpb);
}

// C = A(M,K) @ W(N,K)^T (non-batched)
template<int EPI,int RND>
static void gemm_nt(const float* A, const float* W, float* C, int M, int N, int K,
                    const float* resid, const float* gate, int gate_ld, int rpb)
{
    dim3 grid(N/128, M/128, 1);
    launch_mma<128,128,64,32,EPI,RND>(grid, A, W, C, K, K, K, N,
        0,0,0,0,0,0,1, resid, gate, gate_ld, rpb);
}

static void round_to(float* dst, const float* src, int n)
{
    round_tf32_kernel<<<(n/4 + 255)/256, 256>>>((const float4*)src, (float4*)dst, n/4);
}

extern "C" void kernel_launch(void* const* d_in, const int* in_sizes, int n_in,
                              void* d_out, int out_size)
{
    const float* x       = (const float*)d_in[0];
    const float* context = (const float*)d_in[1];
    const float* cond    = (const float*)d_in[2];
    const float* n1_w  = (const float*)d_in[3];
    const float* n1_mw = (const float*)d_in[4];
    const float* n1_mb = (const float*)d_in[5];
    const float* n2_w  = (const float*)d_in[6];
    const float* n2_mw = (const float*)d_in[7];
    const float* n2_mb = (const float*)d_in[8];
    const float* n3_w  = (const float*)d_in[9];
    const float* n3_mw = (const float*)d_in[10];
    const float* n3_mb = (const float*)d_in[11];
    const float* sa_q  = (const float*)d_in[12];
    const float* sa_k  = (const float*)d_in[13];
    const float* sa_v  = (const float*)d_in[14];
    const float* sa_o  = (const float*)d_in[15];
    const float* ca_q  = (const float*)d_in[16];
    const float* ca_k  = (const float*)d_in[17];
    const float* ca_v  = (const float*)d_in[18];
    const float* ca_o  = (const float*)d_in[19];
    const float* ff_gate = (const float*)d_in[20];
    const float* ff_up   = (const float*)d_in[21];
    const float* ff_down = (const float*)d_in[22];
    float* out = (float*)d_out;

    float* mods   = sym(d_mods);
    float* normed = sym(d_normed);
    float* q      = sym(d_q);
    float* k      = sym(d_k);
    float* v      = sym(d_v);
    float* vt     = sym(d_vt);
    float* sc     = sym(d_scores);
    float* ao     = sym(d_attno);
    float* x1     = sym(d_x1);
    float* x2     = sym(d_x2);
    float* gb     = sym(d_gbuf);
    float* ub     = sym(d_ubuf);
    float* hb     = sym(d_hbuf);
    float* ctx    = sym(d_ctx);
    float* wr     = sym(d_wrnd);

    const int MQ = Bb * Nn;
    const float sm_scale = 0.125f;

    // round weights + context to tf32 (rna) once per launch
    round_to(wr + W_SAQ, sa_q, INNER*Dm);
    round_to(wr + W_SAK, sa_k, INNER*Dm);
    round_to(wr + W_SAV, sa_v, INNER*Dm);
    round_to(wr + W_SAO, sa_o, Dm*INNER);
    round_to(wr + W_CAQ, ca_q, INNER*Dm);
    round_to(wr + W_CAK, ca_k, INNER*Cm);
    round_to(wr + W_CAV, ca_v, INNER*Cm);
    round_to(wr + W_CAO, ca_o, Dm*INNER);
    round_to(wr + W_FFG, ff_gate, MLPm*Dm);
    round_to(wr + W_FFU, ff_up,   MLPm*Dm);
    round_to(wr + W_FFD, ff_down, Dm*MLPm);
    round_to(ctx, context, Bb*Ss*Cm);

    mod_kernel<<<(3*3*Dm)/8, 256>>>(cond, n1_mw, n1_mb, n2_mw, n2_mb, n3_mw, n3_mb, mods);

    // ===================== Self attention =====================
    rmsnorm_kernel<<<MQ, 256>>>(x, n1_w, mods + 0*Bb*3*Dm, normed);
    gemm_nt<0,1>(normed, wr + W_SAQ, q, MQ, INNER, Dm, nullptr, nullptr, 0, 1);
    gemm_nt<0,1>(normed, wr + W_SAK, k, MQ, INNER, Dm, nullptr, nullptr, 0, 1);
    gemm_nt<0,1>(normed, wr + W_SAV, v, MQ, INNER, Dm, nullptr, nullptr, 0, 1);
    transpose_kernel<<<dim3(INNER/32, Nn/32, Bb), dim3(32,8)>>>(v, vt, Nn, INNER);

    // scores[b,h] = Q[b,:,h,:] @ K[b,:,h,:]^T
    launch_mma<128,128,64,32,0,0>(dim3(Nn/128, Nn/128, Bb*Hh),
        q, k, sc, HDh, INNER, INNER, Nn,
        (long)Nn*INNER, HDh, (long)Nn*INNER, HDh, (long)Hh*Nn*Nn, (long)Nn*Nn, Hh,
        nullptr, nullptr, 0, 1);
    softmax_kernel<<<Bb*Hh*Nn, 256, Nn*sizeof(float)>>>(sc, Nn, sm_scale);
    // O = P @ Vt^T
    launch_mma<128,64,64,16,0,1>(dim3(1, Nn/128, Bb*Hh),
        sc, vt, ao, Nn, Nn, Nn, INNER,
        (long)Hh*Nn*Nn, (long)Nn*Nn, (long)INNER*Nn, (long)HDh*Nn, (long)Nn*INNER, HDh, Hh,
        nullptr, nullptr, 0, 1);
    gemm_nt<1,0>(ao, wr + W_SAO, x1, MQ, Dm, INNER, x, mods + 0*Bb*3*Dm + 2*Dm, 3*Dm, Nn);

    // ===================== Cross attention =====================
    rmsnorm_kernel<<<MQ, 256>>>(x1, n2_w, mods + 1*Bb*3*Dm, normed);
    gemm_nt<0,1>(normed, wr + W_CAQ, q, MQ, INNER, Dm, nullptr, nullptr, 0, 1);
    gemm_nt<0,1>(ctx, wr + W_CAK, k, Bb*Ss, INNER, Cm, nullptr, nullptr, 0, 1);
    gemm_nt<0,1>(ctx, wr + W_CAV, v, Bb*Ss, INNER, Cm, nullptr, nullptr, 0, 1);
    transpose_kernel<<<dim3(INNER/32, Ss/32, Bb), dim3(32,8)>>>(v, vt, Ss, INNER);

    launch_mma<128,128,64,32,0,0>(dim3(Ss/128, Nn/128, Bb*Hh),
        q, k, sc, HDh, INNER, INNER, Ss,
        (long)Nn*INNER, HDh, (long)Ss*INNER, HDh, (long)Hh*Nn*Ss, (long)Nn*Ss, Hh,
        nullptr, nullptr, 0, 1);
    softmax_kernel<<<Bb*Hh*Nn, 256, Ss*sizeof(float)>>>(sc, Ss, sm_scale);
    launch_mma<128,64,64,16,0,1>(dim3(1, Nn/128, Bb*Hh),
        sc, vt, ao, Ss, Ss, Ss, INNER,
        (long)Hh*Nn*Ss, (long)Nn*Ss, (long)INNER*Ss, (long)HDh*Ss, (long)Nn*INNER, HDh, Hh,
        nullptr, nullptr, 0, 1);
    gemm_nt<1,0>(ao, wr + W_CAO, x2, MQ, Dm, INNER, x1, mods + 1*Bb*3*Dm + 2*Dm, 3*Dm, Nn);

    // ===================== FFN =====================
    rmsnorm_kernel<<<MQ, 256>>>(x2, n3_w, mods + 2*Bb*3*Dm, normed);
    gemm_nt<0,0>(normed, wr + W_FFG, gb, MQ, MLPm, Dm, nullptr, nullptr, 0, 1);
    gemm_nt<0,0>(normed, wr + W_FFU, ub, MQ, MLPm, Dm, nullptr, nullptr, 0, 1);
    silu_mul_kernel<<<(MQ*MLPm + 255)/256, 256>>>(gb, ub, hb, MQ*MLPm);
    gemm_nt<1,0>(hb, wr + W_FFD, out, MQ, Dm, MLPm, x2, mods + 2*Bb*3*Dm + 2*Dm, 3*Dm, Nn);
}

// round 5
// speedup vs baseline: 3.9199x; 1.1387x over previous
#include <cuda_runtime.h>
#include <math.h>
#include <stdint.h>

// Problem dims
#define Dm    1024
#define Cm    2048
#define MLPm  4096
#define Hh    16
#define HDh   64
#define Bb    8
#define Nn    512
#define Ss    2048
#define INNER (Hh*HDh)   // 1024
#define EPSf  1e-6f

// ---------------- scratch (static device allocations) ---------------------------
__device__ __align__(16) float d_mods  [3 * Bb * 3 * Dm];
__device__ __align__(16) float d_normed[Bb * Nn * Dm];
__device__ __align__(16) float d_q     [Bb * Nn * INNER];
__device__ __align__(16) float d_k     [Bb * Ss * INNER];
__device__ __align__(16) float d_v     [Bb * Ss * INNER];
__device__ __align__(16) float d_attno [Bb * Nn * INNER];
__device__ __align__(16) float d_x1    [Bb * Nn * Dm];
__device__ __align__(16) float d_x2    [Bb * Nn * Dm];
__device__ __align__(16) float d_gbuf  [Bb * Nn * MLPm];
__device__ __align__(16) float d_ubuf  [Bb * Nn * MLPm];
__device__ __align__(16) float d_hbuf  [Bb * Nn * MLPm];
__device__ __align__(16) float d_ctx   [(size_t)Bb * Ss * Cm];     // tf32-rounded context
__device__ __align__(16) float d_wrnd  [22 * 1024 * 1024];         // tf32-rounded weights

#define W_SAQ  (0)
#define W_SAK  (1*1024*1024)
#define W_SAV  (2*1024*1024)
#define W_SAO  (3*1024*1024)
#define W_CAQ  (4*1024*1024)
#define W_CAK  (5*1024*1024)
#define W_CAV  (7*1024*1024)
#define W_CAO  (9*1024*1024)
#define W_FFG  (10*1024*1024)
#define W_FFU  (14*1024*1024)
#define W_FFD  (18*1024*1024)

// ---------------- tf32 helpers ---------------------------------------------------
__device__ __forceinline__ uint32_t f2tf32(float f) {
    uint32_t o;
    asm("cvt.rna.tf32.f32 %0, %1;" : "=r"(o) : "f"(f));
    return o;
}
__device__ __forceinline__ float rndtf32(float f) { return __uint_as_float(f2tf32(f)); }

__device__ __forceinline__ void mma_tf32(float* c, const uint32_t* a, const uint32_t* b) {
    asm volatile(
        "mma.sync.aligned.m16n8k8.row.col.f32.tf32.tf32.f32 "
        "{%0,%1,%2,%3}, {%4,%5,%6,%7}, {%8,%9}, {%0,%1,%2,%3};\n"
        : "+f"(c[0]), "+f"(c[1]), "+f"(c[2]), "+f"(c[3])
        : "r"(a[0]), "r"(a[1]), "r"(a[2]), "r"(a[3]), "r"(b[0]), "r"(b[1]));
}

__device__ __forceinline__ void cpasync16(uint32_t saddr, const void* gptr) {
    asm volatile("cp.async.cg.shared.global [%0], [%1], 16;\n" :: "r"(saddr), "l"(gptr));
}
__device__ __forceinline__ void cp_commit() { asm volatile("cp.async.commit_group;\n"); }
template<int n> __device__ __forceinline__ void cp_wait() {
    asm volatile("cp.async.wait_group %0;\n" :: "n"(n));
}

// ---------------- cp.async 3-stage pipelined tf32 NT GEMM -----------------------
template<int BM,int BN,int WM,int WN,int EPI,int RND>
__global__ void __launch_bounds__(256)
mma_nt_cp(const float* __restrict__ A, const float* __restrict__ Bg, float* __restrict__ C,
          int K, int lda, int ldb, int ldc,
          long sAo, long sAi, long sBo, long sBi, long sCo, long sCi, int nInner,
          const float* __restrict__ resid, const float* __restrict__ gate,
          int gate_ld, int rows_per_b)
{
    constexpr int BK   = 32;
    constexpr int LDSW = BK + 4;
    constexpr int ST   = 3;
    constexpr int MT   = WM / 16;
    constexpr int NTJ  = WN / 8;
    constexpr int WMX  = BM / WM;
    constexpr int AIT  = (BM * 8) / 256;
    constexpr int BIT  = (BN * 8) / 256;

    extern __shared__ float smf[];
    float* As = smf;
    float* Bs = smf + ST * BM * LDSW;

    int z  = blockIdx.z;
    int zo = z / nInner, zi = z - zo * nInner;
    A  += zo * sAo + zi * sAi;
    Bg += zo * sBo + zi * sBi;
    C  += zo * sCo + zi * sCi;

    const int tid  = threadIdx.x;
    const int wid  = tid >> 5;
    const int lane = tid & 31;
    const int g    = lane >> 2;
    const int c4   = lane & 3;
    const int wm   = wid % WMX;
    const int wn   = wid / WMX;
    const int row0 = blockIdx.y * BM;
    const int col0 = blockIdx.x * BN;

    const float* Ab  = A + (size_t)row0 * lda;
    const float* Bb_ = Bg + (size_t)col0 * ldb;
    const int ldRow = tid >> 3;
    const int ldCol = (tid & 7) * 4;

    const uint32_t sA = (uint32_t)__cvta_generic_to_shared(As);
    const uint32_t sB = (uint32_t)__cvta_generic_to_shared(Bs);

    const int nTiles = K / BK;

    #pragma unroll
    for (int s = 0; s < ST - 1; s++) {
        if (s < nTiles) {
            const int kt = s * BK;
            #pragma unroll
            for (int it = 0; it < AIT; it++)
                cpasync16(sA + (uint32_t)(((s * BM) + (it * 32 + ldRow)) * LDSW + ldCol) * 4,
                          Ab + (size_t)(it * 32 + ldRow) * lda + kt + ldCol);
            #pragma unroll
            for (int it = 0; it < BIT; it++)
                cpasync16(sB + (uint32_t)(((s * BN) + (it * 32 + ldRow)) * LDSW + ldCol) * 4,
                          Bb_ + (size_t)(it * 32 + ldRow) * ldb + kt + ldCol);
        }
        cp_commit();
    }
    cp_wait<ST - 2>();
    __syncthreads();

    float acc[MT][NTJ][4];
    #pragma unroll
    for (int i = 0; i < MT; i++)
        #pragma unroll
        for (int j = 0; j < NTJ; j++)
            #pragma unroll
            for (int r = 0; r < 4; r++) acc[i][j][r] = 0.f;

    for (int t = 0; t < nTiles; t++) {
        const uint32_t* Asb = (const uint32_t*)(As + (t % ST) * BM * LDSW);
        const uint32_t* Bsb = (const uint32_t*)(Bs + (t % ST) * BN * LDSW);

        uint32_t af[2][MT][4], bf[2][NTJ][2];

        auto loadfrag = [&](int ks, uint32_t (&afr)[MT][4], uint32_t (&bfr)[NTJ][2]) {
            const int kk = ks * 8;
            #pragma unroll
            for (int i = 0; i < MT; i++) {
                int m = wm * WM + 16 * i + g;
                afr[i][0] = Asb[(m    ) * LDSW + kk + c4];
                afr[i][1] = Asb[(m + 8) * LDSW + kk + c4];
                afr[i][2] = Asb[(m    ) * LDSW + kk + c4 + 4];
                afr[i][3] = Asb[(m + 8) * LDSW + kk + c4 + 4];
            }
            #pragma unroll
            for (int j = 0; j < NTJ; j++) {
                int n = wn * WN + 8 * j + g;
                bfr[j][0] = Bsb[n * LDSW + kk + c4];
                bfr[j][1] = Bsb[n * LDSW + kk + c4 + 4];
            }
        };

        loadfrag(0, af[0], bf[0]);
        #pragma unroll
        for (int ks = 0; ks < BK / 8; ks++) {
            const int cur = ks & 1;
            if (ks + 1 < BK / 8) loadfrag(ks + 1, af[cur ^ 1], bf[cur ^ 1]);
            #pragma unroll
            for (int i = 0; i < MT; i++)
                #pragma unroll
                for (int j = 0; j < NTJ; j++)
                    mma_tf32(acc[i][j], af[cur][i], bf[cur][j]);
        }

        const int tn = t + ST - 1;
        if (tn < nTiles) {
            const int st = tn % ST;
            const int kt = tn * BK;
            #pragma unroll
            for (int it = 0; it < AIT; it++)
                cpasync16(sA + (uint32_t)(((st * BM) + (it * 32 + ldRow)) * LDSW + ldCol) * 4,
                          Ab + (size_t)(it * 32 + ldRow) * lda + kt + ldCol);
            #pragma unroll
            for (int it = 0; it < BIT; it++)
                cpasync16(sB + (uint32_t)(((st * BN) + (it * 32 + ldRow)) * LDSW + ldCol) * 4,
                          Bb_ + (size_t)(it * 32 + ldRow) * ldb + kt + ldCol);
        }
        cp_commit();
        cp_wait<ST - 2>();
        __syncthreads();
    }

    #pragma unroll
    for (int i = 0; i < MT; i++) {
        #pragma unroll
        for (int j = 0; j < NTJ; j++) {
            int col = col0 + wn * WN + 8 * j + 2 * c4;
            #pragma unroll
            for (int half = 0; half < 2; half++) {
                int row = row0 + wm * WM + 16 * i + g + 8 * half;
                float v0 = acc[i][j][2 * half + 0];
                float v1 = acc[i][j][2 * half + 1];
                if (EPI == 1) {
                    const float* rr = resid + (size_t)row * ldc + col;
                    const float* gg = gate + (size_t)(row / rows_per_b) * gate_ld + col;
                    v0 = rr[0] + gg[0] * v0;
                    v1 = rr[1] + gg[1] * v1;
                }
                if (RND == 1) { v0 = rndtf32(v0); v1 = rndtf32(v1); }
                *(float2*)(C + (size_t)row * ldc + col) = make_float2(v0, v1);
            }
        }
    }
}

// ---------------- fused flash attention (tf32 mma, online softmax) ---------------
// CTA: 128 q-rows × one (batch, head). 8 warps, each owns 16 q-rows.
// K/V tiles of 64 rows, double-buffered via cp.async.
// Inputs Q/K/V are tf32-rounded; Q scaled by 0.125 here (exact pow2).
__global__ void __launch_bounds__(256)
flash_kernel(const float* __restrict__ Qg, const float* __restrict__ Kg,
             const float* __restrict__ Vg, float* __restrict__ Og,
             int Skv)
{
    const int h = blockIdx.y, b = blockIdx.z;
    const int n0 = blockIdx.x * 128;
    const float* Qb = Qg + (size_t)b * Nn * INNER + (size_t)n0 * INNER + h * HDh;
    const float* Kb = Kg + (size_t)b * Skv * INNER + h * HDh;
    const float* Vb = Vg + (size_t)b * Skv * INNER + h * HDh;
    float* Ob = Og + (size_t)b * Nn * INNER + (size_t)n0 * INNER + h * HDh;

    extern __shared__ float sm[];
    float* Qs = sm;                    // [128][68]
    float* Ks = Qs + 128 * 68;         // [2][64][68]
    float* Vs = Ks + 2 * 64 * 68;      // [2][64][68]
    float* Ps = Vs + 2 * 64 * 68;      // [128][68] (per-warp private 16-row slices)

    const int tid = threadIdx.x, wid = tid >> 5, lane = tid & 31;
    const int g = lane >> 2, c4 = lane & 3;

    const uint32_t sK = (uint32_t)__cvta_generic_to_shared(Ks);
    const uint32_t sV = (uint32_t)__cvta_generic_to_shared(Vs);

    // load Q tile (scaled)
    #pragma unroll
    for (int it = 0; it < 8; it++) {
        int idx = it * 256 + tid;
        int r = idx >> 4, c = (idx & 15) * 4;
        float4 qv = *(const float4*)(Qb + (size_t)r * INNER + c);
        Qs[r*68 + c + 0] = qv.x * 0.125f;
        Qs[r*68 + c + 1] = qv.y * 0.125f;
        Qs[r*68 + c + 2] = qv.z * 0.125f;
        Qs[r*68 + c + 3] = qv.w * 0.125f;
    }

    // prefetch KV tile 0 into buf 0
    auto loadKV = [&](int t, int buf) {
        const float* Ksrc = Kb + (size_t)(t * 64) * INNER;
        const float* Vsrc = Vb + (size_t)(t * 64) * INNER;
        #pragma unroll
        for (int it = 0; it < 4; it++) {
            int idx = it * 256 + tid;
            int r = idx >> 4, c = (idx & 15) * 4;
            cpasync16(sK + (uint32_t)((buf*64 + r)*68 + c)*4, Ksrc + (size_t)r * INNER + c);
            cpasync16(sV + (uint32_t)((buf*64 + r)*68 + c)*4, Vsrc + (size_t)r * INNER + c);
        }
    };
    loadKV(0, 0);
    cp_commit();
    cp_wait<0>();
    __syncthreads();

    // per-warp Q fragments (reused for every KV tile)
    uint32_t qf[8][4];
    {
        const uint32_t* Qw = (const uint32_t*)(Qs + wid * 16 * 68);
        #pragma unroll
        for (int ks = 0; ks < 8; ks++) {
            qf[ks][0] = Qw[(g    )*68 + 8*ks + c4];
            qf[ks][1] = Qw[(g + 8)*68 + 8*ks + c4];
            qf[ks][2] = Qw[(g    )*68 + 8*ks + c4 + 4];
            qf[ks][3] = Qw[(g + 8)*68 + 8*ks + c4 + 4];
        }
    }

    float o[8][4];
    #pragma unroll
    for (int j = 0; j < 8; j++)
        #pragma unroll
        for (int r = 0; r < 4; r++) o[j][r] = 0.f;
    float m0 = -1e30f, m1 = -1e30f, l0 = 0.f, l1 = 0.f;

    const int nT = Skv / 64;
    int buf = 0;

    float* Pw = Ps + wid * 16 * 68;
    const uint32_t* Pwu = (const uint32_t*)Pw;

    for (int t = 0; t < nT; t++) {
        if (t + 1 < nT) loadKV(t + 1, buf ^ 1);
        cp_commit();

        // S = Q @ K^T  (128x64 per CTA; this warp: 16x64)
        float s[8][4];
        #pragma unroll
        for (int j = 0; j < 8; j++)
            #pragma unroll
            for (int r = 0; r < 4; r++) s[j][r] = 0.f;

        const uint32_t* Kw = (const uint32_t*)(Ks + buf * 64 * 68);
        #pragma unroll
        for (int ks = 0; ks < 8; ks++) {
            #pragma unroll
            for (int j = 0; j < 8; j++) {
                uint32_t bf[2];
                bf[0] = Kw[(8*j + g)*68 + 8*ks + c4];
                bf[1] = Kw[(8*j + g)*68 + 8*ks + c4 + 4];
                mma_tf32(s[j], qf[ks], bf);
            }
        }

        // online softmax update (rows g and g+8 of this warp's 16)
        float rm0 = -1e30f, rm1 = -1e30f;
        #pragma unroll
        for (int j = 0; j < 8; j++) {
            rm0 = fmaxf(rm0, fmaxf(s[j][0], s[j][1]));
            rm1 = fmaxf(rm1, fmaxf(s[j][2], s[j][3]));
        }
        rm0 = fmaxf(rm0, __shfl_xor_sync(0xffffffff, rm0, 1));
        rm0 = fmaxf(rm0, __shfl_xor_sync(0xffffffff, rm0, 2));
        rm1 = fmaxf(rm1, __shfl_xor_sync(0xffffffff, rm1, 1));
        rm1 = fmaxf(rm1, __shfl_xor_sync(0xffffffff, rm1, 2));

        float mn0 = fmaxf(m0, rm0), mn1 = fmaxf(m1, rm1);
        float f0 = __expf(m0 - mn0), f1 = __expf(m1 - mn1);
        m0 = mn0; m1 = mn1;

        float sum0 = 0.f, sum1 = 0.f;
        #pragma unroll
        for (int j = 0; j < 8; j++) {
            float p0 = __expf(s[j][0] - mn0);
            float p1 = __expf(s[j][1] - mn0);
            float p2 = __expf(s[j][2] - mn1);
            float p3 = __expf(s[j][3] - mn1);
            sum0 += p0 + p1;
            sum1 += p2 + p3;
            // store P (tf32-rounded) into per-warp smem slice
            *(float2*)(Pw + (g    )*68 + 8*j + 2*c4) = make_float2(rndtf32(p0), rndtf32(p1));
            *(float2*)(Pw + (g + 8)*68 + 8*j + 2*c4) = make_float2(rndtf32(p2), rndtf32(p3));
        }
        sum0 += __shfl_xor_sync(0xffffffff, sum0, 1);
        sum0 += __shfl_xor_sync(0xffffffff, sum0, 2);
        sum1 += __shfl_xor_sync(0xffffffff, sum1, 1);
        sum1 += __shfl_xor_sync(0xffffffff, sum1, 2);
        l0 = l0 * f0 + sum0;
        l1 = l1 * f1 + sum1;

        // rescale O
        #pragma unroll
        for (int j = 0; j < 8; j++) {
            o[j][0] *= f0; o[j][1] *= f0;
            o[j][2] *= f1; o[j][3] *= f1;
        }

        __syncwarp();

        // O += P @ V   (16x64 += 16x64 @ 64x64)
        const uint32_t* Vw = (const uint32_t*)(Vs + buf * 64 * 68);
        #pragma unroll
        for (int jk = 0; jk < 8; jk++) {
            uint32_t af[4];
            af[0] = Pwu[(g    )*68 + 8*jk + c4];
            af[1] = Pwu[(g + 8)*68 + 8*jk + c4];
            af[2] = Pwu[(g    )*68 + 8*jk + c4 + 4];
            af[3] = Pwu[(g + 8)*68 + 8*jk + c4 + 4];
            #pragma unroll
            for (int j = 0; j < 8; j++) {
                uint32_t bf[2];
                bf[0] = Vw[(8*jk + c4    )*68 + 8*j + g];
                bf[1] = Vw[(8*jk + c4 + 4)*68 + 8*j + g];
                mma_tf32(o[j], af, bf);
            }
        }

        cp_wait<0>();
        __syncthreads();
        buf ^= 1;
    }

    // normalize + write (tf32-rounded: feeds output projection GEMM)
    float inv0 = 1.0f / l0, inv1 = 1.0f / l1;
    #pragma unroll
    for (int j = 0; j < 8; j++) {
        int col = 8*j + 2*c4;
        *(float2*)(Ob + (size_t)(wid*16 + g    ) * INNER + col) =
            make_float2(rndtf32(o[j][0] * inv0), rndtf32(o[j][1] * inv0));
        *(float2*)(Ob + (size_t)(wid*16 + g + 8) * INNER + col) =
            make_float2(rndtf32(o[j][2] * inv1), rndtf32(o[j][3] * inv1));
    }
}

// ---------------- round-to-tf32 elementwise -------------------------------------
__global__ void round_tf32_kernel(const float4* __restrict__ in, float4* __restrict__ out, int n4)
{
    int i = blockIdx.x * blockDim.x + threadIdx.x;
    if (i < n4) {
        float4 t = in[i];
        out[i] = make_float4(rndtf32(t.x), rndtf32(t.y), rndtf32(t.z), rndtf32(t.w));
    }
}

// ---------------- modulation ------------------------------------------------------
__global__ void mod_kernel(const float* __restrict__ cond,
                           const float* __restrict__ mw0, const float* __restrict__ mb0,
                           const float* __restrict__ mw1, const float* __restrict__ mb1,
                           const float* __restrict__ mw2, const float* __restrict__ mb2,
                           float* __restrict__ mods)
{
    __shared__ float cs[Bb * Dm];
    for (int i = threadIdx.x; i < Bb * Dm; i += blockDim.x) cs[i] = cond[i];
    __syncthreads();

    int warp = threadIdx.x >> 5, lane = threadIdx.x & 31;
    int j = blockIdx.x * 8 + warp;
    int norm = j / (3*Dm), jj = j - norm * (3*Dm);
    const float* mw = (norm == 0) ? mw0 : (norm == 1) ? mw1 : mw2;
    const float* mb = (norm == 0) ? mb0 : (norm == 1) ? mb1 : mb2;

    float acc[Bb];
    #pragma unroll
    for (int b = 0; b < Bb; b++) acc[b] = 0.f;
    const float* wrow = mw + (size_t)jj * Dm;
    for (int d = lane; d < Dm; d += 32) {
        float w = wrow[d];
        #pragma unroll
        for (int b = 0; b < Bb; b++) acc[b] = fmaf(w, cs[b*Dm + d], acc[b]);
    }
    #pragma unroll
    for (int b = 0; b < Bb; b++)
        #pragma unroll
        for (int off = 16; off > 0; off >>= 1)
            acc[b] += __shfl_xor_sync(0xffffffff, acc[b], off);
    if (lane < Bb)
        mods[(size_t)norm * Bb * 3*Dm + lane * 3*Dm + jj] = acc[lane] + mb[jj];
}

// ---------------- adaRMS norm (tf32-rounded output) ------------------------------
__global__ void rmsnorm_kernel(const float* __restrict__ x, const float* __restrict__ w,
                               const float* __restrict__ mod_base,
                               float* __restrict__ out)
{
    int row = blockIdx.x;
    int b   = row / Nn;
    const float* xr = x + (size_t)row * Dm;
    const float* ms = mod_base + b * 3*Dm;

    float ss = 0.f;
    for (int i = threadIdx.x; i < Dm; i += blockDim.x) { float t = xr[i]; ss = fmaf(t,t,ss); }
    #pragma unroll
    for (int off = 16; off > 0; off >>= 1) ss += __shfl_xor_sync(0xffffffff, ss, off);
    __shared__ float red[8];
    if ((threadIdx.x & 31) == 0) red[threadIdx.x >> 5] = ss;
    __syncthreads();
    if (threadIdx.x < 8) {
        float v = red[threadIdx.x];
        #pragma unroll
        for (int off = 4; off > 0; off >>= 1) v += __shfl_xor_sync(0xff, v, off);
        if (threadIdx.x == 0) red[0] = v;
    }
    __syncthreads();
    float rn = rsqrtf(red[0] * (1.0f/Dm) + EPSf);

    float* orow = out + (size_t)row * Dm;
    for (int i = threadIdx.x; i < Dm; i += blockDim.x) {
        float scale = ms[i], shift = ms[Dm + i];
        orow[i] = rndtf32(xr[i] * rn * w[i] * (1.0f + scale) + shift);
    }
}

// ---------------- silu(g)*u (tf32-rounded) ----------------------------------------
__global__ void silu_mul_kernel(const float* __restrict__ g, const float* __restrict__ u,
                                float* __restrict__ h, int n)
{
    int i = blockIdx.x * blockDim.x + threadIdx.x;
    if (i < n) {
        float x = g[i];
        h[i] = rndtf32((x / (1.0f + __expf(-x))) * u[i]);
    }
}

// ---------------- host orchestration -------------------------------------------
static float* sym(const void* s) { void* p = nullptr; cudaGetSymbolAddress(&p, s); return (float*)p; }

template<int BM,int BN,int WM,int WN,int EPI,int RND>
static void launch_mma(dim3 grid,
                       const float* A, const float* Bg, float* C,
                       int K, int lda, int ldb, int ldc,
                       long sAo, long sAi, long sBo, long sBi, long sCo, long sCi, int nInner,
                       const float* resid, const float* gate, int gate_ld, int rpb)
{
    size_t sm = (size_t)3 * (BM + BN) * 36 * sizeof(float);
    cudaFuncSetAttribute(mma_nt_cp<BM,BN,WM,WN,EPI,RND>,
                         cudaFuncAttributeMaxDynamicSharedMemorySize, (int)sm);
    mma_nt_cp<BM,BN,WM,WN,EPI,RND><<<grid, 256, sm>>>(
        A, Bg, C, K, lda, ldb, ldc,
        sAo, sAi, sBo, sBi, sCo, sCi, nInner, resid, gate, gate_ld, rpb);
}

template<int EPI,int RND>
static void gemm_nt(const float* A, const float* W, float* C, int M, int N, int K,
                    const float* resid, const float* gate, int gate_ld, int rpb)
{
    dim3 grid(N/128, M/128, 1);
    launch_mma<128,128,64,32,EPI,RND>(grid, A, W, C, K, K, K, N,
        0,0,0,0,0,0,1, resid, gate, gate_ld, rpb);
}

static void round_to(float* dst, const float* src, int n)
{
    round_tf32_kernel<<<(n/4 + 255)/256, 256>>>((const float4*)src, (float4*)dst, n/4);
}

static void launch_flash(const float* q, const float* k, const float* v, float* o, int Skv)
{
    size_t sm = (size_t)(128*68 + 4*64*68 + 128*68) * sizeof(float);  // 139264
    cudaFuncSetAttribute(flash_kernel, cudaFuncAttributeMaxDynamicSharedMemorySize, (int)sm);
    flash_kernel<<<dim3(Nn/128, Hh, Bb), 256, sm>>>(q, k, v, o, Skv);
}

extern "C" void kernel_launch(void* const* d_in, const int* in_sizes, int n_in,
                              void* d_out, int out_size)
{
    const float* x       = (const float*)d_in[0];
    const float* context = (const float*)d_in[1];
    const float* cond    = (const float*)d_in[2];
    const float* n1_w  = (const float*)d_in[3];
    const float* n1_mw = (const float*)d_in[4];
    const float* n1_mb = (const float*)d_in[5];
    const float* n2_w  = (const float*)d_in[6];
    const float* n2_mw = (const float*)d_in[7];
    const float* n2_mb = (const float*)d_in[8];
    const float* n3_w  = (const float*)d_in[9];
    const float* n3_mw = (const float*)d_in[10];
    const float* n3_mb = (const float*)d_in[11];
    const float* sa_q  = (const float*)d_in[12];
    const float* sa_k  = (const float*)d_in[13];
    const float* sa_v  = (const float*)d_in[14];
    const float* sa_o  = (const float*)d_in[15];
    const float* ca_q  = (const float*)d_in[16];
    const float* ca_k  = (const float*)d_in[17];
    const float* ca_v  = (const float*)d_in[18];
    const float* ca_o  = (const float*)d_in[19];
    const float* ff_gate = (const float*)d_in[20];
    const float* ff_up   = (const float*)d_in[21];
    const float* ff_down = (const float*)d_in[22];
    float* out = (float*)d_out;

    float* mods   = sym(d_mods);
    float* normed = sym(d_normed);
    float* q      = sym(d_q);
    float* k      = sym(d_k);
    float* v      = sym(d_v);
    float* ao     = sym(d_attno);
    float* x1     = sym(d_x1);
    float* x2     = sym(d_x2);
    float* gb     = sym(d_gbuf);
    float* ub     = sym(d_ubuf);
    float* hb     = sym(d_hbuf);
    float* ctx    = sym(d_ctx);
    float* wr     = sym(d_wrnd);

    const int MQ = Bb * Nn;

    // round weights + context to tf32 (rna) once per launch
    round_to(wr + W_SAQ, sa_q, INNER*Dm);
    round_to(wr + W_SAK, sa_k, INNER*Dm);
    round_to(wr + W_SAV, sa_v, INNER*Dm);
    round_to(wr + W_SAO, sa_o, Dm*INNER);
    round_to(wr + W_CAQ, ca_q, INNER*Dm);
    round_to(wr + W_CAK, ca_k, INNER*Cm);
    round_to(wr + W_CAV, ca_v, INNER*Cm);
    round_to(wr + W_CAO, ca_o, Dm*INNER);
    round_to(wr + W_FFG, ff_gate, MLPm*Dm);
    round_to(wr + W_FFU, ff_up,   MLPm*Dm);
    round_to(wr + W_FFD, ff_down, Dm*MLPm);
    round_to(ctx, context, Bb*Ss*Cm);

    mod_kernel<<<(3*3*Dm)/8, 256>>>(cond, n1_mw, n1_mb, n2_mw, n2_mb, n3_mw, n3_mb, mods);

    // ===================== Self attention =====================
    rmsnorm_kernel<<<MQ, 256>>>(x, n1_w, mods + 0*Bb*3*Dm, normed);
    gemm_nt<0,1>(normed, wr + W_SAQ, q, MQ, INNER, Dm, nullptr, nullptr, 0, 1);
    gemm_nt<0,1>(normed, wr + W_SAK, k, MQ, INNER, Dm, nullptr, nullptr, 0, 1);
    gemm_nt<0,1>(normed, wr + W_SAV, v, MQ, INNER, Dm, nullptr, nullptr, 0, 1);
    launch_flash(q, k, v, ao, Nn);
    gemm_nt<1,0>(ao, wr + W_SAO, x1, MQ, Dm, INNER, x, mods + 0*Bb*3*Dm + 2*Dm, 3*Dm, Nn);

    // ===================== Cross attention =====================
    rmsnorm_kernel<<<MQ, 256>>>(x1, n2_w, mods + 1*Bb*3*Dm, normed);
    gemm_nt<0,1>(normed, wr + W_CAQ, q, MQ, INNER, Dm, nullptr, nullptr, 0, 1);
    gemm_nt<0,1>(ctx, wr + W_CAK, k, Bb*Ss, INNER, Cm, nullptr, nullptr, 0, 1);
    gemm_nt<0,1>(ctx, wr + W_CAV, v, Bb*Ss, INNER, Cm, nullptr, nullptr, 0, 1);
    launch_flash(q, k, v, ao, Ss);
    gemm_nt<1,0>(ao, wr + W_CAO, x2, MQ, Dm, INNER, x1, mods + 1*Bb*3*Dm + 2*Dm, 3*Dm, Nn);

    // ===================== FFN =====================
    rmsnorm_kernel<<<MQ, 256>>>(x2, n3_w, mods + 2*Bb*3*Dm, normed);
    gemm_nt<0,0>(normed, wr + W_FFG, gb, MQ, MLPm, Dm, nullptr, nullptr, 0, 1);
    gemm_nt<0,0>(normed, wr + W_FFU, ub, MQ, MLPm, Dm, nullptr, nullptr, 0, 1);
    silu_mul_kernel<<<(MQ*MLPm + 255)/256, 256>>>(gb, ub, hb, MQ*MLPm);
    gemm_nt<1,0>(hb, wr + W_FFD, out, MQ, Dm, MLPm, x2, mods + 2*Bb*3*Dm + 2*Dm, 3*Dm, Nn);
}

// round 6
// speedup vs baseline: 4.2390x; 1.0814x over previous
#include <cuda_runtime.h>
#include <math.h>
#include <stdint.h>

// Problem dims
#define Dm    1024
#define Cm    2048
#define MLPm  4096
#define Hh    16
#define HDh   64
#define Bb    8
#define Nn    512
#define Ss    2048
#define INNER (Hh*HDh)   // 1024
#define EPSf  1e-6f

// ---------------- scratch (static device allocations) ---------------------------
__device__ __align__(16) float d_mods  [3 * Bb * 3 * Dm];
__device__ __align__(16) float d_normed[Bb * Nn * Dm];
__device__ __align__(16) float d_qkv   [Bb * Nn * 3 * INNER];      // SA fused QKV / CA q
__device__ __align__(16) float d_kv    [(size_t)Bb * Ss * 2 * INNER]; // CA fused KV
__device__ __align__(16) float d_attno [Bb * Nn * INNER];
__device__ __align__(16) float d_x1    [Bb * Nn * Dm];
__device__ __align__(16) float d_x2    [Bb * Nn * Dm];
__device__ __align__(16) float d_gu    [(size_t)Bb * Nn * 2 * MLPm]; // FFN fused gate|up
__device__ __align__(16) float d_hbuf  [Bb * Nn * MLPm];
__device__ __align__(16) float d_ctx   [(size_t)Bb * Ss * Cm];
__device__ __align__(16) float d_wrnd  [22 * 1024 * 1024];

// weight offsets inside d_wrnd (floats). NOTE adjacency is load-bearing:
// [SAQ|SAK|SAV] = fused 3072x1024, [CAK|CAV] = fused 2048x2048, [FFG|FFU] = fused 8192x1024.
#define W_SAQ  (0)
#define W_SAO  (3*1024*1024)
#define W_CAQ  (4*1024*1024)
#define W_CAK  (5*1024*1024)
#define W_CAO  (9*1024*1024)
#define W_FFG  (10*1024*1024)
#define W_FFD  (18*1024*1024)

// ---------------- tf32 helpers ---------------------------------------------------
__device__ __forceinline__ uint32_t f2tf32(float f) {
    uint32_t o;
    asm("cvt.rna.tf32.f32 %0, %1;" : "=r"(o) : "f"(f));
    return o;
}
__device__ __forceinline__ float rndtf32(float f) { return __uint_as_float(f2tf32(f)); }

__device__ __forceinline__ void mma_tf32(float* c, const uint32_t* a, const uint32_t* b) {
    asm volatile(
        "mma.sync.aligned.m16n8k8.row.col.f32.tf32.tf32.f32 "
        "{%0,%1,%2,%3}, {%4,%5,%6,%7}, {%8,%9}, {%0,%1,%2,%3};\n"
        : "+f"(c[0]), "+f"(c[1]), "+f"(c[2]), "+f"(c[3])
        : "r"(a[0]), "r"(a[1]), "r"(a[2]), "r"(a[3]), "r"(b[0]), "r"(b[1]));
}

__device__ __forceinline__ void cpasync16(uint32_t saddr, const void* gptr) {
    asm volatile("cp.async.cg.shared.global [%0], [%1], 16;\n" :: "r"(saddr), "l"(gptr));
}
__device__ __forceinline__ void cp_commit() { asm volatile("cp.async.commit_group;\n"); }
template<int n> __device__ __forceinline__ void cp_wait() {
    asm volatile("cp.async.wait_group %0;\n" :: "n"(n));
}

// ---------------- cp.async 3-stage pipelined tf32 NT GEMM (2 CTAs/SM) -----------
template<int BM,int BN,int WM,int WN,int EPI,int RND>
__global__ void __launch_bounds__(256, 2)
mma_nt_cp(const float* __restrict__ A, const float* __restrict__ Bg, float* __restrict__ C,
          int K, int lda, int ldb, int ldc,
          const float* __restrict__ resid, const float* __restrict__ gate,
          int gate_ld, int rows_per_b)
{
    constexpr int BK   = 32;
    constexpr int LDSW = BK + 4;
    constexpr int ST   = 3;
    constexpr int MT   = WM / 16;
    constexpr int NTJ  = WN / 8;
    constexpr int WMX  = BM / WM;
    constexpr int AIT  = (BM * 8) / 256;
    constexpr int BIT  = (BN * 8) / 256;

    extern __shared__ float smf[];
    float* As = smf;
    float* Bs = smf + ST * BM * LDSW;

    const int tid  = threadIdx.x;
    const int wid  = tid >> 5;
    const int lane = tid & 31;
    const int g    = lane >> 2;
    const int c4   = lane & 3;
    const int wm   = wid % WMX;
    const int wn   = wid / WMX;
    const int row0 = blockIdx.y * BM;
    const int col0 = blockIdx.x * BN;

    const float* Ab  = A + (size_t)row0 * lda;
    const float* Bb_ = Bg + (size_t)col0 * ldb;
    const int ldRow = tid >> 3;
    const int ldCol = (tid & 7) * 4;

    const uint32_t sA = (uint32_t)__cvta_generic_to_shared(As);
    const uint32_t sB = (uint32_t)__cvta_generic_to_shared(Bs);

    const int nTiles = K / BK;

    #pragma unroll
    for (int s = 0; s < ST - 1; s++) {
        if (s < nTiles) {
            const int kt = s * BK;
            #pragma unroll
            for (int it = 0; it < AIT; it++)
                cpasync16(sA + (uint32_t)(((s * BM) + (it * 32 + ldRow)) * LDSW + ldCol) * 4,
                          Ab + (size_t)(it * 32 + ldRow) * lda + kt + ldCol);
            #pragma unroll
            for (int it = 0; it < BIT; it++)
                cpasync16(sB + (uint32_t)(((s * BN) + (it * 32 + ldRow)) * LDSW + ldCol) * 4,
                          Bb_ + (size_t)(it * 32 + ldRow) * ldb + kt + ldCol);
        }
        cp_commit();
    }
    cp_wait<ST - 2>();
    __syncthreads();

    float acc[MT][NTJ][4];
    #pragma unroll
    for (int i = 0; i < MT; i++)
        #pragma unroll
        for (int j = 0; j < NTJ; j++)
            #pragma unroll
            for (int r = 0; r < 4; r++) acc[i][j][r] = 0.f;

    for (int t = 0; t < nTiles; t++) {
        const uint32_t* Asb = (const uint32_t*)(As + (t % ST) * BM * LDSW);
        const uint32_t* Bsb = (const uint32_t*)(Bs + (t % ST) * BN * LDSW);

        #pragma unroll
        for (int ks = 0; ks < BK / 8; ks++) {
            const int kk = ks * 8;
            uint32_t af[MT][4], bf[NTJ][2];
            #pragma unroll
            for (int i = 0; i < MT; i++) {
                int m = wm * WM + 16 * i + g;
                af[i][0] = Asb[(m    ) * LDSW + kk + c4];
                af[i][1] = Asb[(m + 8) * LDSW + kk + c4];
                af[i][2] = Asb[(m    ) * LDSW + kk + c4 + 4];
                af[i][3] = Asb[(m + 8) * LDSW + kk + c4 + 4];
            }
            #pragma unroll
            for (int j = 0; j < NTJ; j++) {
                int n = wn * WN + 8 * j + g;
                bf[j][0] = Bsb[n * LDSW + kk + c4];
                bf[j][1] = Bsb[n * LDSW + kk + c4 + 4];
            }
            #pragma unroll
            for (int i = 0; i < MT; i++)
                #pragma unroll
                for (int j = 0; j < NTJ; j++)
                    mma_tf32(acc[i][j], af[i], bf[j]);
        }

        const int tn = t + ST - 1;
        if (tn < nTiles) {
            const int st = tn % ST;
            const int kt = tn * BK;
            #pragma unroll
            for (int it = 0; it < AIT; it++)
                cpasync16(sA + (uint32_t)(((st * BM) + (it * 32 + ldRow)) * LDSW + ldCol) * 4,
                          Ab + (size_t)(it * 32 + ldRow) * lda + kt + ldCol);
            #pragma unroll
            for (int it = 0; it < BIT; it++)
                cpasync16(sB + (uint32_t)(((st * BN) + (it * 32 + ldRow)) * LDSW + ldCol) * 4,
                          Bb_ + (size_t)(it * 32 + ldRow) * ldb + kt + ldCol);
        }
        cp_commit();
        cp_wait<ST - 2>();
        __syncthreads();
    }

    #pragma unroll
    for (int i = 0; i < MT; i++) {
        #pragma unroll
        for (int j = 0; j < NTJ; j++) {
            int col = col0 + wn * WN + 8 * j + 2 * c4;
            #pragma unroll
            for (int half = 0; half < 2; half++) {
                int row = row0 + wm * WM + 16 * i + g + 8 * half;
                float v0 = acc[i][j][2 * half + 0];
                float v1 = acc[i][j][2 * half + 1];
                if (EPI == 1) {
                    const float* rr = resid + (size_t)row * ldc + col;
                    const float* gg = gate + (size_t)(row / rows_per_b) * gate_ld + col;
                    v0 = rr[0] + gg[0] * v0;
                    v1 = rr[1] + gg[1] * v1;
                }
                if (RND == 1) { v0 = rndtf32(v0); v1 = rndtf32(v1); }
                *(float2*)(C + (size_t)row * ldc + col) = make_float2(v0, v1);
            }
        }
    }
}

// ---------------- fused flash attention (tf32 mma, online softmax) ---------------
// Q/K/V row strides parameterized so it can consume packed QKV / KV buffers.
__global__ void __launch_bounds__(256)
flash_kernel(const float* __restrict__ Qg, const float* __restrict__ Kg,
             const float* __restrict__ Vg, float* __restrict__ Og,
             int Skv, int ldq, int ldkv)
{
    const int h = blockIdx.y, b = blockIdx.z;
    const int n0 = blockIdx.x * 128;
    const float* Qb = Qg + (size_t)b * Nn * ldq + (size_t)n0 * ldq + h * HDh;
    const float* Kb = Kg + (size_t)b * Skv * ldkv + h * HDh;
    const float* Vb = Vg + (size_t)b * Skv * ldkv + h * HDh;
    float* Ob = Og + (size_t)b * Nn * INNER + (size_t)n0 * INNER + h * HDh;

    extern __shared__ float sm[];
    float* Qs = sm;                    // [128][68]
    float* Ks = Qs + 128 * 68;         // [2][64][68]
    float* Vs = Ks + 2 * 64 * 68;      // [2][64][68]
    float* Ps = Vs + 2 * 64 * 68;      // [128][68]

    const int tid = threadIdx.x, wid = tid >> 5, lane = tid & 31;
    const int g = lane >> 2, c4 = lane & 3;

    const uint32_t sK = (uint32_t)__cvta_generic_to_shared(Ks);
    const uint32_t sV = (uint32_t)__cvta_generic_to_shared(Vs);

    #pragma unroll
    for (int it = 0; it < 8; it++) {
        int idx = it * 256 + tid;
        int r = idx >> 4, c = (idx & 15) * 4;
        float4 qv = *(const float4*)(Qb + (size_t)r * ldq + c);
        Qs[r*68 + c + 0] = qv.x * 0.125f;
        Qs[r*68 + c + 1] = qv.y * 0.125f;
        Qs[r*68 + c + 2] = qv.z * 0.125f;
        Qs[r*68 + c + 3] = qv.w * 0.125f;
    }

    auto loadKV = [&](int t, int buf) {
        const float* Ksrc = Kb + (size_t)(t * 64) * ldkv;
        const float* Vsrc = Vb + (size_t)(t * 64) * ldkv;
        #pragma unroll
        for (int it = 0; it < 4; it++) {
            int idx = it * 256 + tid;
            int r = idx >> 4, c = (idx & 15) * 4;
            cpasync16(sK + (uint32_t)((buf*64 + r)*68 + c)*4, Ksrc + (size_t)r * ldkv + c);
            cpasync16(sV + (uint32_t)((buf*64 + r)*68 + c)*4, Vsrc + (size_t)r * ldkv + c);
        }
    };
    loadKV(0, 0);
    cp_commit();
    cp_wait<0>();
    __syncthreads();

    uint32_t qf[8][4];
    {
        const uint32_t* Qw = (const uint32_t*)(Qs + wid * 16 * 68);
        #pragma unroll
        for (int ks = 0; ks < 8; ks++) {
            qf[ks][0] = Qw[(g    )*68 + 8*ks + c4];
            qf[ks][1] = Qw[(g + 8)*68 + 8*ks + c4];
            qf[ks][2] = Qw[(g    )*68 + 8*ks + c4 + 4];
            qf[ks][3] = Qw[(g + 8)*68 + 8*ks + c4 + 4];
        }
    }

    float o[8][4];
    #pragma unroll
    for (int j = 0; j < 8; j++)
        #pragma unroll
        for (int r = 0; r < 4; r++) o[j][r] = 0.f;
    float m0 = -1e30f, m1 = -1e30f, l0 = 0.f, l1 = 0.f;

    const int nT = Skv / 64;
    int buf = 0;

    float* Pw = Ps + wid * 16 * 68;
    const uint32_t* Pwu = (const uint32_t*)Pw;

    for (int t = 0; t < nT; t++) {
        if (t + 1 < nT) loadKV(t + 1, buf ^ 1);
        cp_commit();

        float s[8][4];
        #pragma unroll
        for (int j = 0; j < 8; j++)
            #pragma unroll
            for (int r = 0; r < 4; r++) s[j][r] = 0.f;

        const uint32_t* Kw = (const uint32_t*)(Ks + buf * 64 * 68);
        #pragma unroll
        for (int ks = 0; ks < 8; ks++) {
            #pragma unroll
            for (int j = 0; j < 8; j++) {
                uint32_t bfr[2];
                bfr[0] = Kw[(8*j + g)*68 + 8*ks + c4];
                bfr[1] = Kw[(8*j + g)*68 + 8*ks + c4 + 4];
                mma_tf32(s[j], qf[ks], bfr);
            }
        }

        float rm0 = -1e30f, rm1 = -1e30f;
        #pragma unroll
        for (int j = 0; j < 8; j++) {
            rm0 = fmaxf(rm0, fmaxf(s[j][0], s[j][1]));
            rm1 = fmaxf(rm1, fmaxf(s[j][2], s[j][3]));
        }
        rm0 = fmaxf(rm0, __shfl_xor_sync(0xffffffff, rm0, 1));
        rm0 = fmaxf(rm0, __shfl_xor_sync(0xffffffff, rm0, 2));
        rm1 = fmaxf(rm1, __shfl_xor_sync(0xffffffff, rm1, 1));
        rm1 = fmaxf(rm1, __shfl_xor_sync(0xffffffff, rm1, 2));

        float mn0 = fmaxf(m0, rm0), mn1 = fmaxf(m1, rm1);
        float f0 = __expf(m0 - mn0), f1 = __expf(m1 - mn1);
        m0 = mn0; m1 = mn1;

        float sum0 = 0.f, sum1 = 0.f;
        #pragma unroll
        for (int j = 0; j < 8; j++) {
            float p0 = __expf(s[j][0] - mn0);
            float p1 = __expf(s[j][1] - mn0);
            float p2 = __expf(s[j][2] - mn1);
            float p3 = __expf(s[j][3] - mn1);
            sum0 += p0 + p1;
            sum1 += p2 + p3;
            *(float2*)(Pw + (g    )*68 + 8*j + 2*c4) = make_float2(rndtf32(p0), rndtf32(p1));
            *(float2*)(Pw + (g + 8)*68 + 8*j + 2*c4) = make_float2(rndtf32(p2), rndtf32(p3));
        }
        sum0 += __shfl_xor_sync(0xffffffff, sum0, 1);
        sum0 += __shfl_xor_sync(0xffffffff, sum0, 2);
        sum1 += __shfl_xor_sync(0xffffffff, sum1, 1);
        sum1 += __shfl_xor_sync(0xffffffff, sum1, 2);
        l0 = l0 * f0 + sum0;
        l1 = l1 * f1 + sum1;

        #pragma unroll
        for (int j = 0; j < 8; j++) {
            o[j][0] *= f0; o[j][1] *= f0;
            o[j][2] *= f1; o[j][3] *= f1;
        }

        __syncwarp();

        const uint32_t* Vw = (const uint32_t*)(Vs + buf * 64 * 68);
        #pragma unroll
        for (int jk = 0; jk < 8; jk++) {
            uint32_t af[4];
            af[0] = Pwu[(g    )*68 + 8*jk + c4];
            af[1] = Pwu[(g + 8)*68 + 8*jk + c4];
            af[2] = Pwu[(g    )*68 + 8*jk + c4 + 4];
            af[3] = Pwu[(g + 8)*68 + 8*jk + c4 + 4];
            #pragma unroll
            for (int j = 0; j < 8; j++) {
                uint32_t bfr[2];
                bfr[0] = Vw[(8*jk + c4    )*68 + 8*j + g];
                bfr[1] = Vw[(8*jk + c4 + 4)*68 + 8*j + g];
                mma_tf32(o[j], af, bfr);
            }
        }

        cp_wait<0>();
        __syncthreads();
        buf ^= 1;
    }

    float inv0 = 1.0f / l0, inv1 = 1.0f / l1;
    #pragma unroll
    for (int j = 0; j < 8; j++) {
        int col = 8*j + 2*c4;
        *(float2*)(Ob + (size_t)(wid*16 + g    ) * INNER + col) =
            make_float2(rndtf32(o[j][0] * inv0), rndtf32(o[j][1] * inv0));
        *(float2*)(Ob + (size_t)(wid*16 + g + 8) * INNER + col) =
            make_float2(rndtf32(o[j][2] * inv1), rndtf32(o[j][3] * inv1));
    }
}

// ---------------- round-to-tf32 elementwise -------------------------------------
__global__ void round_tf32_kernel(const float4* __restrict__ in, float4* __restrict__ out, int n4)
{
    int i = blockIdx.x * blockDim.x + threadIdx.x;
    if (i < n4) {
        float4 t = in[i];
        out[i] = make_float4(rndtf32(t.x), rndtf32(t.y), rndtf32(t.z), rndtf32(t.w));
    }
}

// ---------------- modulation ------------------------------------------------------
__global__ void mod_kernel(const float* __restrict__ cond,
                           const float* __restrict__ mw0, const float* __restrict__ mb0,
                           const float* __restrict__ mw1, const float* __restrict__ mb1,
                           const float* __restrict__ mw2, const float* __restrict__ mb2,
                           float* __restrict__ mods)
{
    __shared__ float cs[Bb * Dm];
    for (int i = threadIdx.x; i < Bb * Dm; i += blockDim.x) cs[i] = cond[i];
    __syncthreads();

    int warp = threadIdx.x >> 5, lane = threadIdx.x & 31;
    int j = blockIdx.x * 8 + warp;
    int norm = j / (3*Dm), jj = j - norm * (3*Dm);
    const float* mw = (norm == 0) ? mw0 : (norm == 1) ? mw1 : mw2;
    const float* mb = (norm == 0) ? mb0 : (norm == 1) ? mb1 : mb2;

    float acc[Bb];
    #pragma unroll
    for (int b = 0; b < Bb; b++) acc[b] = 0.f;
    const float* wrow = mw + (size_t)jj * Dm;
    for (int d = lane; d < Dm; d += 32) {
        float w = wrow[d];
        #pragma unroll
        for (int b = 0; b < Bb; b++) acc[b] = fmaf(w, cs[b*Dm + d], acc[b]);
    }
    #pragma unroll
    for (int b = 0; b < Bb; b++)
        #pragma unroll
        for (int off = 16; off > 0; off >>= 1)
            acc[b] += __shfl_xor_sync(0xffffffff, acc[b], off);
    if (lane < Bb)
        mods[(size_t)norm * Bb * 3*Dm + lane * 3*Dm + jj] = acc[lane] + mb[jj];
}

// ---------------- adaRMS norm (tf32-rounded output) ------------------------------
__global__ void rmsnorm_kernel(const float* __restrict__ x, const float* __restrict__ w,
                               const float* __restrict__ mod_base,
                               float* __restrict__ out)
{
    int row = blockIdx.x;
    int b   = row / Nn;
    const float* xr = x + (size_t)row * Dm;
    const float* ms = mod_base + b * 3*Dm;

    float ss = 0.f;
    for (int i = threadIdx.x; i < Dm; i += blockDim.x) { float t = xr[i]; ss = fmaf(t,t,ss); }
    #pragma unroll
    for (int off = 16; off > 0; off >>= 1) ss += __shfl_xor_sync(0xffffffff, ss, off);
    __shared__ float red[8];
    if ((threadIdx.x & 31) == 0) red[threadIdx.x >> 5] = ss;
    __syncthreads();
    if (threadIdx.x < 8) {
        float v = red[threadIdx.x];
        #pragma unroll
        for (int off = 4; off > 0; off >>= 1) v += __shfl_xor_sync(0xff, v, off);
        if (threadIdx.x == 0) red[0] = v;
    }
    __syncthreads();
    float rn = rsqrtf(red[0] * (1.0f/Dm) + EPSf);

    float* orow = out + (size_t)row * Dm;
    for (int i = threadIdx.x; i < Dm; i += blockDim.x) {
        float scale = ms[i], shift = ms[Dm + i];
        orow[i] = rndtf32(xr[i] * rn * w[i] * (1.0f + scale) + shift);
    }
}

// ---------------- silu(gate)*up from packed [row][2*MLP] buffer ------------------
__global__ void silu_mul_kernel(const float* __restrict__ gu, float* __restrict__ h, int n)
{
    int i = blockIdx.x * blockDim.x + threadIdx.x;   // over MQ*MLP
    if (i < n) {
        int row = i / MLPm, col = i - row * MLPm;
        float x = gu[(size_t)row * 2 * MLPm + col];
        float u = gu[(size_t)row * 2 * MLPm + MLPm + col];
        h[i] = rndtf32((x / (1.0f + __expf(-x))) * u);
    }
}

// ---------------- host orchestration -------------------------------------------
static float* sym(const void* s) { void* p = nullptr; cudaGetSymbolAddress(&p, s); return (float*)p; }

template<int EPI,int RND>
static void gemm_nt(const float* A, const float* W, float* C, int M, int N, int K,
                    const float* resid, const float* gate, int gate_ld, int rpb)
{
    constexpr int BM = 128, BN = 128;
    size_t sm = (size_t)3 * (BM + BN) * 36 * sizeof(float);
    cudaFuncSetAttribute(mma_nt_cp<BM,BN,64,32,EPI,RND>,
                         cudaFuncAttributeMaxDynamicSharedMemorySize, (int)sm);
    mma_nt_cp<BM,BN,64,32,EPI,RND><<<dim3(N/BN, M/BM, 1), 256, sm>>>(
        A, W, C, K, K, K, N, resid, gate, gate_ld, rpb);
}

static void round_to(float* dst, const float* src, int n)
{
    round_tf32_kernel<<<(n/4 + 255)/256, 256>>>((const float4*)src, (float4*)dst, n/4);
}

static void launch_flash(const float* q, const float* k, const float* v, float* o,
                         int Skv, int ldq, int ldkv)
{
    size_t sm = (size_t)(128*68 + 4*64*68 + 128*68) * sizeof(float);
    cudaFuncSetAttribute(flash_kernel, cudaFuncAttributeMaxDynamicSharedMemorySize, (int)sm);
    flash_kernel<<<dim3(Nn/128, Hh, Bb), 256, sm>>>(q, k, v, o, Skv, ldq, ldkv);
}

extern "C" void kernel_launch(void* const* d_in, const int* in_sizes, int n_in,
                              void* d_out, int out_size)
{
    const float* x       = (const float*)d_in[0];
    const float* context = (const float*)d_in[1];
    const float* cond    = (const float*)d_in[2];
    const float* n1_w  = (const float*)d_in[3];
    const float* n1_mw = (const float*)d_in[4];
    const float* n1_mb = (const float*)d_in[5];
    const float* n2_w  = (const float*)d_in[6];
    const float* n2_mw = (const float*)d_in[7];
    const float* n2_mb = (const float*)d_in[8];
    const float* n3_w  = (const float*)d_in[9];
    const float* n3_mw = (const float*)d_in[10];
    const float* n3_mb = (const float*)d_in[11];
    const float* sa_q  = (const float*)d_in[12];
    const float* sa_k  = (const float*)d_in[13];
    const float* sa_v  = (const float*)d_in[14];
    const float* sa_o  = (const float*)d_in[15];
    const float* ca_q  = (const float*)d_in[16];
    const float* ca_k  = (const float*)d_in[17];
    const float* ca_v  = (const float*)d_in[18];
    const float* ca_o  = (const float*)d_in[19];
    const float* ff_gate = (const float*)d_in[20];
    const float* ff_up   = (const float*)d_in[21];
    const float* ff_down = (const float*)d_in[22];
    float* out = (float*)d_out;

    float* mods   = sym(d_mods);
    float* normed = sym(d_normed);
    float* qkv    = sym(d_qkv);
    float* kv     = sym(d_kv);
    float* ao     = sym(d_attno);
    float* x1     = sym(d_x1);
    float* x2     = sym(d_x2);
    float* gu     = sym(d_gu);
    float* hb     = sym(d_hbuf);
    float* ctx    = sym(d_ctx);
    float* wr     = sym(d_wrnd);

    const int MQ = Bb * Nn;

    // round weights + context to tf32 (rna) once per launch
    round_to(wr + W_SAQ,             sa_q, INNER*Dm);
    round_to(wr + W_SAQ + 1024*1024, sa_k, INNER*Dm);
    round_to(wr + W_SAQ + 2048*1024, sa_v, INNER*Dm);
    round_to(wr + W_SAO, sa_o, Dm*INNER);
    round_to(wr + W_CAQ, ca_q, INNER*Dm);
    round_to(wr + W_CAK,             ca_k, INNER*Cm);
    round_to(wr + W_CAK + 2048*1024, ca_v, INNER*Cm);
    round_to(wr + W_CAO, ca_o, Dm*INNER);
    round_to(wr + W_FFG,             ff_gate, MLPm*Dm);
    round_to(wr + W_FFG + 4096*1024, ff_up,   MLPm*Dm);
    round_to(wr + W_FFD, ff_down, Dm*MLPm);
    round_to(ctx, context, Bb*Ss*Cm);

    mod_kernel<<<(3*3*Dm)/8, 256>>>(cond, n1_mw, n1_mb, n2_mw, n2_mb, n3_mw, n3_mb, mods);

    // ===================== Self attention =====================
    rmsnorm_kernel<<<MQ, 256>>>(x, n1_w, mods + 0*Bb*3*Dm, normed);
    // fused QKV: [MQ, 3072]
    gemm_nt<0,1>(normed, wr + W_SAQ, qkv, MQ, 3*INNER, Dm, nullptr, nullptr, 0, 1);
    launch_flash(qkv, qkv + INNER, qkv + 2*INNER, ao, Nn, 3*INNER, 3*INNER);
    gemm_nt<1,0>(ao, wr + W_SAO, x1, MQ, Dm, INNER, x, mods + 0*Bb*3*Dm + 2*Dm, 3*Dm, Nn);

    // ===================== Cross attention =====================
    rmsnorm_kernel<<<MQ, 256>>>(x1, n2_w, mods + 1*Bb*3*Dm, normed);
    gemm_nt<0,1>(normed, wr + W_CAQ, qkv, MQ, INNER, Dm, nullptr, nullptr, 0, 1);
    // fused KV from context: [B*S, 2048]
    gemm_nt<0,1>(ctx, wr + W_CAK, kv, Bb*Ss, 2*INNER, Cm, nullptr, nullptr, 0, 1);
    launch_flash(qkv, kv, kv + INNER, ao, Ss, INNER, 2*INNER);
    gemm_nt<1,0>(ao, wr + W_CAO, x2, MQ, Dm, INNER, x1, mods + 1*Bb*3*Dm + 2*Dm, 3*Dm, Nn);

    // ===================== FFN =====================
    rmsnorm_kernel<<<MQ, 256>>>(x2, n3_w, mods + 2*Bb*3*Dm, normed);
    // fused gate|up: [MQ, 8192]
    gemm_nt<0,0>(normed, wr + W_FFG, gu, MQ, 2*MLPm, Dm, nullptr, nullptr, 0, 1);
    silu_mul_kernel<<<(MQ*MLPm + 255)/256, 256>>>(gu, hb, MQ*MLPm);
    gemm_nt<1,0>(hb, wr + W_FFD, out, MQ, Dm, MLPm, x2, mods + 2*Bb*3*Dm + 2*Dm, 3*Dm, Nn);
}

// round 8
// speedup vs baseline: 7.7315x; 1.8239x over previous
#include <cuda_runtime.h>
#include <cuda_fp16.h>
#include <math.h>
#include <stdint.h>

// Problem dims
#define Dm    1024
#define Cm    2048
#define MLPm  4096
#define Hh    16
#define HDh   64
#define Bb    8
#define Nn    512
#define Ss    2048
#define INNER (Hh*HDh)   // 1024
#define EPSf  1e-6f

// ---------------- scratch (static device allocations) ---------------------------
__device__ __align__(16) float  d_mods  [3 * Bb * 3 * Dm];
__device__ __align__(16) __half d_normed[Bb * Nn * Dm];
__device__ __align__(16) __half d_qkv   [Bb * Nn * 3 * INNER];
__device__ __align__(16) __half d_kv    [(size_t)Bb * Ss * 2 * INNER];
__device__ __align__(16) __half d_attno [Bb * Nn * INNER];
__device__ __align__(16) float  d_x1    [Bb * Nn * Dm];
__device__ __align__(16) float  d_x2    [Bb * Nn * Dm];
__device__ __align__(16) __half d_gu    [(size_t)Bb * Nn * 2 * MLPm];
__device__ __align__(16) __half d_hbuf  [Bb * Nn * MLPm];
__device__ __align__(16) __half d_ctx   [(size_t)Bb * Ss * Cm];
__device__ __align__(16) __half d_wrnd  [22 * 1024 * 1024];

// weight offsets (elements); adjacency is load-bearing for fused GEMMs:
// [SAQ|SAK|SAV] 3072x1024, [CAK|CAV] 2048x2048, [FFG|FFU] 8192x1024
#define W_SAQ  (0)
#define W_SAO  (3*1024*1024)
#define W_CAQ  (4*1024*1024)
#define W_CAK  (5*1024*1024)
#define W_CAO  (9*1024*1024)
#define W_FFG  (10*1024*1024)
#define W_FFD  (18*1024*1024)

// ---------------- helpers ---------------------------------------------------------
__device__ __forceinline__ void mma_f16(float* c, const uint32_t* a, const uint32_t* b) {
    asm volatile(
        "mma.sync.aligned.m16n8k16.row.col.f32.f16.f16.f32 "
        "{%0,%1,%2,%3}, {%4,%5,%6,%7}, {%8,%9}, {%0,%1,%2,%3};\n"
        : "+f"(c[0]), "+f"(c[1]), "+f"(c[2]), "+f"(c[3])
        : "r"(a[0]), "r"(a[1]), "r"(a[2]), "r"(a[3]), "r"(b[0]), "r"(b[1]));
}

__device__ __forceinline__ void cpasync16(uint32_t saddr, const void* gptr) {
    asm volatile("cp.async.cg.shared.global [%0], [%1], 16;\n" :: "r"(saddr), "l"(gptr));
}
__device__ __forceinline__ void cp_commit() { asm volatile("cp.async.commit_group;\n"); }
template<int n> __device__ __forceinline__ void cp_wait() {
    asm volatile("cp.async.wait_group %0;\n" :: "n"(n));
}
__device__ __forceinline__ uint32_t cvta_smem(const void* p) {
    uint32_t a;
    asm("{ .reg .u64 t; cvta.to.shared.u64 t, %1; cvt.u32.u64 %0, t; }" : "=r"(a) : "l"(p));
    return a;
}
__device__ __forceinline__ void ldsm_x2_trans(uint32_t& r0, uint32_t& r1, uint32_t addr) {
    asm volatile("ldmatrix.sync.aligned.m8n8.x2.trans.shared.b16 {%0,%1}, [%2];"
                 : "=r"(r0), "=r"(r1) : "r"(addr));
}

// ---------------- fp16 NT GEMM: C(M,N) = A(M,K) @ B(N,K)^T ----------------------
// A,B half (K-major). 128x128x64 tiles, row pad to 72 halves (144B = 36 words ->
// conflict-free frag LDS and cp.async stores). 3-stage cp.async ring, 2 CTAs/SM.
// EPI==1: C(float) = resid + gate[(row/rows_per_b)*gate_ld+col]*acc
// OH==1:  C is __half (feeds another GEMM / flash)
template<int EPI,int OH>
__global__ void __launch_bounds__(256, 2)
gemm_f16(const __half* __restrict__ A, const __half* __restrict__ Bg, void* __restrict__ Cv,
         int K, int lda, int ldb, int ldc,
         const float* __restrict__ resid, const float* __restrict__ gate,
         int gate_ld, int rows_per_b)
{
    constexpr int BM = 128, BN = 128, BK = 64, LDH = 72, ST = 3;

    extern __shared__ __half hsm[];
    __half* As = hsm;                    // ST * BM * LDH
    __half* Bs = hsm + ST * BM * LDH;

    const int tid = threadIdx.x, wid = tid >> 5, lane = tid & 31;
    const int g = lane >> 2, c4 = lane & 3;
    const int wm = wid & 1, wn = wid >> 1;        // 2 warps on M, 4 on N
    const int row0 = blockIdx.y * BM, col0 = blockIdx.x * BN;

    const __half* Arow = A  + (size_t)row0 * lda;
    const __half* Brow = Bg + (size_t)col0 * ldb;

    const uint32_t sA = cvta_smem(As);
    const uint32_t sB = cvta_smem(Bs);
    const int ldRow = tid >> 3;          // 0..31
    const int ldCol = (tid & 7) * 8;     // halves (16B chunks)

    auto load_tile = [&](int t) {
        const int st = t % ST;
        const int kt = t * BK;
        #pragma unroll
        for (int i = 0; i < 4; i++) {
            int r = i * 32 + ldRow;
            cpasync16(sA + (uint32_t)((st * BM + r) * LDH + ldCol) * 2,
                      Arow + (size_t)r * lda + kt + ldCol);
        }
        #pragma unroll
        for (int i = 0; i < 4; i++) {
            int r = i * 32 + ldRow;
            cpasync16(sB + (uint32_t)((st * BN + r) * LDH + ldCol) * 2,
                      Brow + (size_t)r * ldb + kt + ldCol);
        }
    };

    const int nT = K / BK;
    load_tile(0); cp_commit();
    if (nT > 1) load_tile(1);
    cp_commit();
    cp_wait<1>();
    __syncthreads();

    float acc[4][4][4];
    #pragma unroll
    for (int i = 0; i < 4; i++)
        #pragma unroll
        for (int j = 0; j < 4; j++)
            #pragma unroll
            for (int r = 0; r < 4; r++) acc[i][j][r] = 0.f;

    for (int t = 0; t < nT; t++) {
        const uint32_t* Aw = (const uint32_t*)(As + (t % ST) * BM * LDH);
        const uint32_t* Bw = (const uint32_t*)(Bs + (t % ST) * BN * LDH);

        #pragma unroll
        for (int ks = 0; ks < 4; ks++) {
            const int kw = ks * 8 + c4;          // word offset within row
            uint32_t af[4][4], bf[4][2];
            #pragma unroll
            for (int i = 0; i < 4; i++) {
                int m = wm * 64 + 16 * i + g;
                af[i][0] = Aw[m * 36 + kw];
                af[i][1] = Aw[(m + 8) * 36 + kw];
                af[i][2] = Aw[m * 36 + kw + 4];
                af[i][3] = Aw[(m + 8) * 36 + kw + 4];
            }
            #pragma unroll
            for (int j = 0; j < 4; j++) {
                int n = wn * 32 + 8 * j + g;
                bf[j][0] = Bw[n * 36 + kw];
                bf[j][1] = Bw[n * 36 + kw + 4];
            }
            #pragma unroll
            for (int i = 0; i < 4; i++)
                #pragma unroll
                for (int j = 0; j < 4; j++)
                    mma_f16(acc[i][j], af[i], bf[j]);
        }

        if (t + 2 < nT) load_tile(t + 2);
        cp_commit();
        cp_wait<1>();
        __syncthreads();
    }

    #pragma unroll
    for (int i = 0; i < 4; i++) {
        #pragma unroll
        for (int j = 0; j < 4; j++) {
            int col = col0 + wn * 32 + 8 * j + 2 * c4;
            #pragma unroll
            for (int h = 0; h < 2; h++) {
                int row = row0 + wm * 64 + 16 * i + g + 8 * h;
                float v0 = acc[i][j][2 * h + 0];
                float v1 = acc[i][j][2 * h + 1];
                if (EPI == 1) {
                    const float* rr = resid + (size_t)row * ldc + col;
                    const float* gg = gate + (size_t)(row / rows_per_b) * gate_ld + col;
                    v0 = rr[0] + gg[0] * v0;
                    v1 = rr[1] + gg[1] * v1;
                }
                if (OH == 1) {
                    *(__half2*)((__half*)Cv + (size_t)row * ldc + col) =
                        __floats2half2_rn(v0, v1);
                } else {
                    *(float2*)((float*)Cv + (size_t)row * ldc + col) = make_float2(v0, v1);
                }
            }
        }
    }
}

// ---------------- fused flash attention (fp16 mma, online softmax) ---------------
// CTA: 128 q rows x (head, batch). 8 warps x 16 rows. KV tiles 64, double-buffered.
__global__ void __launch_bounds__(256, 2)
flash_kernel(const __half* __restrict__ Qg, const __half* __restrict__ Kg,
             const __half* __restrict__ Vg, __half* __restrict__ Og,
             int Skv, int ldq, int ldkv)
{
    const int h = blockIdx.y, b = blockIdx.z;
    const int n0 = blockIdx.x * 128;
    const __half* Qb = Qg + (size_t)b * Nn * ldq + (size_t)n0 * ldq + h * HDh;
    const __half* Kb = Kg + (size_t)b * Skv * ldkv + h * HDh;
    const __half* Vb = Vg + (size_t)b * Skv * ldkv + h * HDh;
    __half* Ob = Og + (size_t)b * Nn * INNER + (size_t)n0 * INNER + h * HDh;

    extern __shared__ __half fsm[];
    __half* Qs = fsm;                      // [128][72]
    __half* Ks = Qs + 128 * 72;            // [2][64][72]
    __half* Vs = Ks + 2 * 64 * 72;         // [2][64][72]
    __half* Ps = Vs + 2 * 64 * 72;         // [8 warps][16][72]

    const int tid = threadIdx.x, wid = tid >> 5, lane = tid & 31;
    const int g = lane >> 2, c4 = lane & 3;

    const uint32_t sK = cvta_smem(Ks);
    const uint32_t sV = cvta_smem(Vs);

    // load + scale Q (0.125 exact pow2 in fp16)
    {
        const __half2 sc2 = __floats2half2_rn(0.125f, 0.125f);
        #pragma unroll
        for (int it = 0; it < 4; it++) {
            int idx = it * 256 + tid;
            int r = idx >> 3, c = (idx & 7) * 8;
            uint4 qv = *(const uint4*)(Qb + (size_t)r * ldq + c);
            __half2* hp = (__half2*)&qv;
            hp[0] = __hmul2(hp[0], sc2);
            hp[1] = __hmul2(hp[1], sc2);
            hp[2] = __hmul2(hp[2], sc2);
            hp[3] = __hmul2(hp[3], sc2);
            *(uint4*)(Qs + r * 72 + c) = qv;
        }
    }

    auto loadKV = [&](int t, int buf) {
        const __half* Ksrc = Kb + (size_t)(t * 64) * ldkv;
        const __half* Vsrc = Vb + (size_t)(t * 64) * ldkv;
        #pragma unroll
        for (int it = 0; it < 2; it++) {
            int idx = it * 256 + tid;
            int r = idx >> 3, c = (idx & 7) * 8;
            cpasync16(sK + (uint32_t)((buf * 64 + r) * 72 + c) * 2, Ksrc + (size_t)r * ldkv + c);
            cpasync16(sV + (uint32_t)((buf * 64 + r) * 72 + c) * 2, Vsrc + (size_t)r * ldkv + c);
        }
    };
    loadKV(0, 0);
    cp_commit();
    cp_wait<0>();
    __syncthreads();

    // per-warp Q fragments (4 k16-steps over HD=64)
    uint32_t qf[4][4];
    {
        const uint32_t* Qw = (const uint32_t*)(Qs + wid * 16 * 72);
        #pragma unroll
        for (int ks = 0; ks < 4; ks++) {
            qf[ks][0] = Qw[(g    ) * 36 + 8 * ks + c4];
            qf[ks][1] = Qw[(g + 8) * 36 + 8 * ks + c4];
            qf[ks][2] = Qw[(g    ) * 36 + 8 * ks + c4 + 4];
            qf[ks][3] = Qw[(g + 8) * 36 + 8 * ks + c4 + 4];
        }
    }

    float o[8][4];
    #pragma unroll
    for (int j = 0; j < 8; j++)
        #pragma unroll
        for (int r = 0; r < 4; r++) o[j][r] = 0.f;
    float m0 = -1e30f, m1 = -1e30f, l0 = 0.f, l1 = 0.f;

    const int nT = Skv / 64;
    int buf = 0;

    __half* Pw = Ps + wid * 16 * 72;
    const uint32_t* Pww = (const uint32_t*)Pw;

    for (int t = 0; t < nT; t++) {
        if (t + 1 < nT) loadKV(t + 1, buf ^ 1);
        cp_commit();

        // S = Q @ K^T (this warp: 16x64)
        float s[8][4];
        #pragma unroll
        for (int j = 0; j < 8; j++)
            #pragma unroll
            for (int r = 0; r < 4; r++) s[j][r] = 0.f;

        const uint32_t* Kw = (const uint32_t*)(Ks + buf * 64 * 72);
        #pragma unroll
        for (int ks = 0; ks < 4; ks++) {
            #pragma unroll
            for (int j = 0; j < 8; j++) {
                uint32_t bfr[2];
                bfr[0] = Kw[(8 * j + g) * 36 + 8 * ks + c4];
                bfr[1] = Kw[(8 * j + g) * 36 + 8 * ks + c4 + 4];
                mma_f16(s[j], qf[ks], bfr);
            }
        }

        // online softmax (rows g, g+8)
        float rm0 = -1e30f, rm1 = -1e30f;
        #pragma unroll
        for (int j = 0; j < 8; j++) {
            rm0 = fmaxf(rm0, fmaxf(s[j][0], s[j][1]));
            rm1 = fmaxf(rm1, fmaxf(s[j][2], s[j][3]));
        }
        rm0 = fmaxf(rm0, __shfl_xor_sync(0xffffffff, rm0, 1));
        rm0 = fmaxf(rm0, __shfl_xor_sync(0xffffffff, rm0, 2));
        rm1 = fmaxf(rm1, __shfl_xor_sync(0xffffffff, rm1, 1));
        rm1 = fmaxf(rm1, __shfl_xor_sync(0xffffffff, rm1, 2));

        float mn0 = fmaxf(m0, rm0), mn1 = fmaxf(m1, rm1);
        float f0 = __expf(m0 - mn0), f1 = __expf(m1 - mn1);
        m0 = mn0; m1 = mn1;

        float sum0 = 0.f, sum1 = 0.f;
        #pragma unroll
        for (int j = 0; j < 8; j++) {
            float p0 = __expf(s[j][0] - mn0);
            float p1 = __expf(s[j][1] - mn0);
            float p2 = __expf(s[j][2] - mn1);
            float p3 = __expf(s[j][3] - mn1);
            sum0 += p0 + p1;
            sum1 += p2 + p3;
            *(__half2*)(Pw + (g    ) * 72 + 8 * j + 2 * c4) = __floats2half2_rn(p0, p1);
            *(__half2*)(Pw + (g + 8) * 72 + 8 * j + 2 * c4) = __floats2half2_rn(p2, p3);
        }
        sum0 += __shfl_xor_sync(0xffffffff, sum0, 1);
        sum0 += __shfl_xor_sync(0xffffffff, sum0, 2);
        sum1 += __shfl_xor_sync(0xffffffff, sum1, 1);
        sum1 += __shfl_xor_sync(0xffffffff, sum1, 2);
        l0 = l0 * f0 + sum0;
        l1 = l1 * f1 + sum1;

        #pragma unroll
        for (int j = 0; j < 8; j++) {
            o[j][0] *= f0; o[j][1] *= f0;
            o[j][2] *= f1; o[j][3] *= f1;
        }

        __syncwarp();

        // O += P @ V  (B frags via ldmatrix.x2.trans)
        const uint32_t sVb = sV + (uint32_t)(buf * 64 * 72) * 2;
        #pragma unroll
        for (int jk = 0; jk < 4; jk++) {
            uint32_t af[4];
            af[0] = Pww[(g    ) * 36 + 8 * jk + c4];
            af[1] = Pww[(g + 8) * 36 + 8 * jk + c4];
            af[2] = Pww[(g    ) * 36 + 8 * jk + c4 + 4];
            af[3] = Pww[(g + 8) * 36 + 8 * jk + c4 + 4];
            const uint32_t rowa = sVb + (uint32_t)((16 * jk + (lane & 15)) * 72) * 2;
            #pragma unroll
            for (int j = 0; j < 8; j++) {
                uint32_t b0, b1;
                ldsm_x2_trans(b0, b1, rowa + (uint32_t)(8 * j) * 2);
                uint32_t bfr[2] = {b0, b1};
                mma_f16(o[j], af, bfr);
            }
        }

        cp_wait<0>();
        __syncthreads();
        buf ^= 1;
    }

    float inv0 = 1.0f / l0, inv1 = 1.0f / l1;
    #pragma unroll
    for (int j = 0; j < 8; j++) {
        int col = 8 * j + 2 * c4;
        *(__half2*)(Ob + (size_t)(wid * 16 + g    ) * INNER + col) =
            __floats2half2_rn(o[j][0] * inv0, o[j][1] * inv0);
        *(__half2*)(Ob + (size_t)(wid * 16 + g + 8) * INNER + col) =
            __floats2half2_rn(o[j][2] * inv1, o[j][3] * inv1);
    }
}

// ---------------- fp32 -> fp16 conversion ----------------------------------------
__global__ void f32_to_f16_kernel(const float4* __restrict__ in, uint2* __restrict__ out, int n4)
{
    int i = blockIdx.x * blockDim.x + threadIdx.x;
    if (i < n4) {
        float4 t = in[i];
        __half2 lo = __floats2half2_rn(t.x, t.y);
        __half2 hi = __floats2half2_rn(t.z, t.w);
        uint2 o;
        o.x = *(uint32_t*)&lo;
        o.y = *(uint32_t*)&hi;
        out[i] = o;
    }
}

// ---------------- modulation (fp32) ----------------------------------------------
__global__ void mod_kernel(const float* __restrict__ cond,
                           const float* __restrict__ mw0, const float* __restrict__ mb0,
                           const float* __restrict__ mw1, const float* __restrict__ mb1,
                           const float* __restrict__ mw2, const float* __restrict__ mb2,
                           float* __restrict__ mods)
{
    __shared__ float cs[Bb * Dm];
    for (int i = threadIdx.x; i < Bb * Dm; i += blockDim.x) cs[i] = cond[i];
    __syncthreads();

    int warp = threadIdx.x >> 5, lane = threadIdx.x & 31;
    int j = blockIdx.x * 8 + warp;
    int norm = j / (3*Dm), jj = j - norm * (3*Dm);
    const float* mw = (norm == 0) ? mw0 : (norm == 1) ? mw1 : mw2;
    const float* mb = (norm == 0) ? mb0 : (norm == 1) ? mb1 : mb2;

    float acc[Bb];
    #pragma unroll
    for (int b = 0; b < Bb; b++) acc[b] = 0.f;
    const float* wrow = mw + (size_t)jj * Dm;
    for (int d = lane; d < Dm; d += 32) {
        float w = wrow[d];
        #pragma unroll
        for (int b = 0; b < Bb; b++) acc[b] = fmaf(w, cs[b*Dm + d], acc[b]);
    }
    #pragma unroll
    for (int b = 0; b < Bb; b++)
        #pragma unroll
        for (int off = 16; off > 0; off >>= 1)
            acc[b] += __shfl_xor_sync(0xffffffff, acc[b], off);
    if (lane < Bb)
        mods[(size_t)norm * Bb * 3*Dm + lane * 3*Dm + jj] = acc[lane] + mb[jj];
}

// ---------------- adaRMS norm (fp16 output) --------------------------------------
__global__ void rmsnorm_kernel(const float* __restrict__ x, const float* __restrict__ w,
                               const float* __restrict__ mod_base,
                               __half* __restrict__ out)
{
    int row = blockIdx.x;
    int b   = row / Nn;
    const float* xr = x + (size_t)row * Dm;
    const float* ms = mod_base + b * 3*Dm;

    float ss = 0.f;
    for (int i = threadIdx.x; i < Dm; i += blockDim.x) { float t = xr[i]; ss = fmaf(t,t,ss); }
    #pragma unroll
    for (int off = 16; off > 0; off >>= 1) ss += __shfl_xor_sync(0xffffffff, ss, off);
    __shared__ float red[8];
    if ((threadIdx.x & 31) == 0) red[threadIdx.x >> 5] = ss;
    __syncthreads();
    if (threadIdx.x < 8) {
        float v = red[threadIdx.x];
        #pragma unroll
        for (int off = 4; off > 0; off >>= 1) v += __shfl_xor_sync(0xff, v, off);
        if (threadIdx.x == 0) red[0] = v;
    }
    __syncthreads();
    float rn = rsqrtf(red[0] * (1.0f/Dm) + EPSf);

    __half* orow = out + (size_t)row * Dm;
    for (int i = threadIdx.x; i < Dm/2; i += blockDim.x) {
        int i2 = 2 * i;
        float a = xr[i2]   * rn * w[i2]   * (1.0f + ms[i2])   + ms[Dm + i2];
        float c = xr[i2+1] * rn * w[i2+1] * (1.0f + ms[i2+1]) + ms[Dm + i2+1];
        *(__half2*)(orow + i2) = __floats2half2_rn(a, c);
    }
}

// ---------------- silu(gate)*up from packed [row][2*MLP] half buffer -------------
__global__ void silu_mul_kernel(const __half2* __restrict__ gu, __half2* __restrict__ h, int n2)
{
    int i = blockIdx.x * blockDim.x + threadIdx.x;
    if (i < n2) {
        int row = i / (MLPm/2), c2 = i - row * (MLPm/2);
        __half2 g2 = gu[(size_t)row * MLPm + c2];
        __half2 u2 = gu[(size_t)row * MLPm + MLPm/2 + c2];
        float2 gf = __half22float2(g2);
        float2 uf = __half22float2(u2);
        float h0 = (gf.x / (1.0f + __expf(-gf.x))) * uf.x;
        float h1 = (gf.y / (1.0f + __expf(-gf.y))) * uf.y;
        h[i] = __floats2half2_rn(h0, h1);
    }
}

// ---------------- host orchestration -------------------------------------------
static void* symv(const void* s) { void* p = nullptr; cudaGetSymbolAddress(&p, s); return p; }

template<int EPI,int OH>
static void gemm_h(const __half* A, const __half* W, void* C, int M, int N, int K,
                   const float* resid, const float* gate, int gate_ld, int rpb)
{
    size_t sm = (size_t)3 * (128 + 128) * 72 * sizeof(__half);   // 110592
    cudaFuncSetAttribute(gemm_f16<EPI,OH>,
                         cudaFuncAttributeMaxDynamicSharedMemorySize, (int)sm);
    gemm_f16<EPI,OH><<<dim3(N/128, M/128), 256, sm>>>(
        A, W, C, K, K, K, N, resid, gate, gate_ld, rpb);
}

static void cvt_to(__half* dst, const float* src, int n)
{
    f32_to_f16_kernel<<<(n/4 + 255)/256, 256>>>((const float4*)src, (uint2*)dst, n/4);
}

static void launch_flash(const __half* q, const __half* k, const __half* v, __half* o,
                         int Skv, int ldq, int ldkv)
{
    size_t sm = (size_t)(128*72 + 2*64*72 + 2*64*72 + 8*16*72) * sizeof(__half);  // 73728
    cudaFuncSetAttribute(flash_kernel, cudaFuncAttributeMaxDynamicSharedMemorySize, (int)sm);
    flash_kernel<<<dim3(Nn/128, Hh, Bb), 256, sm>>>(q, k, v, o, Skv, ldq, ldkv);
}

extern "C" void kernel_launch(void* const* d_in, const int* in_sizes, int n_in,
                              void* d_out, int out_size)
{
    const float* x       = (const float*)d_in[0];
    const float* context = (const float*)d_in[1];
    const float* cond    = (const float*)d_in[2];
    const float* n1_w  = (const float*)d_in[3];
    const float* n1_mw = (const float*)d_in[4];
    const float* n1_mb = (const float*)d_in[5];
    const float* n2_w  = (const float*)d_in[6];
    const float* n2_mw = (const float*)d_in[7];
    const float* n2_mb = (const float*)d_in[8];
    const float* n3_w  = (const float*)d_in[9];
    const float* n3_mw = (const float*)d_in[10];
    const float* n3_mb = (const float*)d_in[11];
    const float* sa_q  = (const float*)d_in[12];
    const float* sa_k  = (const float*)d_in[13];
    const float* sa_v  = (const float*)d_in[14];
    const float* sa_o  = (const float*)d_in[15];
    const float* ca_q  = (const float*)d_in[16];
    const float* ca_k  = (const float*)d_in[17];
    const float* ca_v  = (const float*)d_in[18];
    const float* ca_o  = (const float*)d_in[19];
    const float* ff_gate = (const float*)d_in[20];
    const float* ff_up   = (const float*)d_in[21];
    const float* ff_down = (const float*)d_in[22];
    float* out = (float*)d_out;

    float*  mods   = (float*)symv(d_mods);
    __half* normed = (__half*)symv(d_normed);
    __half* qkv    = (__half*)symv(d_qkv);
    __half* kv     = (__half*)symv(d_kv);
    __half* ao     = (__half*)symv(d_attno);
    float*  x1     = (float*)symv(d_x1);
    float*  x2     = (float*)symv(d_x2);
    __half* gu     = (__half*)symv(d_gu);
    __half* hb     = (__half*)symv(d_hbuf);
    __half* ctx    = (__half*)symv(d_ctx);
    __half* wr     = (__half*)symv(d_wrnd);

    const int MQ = Bb * Nn;

    // convert weights + context to fp16 once per launch
    cvt_to(wr + W_SAQ,             sa_q, INNER*Dm);
    cvt_to(wr + W_SAQ + 1024*1024, sa_k, INNER*Dm);
    cvt_to(wr + W_SAQ + 2048*1024, sa_v, INNER*Dm);
    cvt_to(wr + W_SAO, sa_o, Dm*INNER);
    cvt_to(wr + W_CAQ, ca_q, INNER*Dm);
    cvt_to(wr + W_CAK,             ca_k, INNER*Cm);
    cvt_to(wr + W_CAK + 2048*1024, ca_v, INNER*Cm);
    cvt_to(wr + W_CAO, ca_o, Dm*INNER);
    cvt_to(wr + W_FFG,             ff_gate, MLPm*Dm);
    cvt_to(wr + W_FFG + 4096*1024, ff_up,   MLPm*Dm);
    cvt_to(wr + W_FFD, ff_down, Dm*MLPm);
    cvt_to(ctx, context, Bb*Ss*Cm);

    mod_kernel<<<(3*3*Dm)/8, 256>>>(cond, n1_mw, n1_mb, n2_mw, n2_mb, n3_mw, n3_mb, mods);

    // ===================== Self attention =====================
    rmsnorm_kernel<<<MQ, 256>>>(x, n1_w, mods + 0*Bb*3*Dm, normed);
    gemm_h<0,1>(normed, wr + W_SAQ, qkv, MQ, 3*INNER, Dm, nullptr, nullptr, 0, 1);
    launch_flash(qkv, qkv + INNER, qkv + 2*INNER, ao, Nn, 3*INNER, 3*INNER);
    gemm_h<1,0>(ao, wr + W_SAO, x1, MQ, Dm, INNER, x, mods + 0*Bb*3*Dm + 2*Dm, 3*Dm, Nn);

    // ===================== Cross attention =====================
    rmsnorm_kernel<<<MQ, 256>>>(x1, n2_w, mods + 1*Bb*3*Dm, normed);
    gemm_h<0,1>(normed, wr + W_CAQ, qkv, MQ, INNER, Dm, nullptr, nullptr, 0, 1);
    gemm_h<0,1>(ctx, wr + W_CAK, kv, Bb*Ss, 2*INNER, Cm, nullptr, nullptr, 0, 1);
    launch_flash(qkv, kv, kv + INNER, ao, Ss, INNER, 2*INNER);
    gemm_h<1,0>(ao, wr + W_CAO, x2, MQ, Dm, INNER, x1, mods + 1*Bb*3*Dm + 2*Dm, 3*Dm, Nn);

    // ===================== FFN =====================
    rmsnorm_kernel<<<MQ, 256>>>(x2, n3_w, mods + 2*Bb*3*Dm, normed);
    gemm_h<0,1>(normed, wr + W_FFG, gu, MQ, 2*MLPm, Dm, nullptr, nullptr, 0, 1);
    silu_mul_kernel<<<(MQ*MLPm/2 + 255)/256, 256>>>((const __half2*)gu, (__half2*)hb, MQ*MLPm/2);
    gemm_h<1,0>(hb, wr + W_FFD, out, MQ, Dm, MLPm, x2, mods + 2*Bb*3*Dm + 2*Dm, 3*Dm, Nn);
}

// round 9
// speedup vs baseline: 8.3330x; 1.0778x over previous
#include <cuda_runtime.h>
#include <cuda_fp16.h>
#include <math.h>
#include <stdint.h>

// Problem dims
#define Dm    1024
#define Cm    2048
#define MLPm  4096
#define Hh    16
#define HDh   64
#define Bb    8
#define Nn    512
#define Ss    2048
#define INNER (Hh*HDh)   // 1024
#define EPSf  1e-6f

// ---------------- scratch (static device allocations) ---------------------------
__device__ __align__(16) float  d_mods  [3 * Bb * 3 * Dm];
__device__ __align__(16) __half d_normed[Bb * Nn * Dm];
__device__ __align__(16) __half d_qkv   [Bb * Nn * 3 * INNER];
__device__ __align__(16) __half d_kv    [(size_t)Bb * Ss * 2 * INNER];
__device__ __align__(16) __half d_attno [Bb * Nn * INNER];
__device__ __align__(16) float  d_x1    [Bb * Nn * Dm];
__device__ __align__(16) float  d_x2    [Bb * Nn * Dm];
__device__ __align__(16) __half d_gu    [(size_t)Bb * Nn * 2 * MLPm];
__device__ __align__(16) __half d_hbuf  [Bb * Nn * MLPm];
__device__ __align__(16) __half d_ctx   [(size_t)Bb * Ss * Cm];
__device__ __align__(16) __half d_wrnd  [22 * 1024 * 1024];

// weight offsets (elements); adjacency is load-bearing for fused GEMMs:
// [SAQ|SAK|SAV] 3072x1024, [CAK|CAV] 2048x2048, [FFG|FFU] 8192x1024
#define W_SAQ  (0)
#define W_SAO  (3*1024*1024)
#define W_CAQ  (4*1024*1024)
#define W_CAK  (5*1024*1024)
#define W_CAO  (9*1024*1024)
#define W_FFG  (10*1024*1024)
#define W_FFD  (18*1024*1024)

// ---------------- helpers ---------------------------------------------------------
__device__ __forceinline__ void mma_f16(float* c, const uint32_t* a, const uint32_t* b) {
    asm volatile(
        "mma.sync.aligned.m16n8k16.row.col.f32.f16.f16.f32 "
        "{%0,%1,%2,%3}, {%4,%5,%6,%7}, {%8,%9}, {%0,%1,%2,%3};\n"
        : "+f"(c[0]), "+f"(c[1]), "+f"(c[2]), "+f"(c[3])
        : "r"(a[0]), "r"(a[1]), "r"(a[2]), "r"(a[3]), "r"(b[0]), "r"(b[1]));
}

__device__ __forceinline__ void cpasync16(uint32_t saddr, const void* gptr) {
    asm volatile("cp.async.cg.shared.global [%0], [%1], 16;\n" :: "r"(saddr), "l"(gptr));
}
__device__ __forceinline__ void cp_commit() { asm volatile("cp.async.commit_group;\n"); }
template<int n> __device__ __forceinline__ void cp_wait() {
    asm volatile("cp.async.wait_group %0;\n" :: "n"(n));
}
__device__ __forceinline__ uint32_t cvta_smem(const void* p) {
    uint32_t a;
    asm("{ .reg .u64 t; cvta.to.shared.u64 t, %1; cvt.u32.u64 %0, t; }" : "=r"(a) : "l"(p));
    return a;
}
__device__ __forceinline__ void ldsm_x4(uint32_t& r0, uint32_t& r1, uint32_t& r2, uint32_t& r3,
                                        uint32_t addr) {
    asm volatile("ldmatrix.sync.aligned.m8n8.x4.shared.b16 {%0,%1,%2,%3}, [%4];"
                 : "=r"(r0), "=r"(r1), "=r"(r2), "=r"(r3) : "r"(addr));
}
__device__ __forceinline__ void ldsm_x2_trans(uint32_t& r0, uint32_t& r1, uint32_t addr) {
    asm volatile("ldmatrix.sync.aligned.m8n8.x2.trans.shared.b16 {%0,%1}, [%2];"
                 : "=r"(r0), "=r"(r1) : "r"(addr));
}

// ---------------- fp16 NT GEMM: C(M,N) = A(M,K) @ B(N,K)^T ----------------------
// 128x256x64 tiles, 512 threads (16 warps: 2 on M x 8 on N, warp tile 64x32),
// row pad 72 halves (144B), 3-stage cp.async ring, ldmatrix fragment loads.
// EPI==1: C(float) = resid + gate[(row/rows_per_b)*gate_ld+col]*acc
// OH==1:  C is __half
template<int EPI,int OH>
__global__ void __launch_bounds__(512, 1)
gemm_f16(const __half* __restrict__ A, const __half* __restrict__ Bg, void* __restrict__ Cv,
         int K, int lda, int ldb, int ldc,
         const float* __restrict__ resid, const float* __restrict__ gate,
         int gate_ld, int rows_per_b)
{
    constexpr int BM = 128, BN = 256, BK = 64, LDH = 72, ST = 3;

    extern __shared__ __half hsm[];
    __half* As = hsm;                    // ST * BM * LDH
    __half* Bs = hsm + ST * BM * LDH;    // ST * BN * LDH

    const int tid = threadIdx.x, wid = tid >> 5, lane = tid & 31;
    const int g = lane >> 2, c4 = lane & 3;
    const int q8 = lane >> 3, r8 = lane & 7;
    const int wm = wid & 1, wn = wid >> 1;        // 2 warps on M, 8 on N
    const int row0 = blockIdx.y * BM, col0 = blockIdx.x * BN;

    const __half* Arow = A  + (size_t)row0 * lda;
    const __half* Brow = Bg + (size_t)col0 * ldb;

    const uint32_t sA = cvta_smem(As);
    const uint32_t sB = cvta_smem(Bs);
    const int ldRow = tid >> 3;          // 0..63
    const int ldCol = (tid & 7) * 8;     // halves

    // ldmatrix per-lane address offsets
    const int rowA = wm * 64 + (q8 & 1) * 8 + r8;   // + 16*i
    const int colA = (q8 >> 1) * 8;                 // + 16*ks (halves)
    const int rowB = wn * 32 + (q8 >> 1) * 8 + r8;  // + 16*p
    const int colB = (q8 & 1) * 8;                  // + 16*ks

    auto load_tile = [&](int t) {
        const int st = t % ST;
        const int kt = t * BK;
        #pragma unroll
        for (int i = 0; i < 2; i++) {
            int r = i * 64 + ldRow;
            cpasync16(sA + (uint32_t)((st * BM + r) * LDH + ldCol) * 2,
                      Arow + (size_t)r * lda + kt + ldCol);
        }
        #pragma unroll
        for (int i = 0; i < 4; i++) {
            int r = i * 64 + ldRow;
            cpasync16(sB + (uint32_t)((st * BN + r) * LDH + ldCol) * 2,
                      Brow + (size_t)r * ldb + kt + ldCol);
        }
    };

    const int nT = K / BK;
    load_tile(0); cp_commit();
    if (nT > 1) load_tile(1);
    cp_commit();
    cp_wait<1>();
    __syncthreads();

    float acc[4][4][4];
    #pragma unroll
    for (int i = 0; i < 4; i++)
        #pragma unroll
        for (int j = 0; j < 4; j++)
            #pragma unroll
            for (int r = 0; r < 4; r++) acc[i][j][r] = 0.f;

    for (int t = 0; t < nT; t++) {
        const uint32_t aBase = sA + (uint32_t)((t % ST) * BM * LDH) * 2;
        const uint32_t bBase = sB + (uint32_t)((t % ST) * BN * LDH) * 2;

        #pragma unroll
        for (int ks = 0; ks < 4; ks++) {
            uint32_t af[4][4], bf[4][2];
            #pragma unroll
            for (int i = 0; i < 4; i++)
                ldsm_x4(af[i][0], af[i][1], af[i][2], af[i][3],
                        aBase + (uint32_t)((rowA + 16 * i) * LDH + colA + ks * 16) * 2);
            #pragma unroll
            for (int p = 0; p < 2; p++) {
                uint32_t b0, b1, b2, b3;
                ldsm_x4(b0, b1, b2, b3,
                        bBase + (uint32_t)((rowB + 16 * p) * LDH + colB + ks * 16) * 2);
                bf[2*p][0] = b0; bf[2*p][1] = b1;
                bf[2*p+1][0] = b2; bf[2*p+1][1] = b3;
            }
            #pragma unroll
            for (int i = 0; i < 4; i++)
                #pragma unroll
                for (int j = 0; j < 4; j++)
                    mma_f16(acc[i][j], af[i], bf[j]);
        }

        if (t + 2 < nT) load_tile(t + 2);
        cp_commit();
        cp_wait<1>();
        __syncthreads();
    }

    #pragma unroll
    for (int i = 0; i < 4; i++) {
        #pragma unroll
        for (int j = 0; j < 4; j++) {
            int col = col0 + wn * 32 + 8 * j + 2 * c4;
            #pragma unroll
            for (int h = 0; h < 2; h++) {
                int row = row0 + wm * 64 + 16 * i + g + 8 * h;
                float v0 = acc[i][j][2 * h + 0];
                float v1 = acc[i][j][2 * h + 1];
                if (EPI == 1) {
                    const float* rr = resid + (size_t)row * ldc + col;
                    const float* gg = gate + (size_t)(row / rows_per_b) * gate_ld + col;
                    v0 = rr[0] + gg[0] * v0;
                    v1 = rr[1] + gg[1] * v1;
                }
                if (OH == 1) {
                    *(__half2*)((__half*)Cv + (size_t)row * ldc + col) =
                        __floats2half2_rn(v0, v1);
                } else {
                    *(float2*)((float*)Cv + (size_t)row * ldc + col) = make_float2(v0, v1);
                }
            }
        }
    }
}

// ---------------- fused flash attention (fp16 mma, online softmax) ---------------
__global__ void __launch_bounds__(256, 2)
flash_kernel(const __half* __restrict__ Qg, const __half* __restrict__ Kg,
             const __half* __restrict__ Vg, __half* __restrict__ Og,
             int Skv, int ldq, int ldkv)
{
    const int h = blockIdx.y, b = blockIdx.z;
    const int n0 = blockIdx.x * 128;
    const __half* Qb = Qg + (size_t)b * Nn * ldq + (size_t)n0 * ldq + h * HDh;
    const __half* Kb = Kg + (size_t)b * Skv * ldkv + h * HDh;
    const __half* Vb = Vg + (size_t)b * Skv * ldkv + h * HDh;
    __half* Ob = Og + (size_t)b * Nn * INNER + (size_t)n0 * INNER + h * HDh;

    extern __shared__ __half fsm[];
    __half* Qs = fsm;                      // [128][72]
    __half* Ks = Qs + 128 * 72;            // [2][64][72]
    __half* Vs = Ks + 2 * 64 * 72;         // [2][64][72]
    __half* Ps = Vs + 2 * 64 * 72;         // [8 warps][16][72]

    const int tid = threadIdx.x, wid = tid >> 5, lane = tid & 31;
    const int g = lane >> 2, c4 = lane & 3;
    const int q8 = lane >> 3, r8 = lane & 7;

    const uint32_t sK = cvta_smem(Ks);
    const uint32_t sV = cvta_smem(Vs);

    {
        const __half2 sc2 = __floats2half2_rn(0.125f, 0.125f);
        #pragma unroll
        for (int it = 0; it < 4; it++) {
            int idx = it * 256 + tid;
            int r = idx >> 3, c = (idx & 7) * 8;
            uint4 qv = *(const uint4*)(Qb + (size_t)r * ldq + c);
            __half2* hp = (__half2*)&qv;
            hp[0] = __hmul2(hp[0], sc2);
            hp[1] = __hmul2(hp[1], sc2);
            hp[2] = __hmul2(hp[2], sc2);
            hp[3] = __hmul2(hp[3], sc2);
            *(uint4*)(Qs + r * 72 + c) = qv;
        }
    }

    auto loadKV = [&](int t, int buf) {
        const __half* Ksrc = Kb + (size_t)(t * 64) * ldkv;
        const __half* Vsrc = Vb + (size_t)(t * 64) * ldkv;
        #pragma unroll
        for (int it = 0; it < 2; it++) {
            int idx = it * 256 + tid;
            int r = idx >> 3, c = (idx & 7) * 8;
            cpasync16(sK + (uint32_t)((buf * 64 + r) * 72 + c) * 2, Ksrc + (size_t)r * ldkv + c);
            cpasync16(sV + (uint32_t)((buf * 64 + r) * 72 + c) * 2, Vsrc + (size_t)r * ldkv + c);
        }
    };
    loadKV(0, 0);
    cp_commit();
    cp_wait<0>();
    __syncthreads();

    uint32_t qf[4][4];
    {
        const uint32_t* Qw = (const uint32_t*)(Qs + wid * 16 * 72);
        #pragma unroll
        for (int ks = 0; ks < 4; ks++) {
            qf[ks][0] = Qw[(g    ) * 36 + 8 * ks + c4];
            qf[ks][1] = Qw[(g + 8) * 36 + 8 * ks + c4];
            qf[ks][2] = Qw[(g    ) * 36 + 8 * ks + c4 + 4];
            qf[ks][3] = Qw[(g + 8) * 36 + 8 * ks + c4 + 4];
        }
    }

    float o[8][4];
    #pragma unroll
    for (int j = 0; j < 8; j++)
        #pragma unroll
        for (int r = 0; r < 4; r++) o[j][r] = 0.f;
    float m0 = -1e30f, m1 = -1e30f, l0 = 0.f, l1 = 0.f;

    const int nT = Skv / 64;
    int buf = 0;

    __half* Pw = Ps + wid * 16 * 72;
    const uint32_t* Pww = (const uint32_t*)Pw;

    // ldmatrix lane offsets for K (B-type fragment)
    const int rowK = (q8 >> 1) * 8 + r8;   // + 16*p
    const int colK = (q8 & 1) * 8;         // + 16*ks

    for (int t = 0; t < nT; t++) {
        if (t + 1 < nT) loadKV(t + 1, buf ^ 1);
        cp_commit();

        float s[8][4];
        #pragma unroll
        for (int j = 0; j < 8; j++)
            #pragma unroll
            for (int r = 0; r < 4; r++) s[j][r] = 0.f;

        const uint32_t sKb = sK + (uint32_t)(buf * 64 * 72) * 2;
        #pragma unroll
        for (int ks = 0; ks < 4; ks++) {
            #pragma unroll
            for (int p = 0; p < 4; p++) {
                uint32_t b0, b1, b2, b3;
                ldsm_x4(b0, b1, b2, b3,
                        sKb + (uint32_t)((16 * p + rowK) * 72 + colK + ks * 16) * 2);
                uint32_t f0[2] = {b0, b1}, f1[2] = {b2, b3};
                mma_f16(s[2*p],   qf[ks], f0);
                mma_f16(s[2*p+1], qf[ks], f1);
            }
        }

        float rm0 = -1e30f, rm1 = -1e30f;
        #pragma unroll
        for (int j = 0; j < 8; j++) {
            rm0 = fmaxf(rm0, fmaxf(s[j][0], s[j][1]));
            rm1 = fmaxf(rm1, fmaxf(s[j][2], s[j][3]));
        }
        rm0 = fmaxf(rm0, __shfl_xor_sync(0xffffffff, rm0, 1));
        rm0 = fmaxf(rm0, __shfl_xor_sync(0xffffffff, rm0, 2));
        rm1 = fmaxf(rm1, __shfl_xor_sync(0xffffffff, rm1, 1));
        rm1 = fmaxf(rm1, __shfl_xor_sync(0xffffffff, rm1, 2));

        float mn0 = fmaxf(m0, rm0), mn1 = fmaxf(m1, rm1);
        float f0 = __expf(m0 - mn0), f1 = __expf(m1 - mn1);
        m0 = mn0; m1 = mn1;

        float sum0 = 0.f, sum1 = 0.f;
        #pragma unroll
        for (int j = 0; j < 8; j++) {
            float p0 = __expf(s[j][0] - mn0);
            float p1 = __expf(s[j][1] - mn0);
            float p2 = __expf(s[j][2] - mn1);
            float p3 = __expf(s[j][3] - mn1);
            sum0 += p0 + p1;
            sum1 += p2 + p3;
            *(__half2*)(Pw + (g    ) * 72 + 8 * j + 2 * c4) = __floats2half2_rn(p0, p1);
            *(__half2*)(Pw + (g + 8) * 72 + 8 * j + 2 * c4) = __floats2half2_rn(p2, p3);
        }
        sum0 += __shfl_xor_sync(0xffffffff, sum0, 1);
        sum0 += __shfl_xor_sync(0xffffffff, sum0, 2);
        sum1 += __shfl_xor_sync(0xffffffff, sum1, 1);
        sum1 += __shfl_xor_sync(0xffffffff, sum1, 2);
        l0 = l0 * f0 + sum0;
        l1 = l1 * f1 + sum1;

        #pragma unroll
        for (int j = 0; j < 8; j++) {
            o[j][0] *= f0; o[j][1] *= f0;
            o[j][2] *= f1; o[j][3] *= f1;
        }

        __syncwarp();

        const uint32_t sVb = sV + (uint32_t)(buf * 64 * 72) * 2;
        #pragma unroll
        for (int jk = 0; jk < 4; jk++) {
            uint32_t af[4];
            af[0] = Pww[(g    ) * 36 + 8 * jk + c4];
            af[1] = Pww[(g + 8) * 36 + 8 * jk + c4];
            af[2] = Pww[(g    ) * 36 + 8 * jk + c4 + 4];
            af[3] = Pww[(g + 8) * 36 + 8 * jk + c4 + 4];
            const uint32_t rowa = sVb + (uint32_t)((16 * jk + (lane & 15)) * 72) * 2;
            #pragma unroll
            for (int j = 0; j < 8; j++) {
                uint32_t b0, b1;
                ldsm_x2_trans(b0, b1, rowa + (uint32_t)(8 * j) * 2);
                uint32_t bfr[2] = {b0, b1};
                mma_f16(o[j], af, bfr);
            }
        }

        cp_wait<0>();
        __syncthreads();
        buf ^= 1;
    }

    float inv0 = 1.0f / l0, inv1 = 1.0f / l1;
    #pragma unroll
    for (int j = 0; j < 8; j++) {
        int col = 8 * j + 2 * c4;
        *(__half2*)(Ob + (size_t)(wid * 16 + g    ) * INNER + col) =
            __floats2half2_rn(o[j][0] * inv0, o[j][1] * inv0);
        *(__half2*)(Ob + (size_t)(wid * 16 + g + 8) * INNER + col) =
            __floats2half2_rn(o[j][2] * inv1, o[j][3] * inv1);
    }
}

// ---------------- fp32 -> fp16 conversion ----------------------------------------
__global__ void f32_to_f16_kernel(const float4* __restrict__ in, uint2* __restrict__ out, int n4)
{
    int i = blockIdx.x * blockDim.x + threadIdx.x;
    if (i < n4) {
        float4 t = in[i];
        __half2 lo = __floats2half2_rn(t.x, t.y);
        __half2 hi = __floats2half2_rn(t.z, t.w);
        uint2 o;
        o.x = *(uint32_t*)&lo;
        o.y = *(uint32_t*)&hi;
        out[i] = o;
    }
}

// ---------------- modulation (fp32) ----------------------------------------------
__global__ void mod_kernel(const float* __restrict__ cond,
                           const float* __restrict__ mw0, const float* __restrict__ mb0,
                           const float* __restrict__ mw1, const float* __restrict__ mb1,
                           const float* __restrict__ mw2, const float* __restrict__ mb2,
                           float* __restrict__ mods)
{
    __shared__ float cs[Bb * Dm];
    for (int i = threadIdx.x; i < Bb * Dm; i += blockDim.x) cs[i] = cond[i];
    __syncthreads();

    int warp = threadIdx.x >> 5, lane = threadIdx.x & 31;
    int j = blockIdx.x * 8 + warp;
    int norm = j / (3*Dm), jj = j - norm * (3*Dm);
    const float* mw = (norm == 0) ? mw0 : (norm == 1) ? mw1 : mw2;
    const float* mb = (norm == 0) ? mb0 : (norm == 1) ? mb1 : mb2;

    float acc[Bb];
    #pragma unroll
    for (int b = 0; b < Bb; b++) acc[b] = 0.f;
    const float* wrow = mw + (size_t)jj * Dm;
    for (int d = lane; d < Dm; d += 32) {
        float w = wrow[d];
        #pragma unroll
        for (int b = 0; b < Bb; b++) acc[b] = fmaf(w, cs[b*Dm + d], acc[b]);
    }
    #pragma unroll
    for (int b = 0; b < Bb; b++)
        #pragma unroll
        for (int off = 16; off > 0; off >>= 1)
            acc[b] += __shfl_xor_sync(0xffffffff, acc[b], off);
    if (lane < Bb)
        mods[(size_t)norm * Bb * 3*Dm + lane * 3*Dm + jj] = acc[lane] + mb[jj];
}

// ---------------- adaRMS norm (fp16 output) --------------------------------------
__global__ void rmsnorm_kernel(const float* __restrict__ x, const float* __restrict__ w,
                               const float* __restrict__ mod_base,
                               __half* __restrict__ out)
{
    int row = blockIdx.x;
    int b   = row / Nn;
    const float* xr = x + (size_t)row * Dm;
    const float* ms = mod_base + b * 3*Dm;

    float ss = 0.f;
    for (int i = threadIdx.x; i < Dm; i += blockDim.x) { float t = xr[i]; ss = fmaf(t,t,ss); }
    #pragma unroll
    for (int off = 16; off > 0; off >>= 1) ss += __shfl_xor_sync(0xffffffff, ss, off);
    __shared__ float red[8];
    if ((threadIdx.x & 31) == 0) red[threadIdx.x >> 5] = ss;
    __syncthreads();
    if (threadIdx.x < 8) {
        float v = red[threadIdx.x];
        #pragma unroll
        for (int off = 4; off > 0; off >>= 1) v += __shfl_xor_sync(0xff, v, off);
        if (threadIdx.x == 0) red[0] = v;
    }
    __syncthreads();
    float rn = rsqrtf(red[0] * (1.0f/Dm) + EPSf);

    __half* orow = out + (size_t)row * Dm;
    for (int i = threadIdx.x; i < Dm/2; i += blockDim.x) {
        int i2 = 2 * i;
        float a = xr[i2]   * rn * w[i2]   * (1.0f + ms[i2])   + ms[Dm + i2];
        float c = xr[i2+1] * rn * w[i2+1] * (1.0f + ms[i2+1]) + ms[Dm + i2+1];
        *(__half2*)(orow + i2) = __floats2half2_rn(a, c);
    }
}

// ---------------- silu(gate)*up from packed [row][2*MLP] half buffer -------------
__global__ void silu_mul_kernel(const __half2* __restrict__ gu, __half2* __restrict__ h, int n2)
{
    int i = blockIdx.x * blockDim.x + threadIdx.x;
    if (i < n2) {
        int row = i / (MLPm/2), c2 = i - row * (MLPm/2);
        __half2 g2 = gu[(size_t)row * MLPm + c2];
        __half2 u2 = gu[(size_t)row * MLPm + MLPm/2 + c2];
        float2 gf = __half22float2(g2);
        float2 uf = __half22float2(u2);
        float h0 = (gf.x / (1.0f + __expf(-gf.x))) * uf.x;
        float h1 = (gf.y / (1.0f + __expf(-gf.y))) * uf.y;
        h[i] = __floats2half2_rn(h0, h1);
    }
}

// ---------------- host orchestration -------------------------------------------
static void* symv(const void* s) { void* p = nullptr; cudaGetSymbolAddress(&p, s); return p; }

template<int EPI,int OH>
static void gemm_h(const __half* A, const __half* W, void* C, int M, int N, int K,
                   const float* resid, const float* gate, int gate_ld, int rpb)
{
    size_t sm = (size_t)3 * (128 + 256) * 72 * sizeof(__half);   // 165888
    cudaFuncSetAttribute(gemm_f16<EPI,OH>,
                         cudaFuncAttributeMaxDynamicSharedMemorySize, (int)sm);
    gemm_f16<EPI,OH><<<dim3(N/256, M/128), 512, sm>>>(
        A, W, C, K, K, K, N, resid, gate, gate_ld, rpb);
}

static void cvt_to(__half* dst, const float* src, int n)
{
    f32_to_f16_kernel<<<(n/4 + 255)/256, 256>>>((const float4*)src, (uint2*)dst, n/4);
}

static void launch_flash(const __half* q, const __half* k, const __half* v, __half* o,
                         int Skv, int ldq, int ldkv)
{
    size_t sm = (size_t)(128*72 + 2*64*72 + 2*64*72 + 8*16*72) * sizeof(__half);  // 73728
    cudaFuncSetAttribute(flash_kernel, cudaFuncAttributeMaxDynamicSharedMemorySize, (int)sm);
    flash_kernel<<<dim3(Nn/128, Hh, Bb), 256, sm>>>(q, k, v, o, Skv, ldq, ldkv);
}

extern "C" void kernel_launch(void* const* d_in, const int* in_sizes, int n_in,
                              void* d_out, int out_size)
{
    const float* x       = (const float*)d_in[0];
    const float* context = (const float*)d_in[1];
    const float* cond    = (const float*)d_in[2];
    const float* n1_w  = (const float*)d_in[3];
    const float* n1_mw = (const float*)d_in[4];
    const float* n1_mb = (const float*)d_in[5];
    const float* n2_w  = (const float*)d_in[6];
    const float* n2_mw = (const float*)d_in[7];
    const float* n2_mb = (const float*)d_in[8];
    const float* n3_w  = (const float*)d_in[9];
    const float* n3_mw = (const float*)d_in[10];
    const float* n3_mb = (const float*)d_in[11];
    const float* sa_q  = (const float*)d_in[12];
    const float* sa_k  = (const float*)d_in[13];
    const float* sa_v  = (const float*)d_in[14];
    const float* sa_o  = (const float*)d_in[15];
    const float* ca_q  = (const float*)d_in[16];
    const float* ca_k  = (const float*)d_in[17];
    const float* ca_v  = (const float*)d_in[18];
    const float* ca_o  = (const float*)d_in[19];
    const float* ff_gate = (const float*)d_in[20];
    const float* ff_up   = (const float*)d_in[21];
    const float* ff_down = (const float*)d_in[22];
    float* out = (float*)d_out;

    float*  mods   = (float*)symv(d_mods);
    __half* normed = (__half*)symv(d_normed);
    __half* qkv    = (__half*)symv(d_qkv);
    __half* kv     = (__half*)symv(d_kv);
    __half* ao     = (__half*)symv(d_attno);
    float*  x1     = (float*)symv(d_x1);
    float*  x2     = (float*)symv(d_x2);
    __half* gu     = (__half*)symv(d_gu);
    __half* hb     = (__half*)symv(d_hbuf);
    __half* ctx    = (__half*)symv(d_ctx);
    __half* wr     = (__half*)symv(d_wrnd);

    const int MQ = Bb * Nn;

    cvt_to(wr + W_SAQ,             sa_q, INNER*Dm);
    cvt_to(wr + W_SAQ + 1024*1024, sa_k, INNER*Dm);
    cvt_to(wr + W_SAQ + 2048*1024, sa_v, INNER*Dm);
    cvt_to(wr + W_SAO, sa_o, Dm*INNER);
    cvt_to(wr + W_CAQ, ca_q, INNER*Dm);
    cvt_to(wr + W_CAK,             ca_k, INNER*Cm);
    cvt_to(wr + W_CAK + 2048*1024, ca_v, INNER*Cm);
    cvt_to(wr + W_CAO, ca_o, Dm*INNER);
    cvt_to(wr + W_FFG,             ff_gate, MLPm*Dm);
    cvt_to(wr + W_FFG + 4096*1024, ff_up,   MLPm*Dm);
    cvt_to(wr + W_FFD, ff_down, Dm*MLPm);
    cvt_to(ctx, context, Bb*Ss*Cm);

    mod_kernel<<<(3*3*Dm)/8, 256>>>(cond, n1_mw, n1_mb, n2_mw, n2_mb, n3_mw, n3_mb, mods);

    // ===================== Self attention =====================
    rmsnorm_kernel<<<MQ, 256>>>(x, n1_w, mods + 0*Bb*3*Dm, normed);
    gemm_h<0,1>(normed, wr + W_SAQ, qkv, MQ, 3*INNER, Dm, nullptr, nullptr, 0, 1);
    launch_flash(qkv, qkv + INNER, qkv + 2*INNER, ao, Nn, 3*INNER, 3*INNER);
    gemm_h<1,0>(ao, wr + W_SAO, x1, MQ, Dm, INNER, x, mods + 0*Bb*3*Dm + 2*Dm, 3*Dm, Nn);

    // ===================== Cross attention =====================
    rmsnorm_kernel<<<MQ, 256>>>(x1, n2_w, mods + 1*Bb*3*Dm, normed);
    gemm_h<0,1>(normed, wr + W_CAQ, qkv, MQ, INNER, Dm, nullptr, nullptr, 0, 1);
    gemm_h<0,1>(ctx, wr + W_CAK, kv, Bb*Ss, 2*INNER, Cm, nullptr, nullptr, 0, 1);
    launch_flash(qkv, kv, kv + INNER, ao, Ss, INNER, 2*INNER);
    gemm_h<1,0>(ao, wr + W_CAO, x2, MQ, Dm, INNER, x1, mods + 1*Bb*3*Dm + 2*Dm, 3*Dm, Nn);

    // ===================== FFN =====================
    rmsnorm_kernel<<<MQ, 256>>>(x2, n3_w, mods + 2*Bb*3*Dm, normed);
    gemm_h<0,1>(normed, wr + W_FFG, gu, MQ, 2*MLPm, Dm, nullptr, nullptr, 0, 1);
    silu_mul_kernel<<<(MQ*MLPm/2 + 255)/256, 256>>>((const __half2*)gu, (__half2*)hb, MQ*MLPm/2);
    gemm_h<1,0>(hb, wr + W_FFD, out, MQ, Dm, MLPm, x2, mods + 2*Bb*3*Dm + 2*Dm, 3*Dm, Nn);
}

// round 10
// speedup vs baseline: 8.5706x; 1.0285x over previous
#include <cuda_runtime.h>
#include <cuda_fp16.h>
#include <math.h>
#include <stdint.h>

// Problem dims
#define Dm    1024
#define Cm    2048
#define MLPm  4096
#define Hh    16
#define HDh   64
#define Bb    8
#define Nn    512
#define Ss    2048
#define INNER (Hh*HDh)   // 1024
#define EPSf  1e-6f

// ---------------- scratch (static device allocations) ---------------------------
__device__ __align__(16) float  d_mods  [3 * Bb * 3 * Dm];
__device__ __align__(16) __half d_normed[Bb * Nn * Dm];
__device__ __align__(16) __half d_qkv   [Bb * Nn * 3 * INNER];
__device__ __align__(16) __half d_kv    [(size_t)Bb * Ss * 2 * INNER];
__device__ __align__(16) __half d_attno [Bb * Nn * INNER];
__device__ __align__(16) float  d_x1    [Bb * Nn * Dm];
__device__ __align__(16) float  d_x2    [Bb * Nn * Dm];
__device__ __align__(16) __half d_hbuf  [Bb * Nn * MLPm];
__device__ __align__(16) __half d_ctx   [(size_t)Bb * Ss * Cm];
__device__ __align__(16) __half d_wrnd  [22 * 1024 * 1024];

// weight offsets (elements); adjacency is load-bearing for fused GEMMs:
// [SAQ|SAK|SAV] 3072x1024, [CAK|CAV] 2048x2048, FFGU interleaved 8192x1024
#define W_SAQ  (0)
#define W_SAO  (3*1024*1024)
#define W_CAQ  (4*1024*1024)
#define W_CAK  (5*1024*1024)
#define W_CAO  (9*1024*1024)
#define W_FFGU (10*1024*1024)
#define W_FFD  (18*1024*1024)

// ---------------- helpers ---------------------------------------------------------
__device__ __forceinline__ void mma_f16(float* c, const uint32_t* a, const uint32_t* b) {
    asm volatile(
        "mma.sync.aligned.m16n8k16.row.col.f32.f16.f16.f32 "
        "{%0,%1,%2,%3}, {%4,%5,%6,%7}, {%8,%9}, {%0,%1,%2,%3};\n"
        : "+f"(c[0]), "+f"(c[1]), "+f"(c[2]), "+f"(c[3])
        : "r"(a[0]), "r"(a[1]), "r"(a[2]), "r"(a[3]), "r"(b[0]), "r"(b[1]));
}

__device__ __forceinline__ void cpasync16(uint32_t saddr, const void* gptr) {
    asm volatile("cp.async.cg.shared.global [%0], [%1], 16;\n" :: "r"(saddr), "l"(gptr));
}
__device__ __forceinline__ void cp_commit() { asm volatile("cp.async.commit_group;\n"); }
template<int n> __device__ __forceinline__ void cp_wait() {
    asm volatile("cp.async.wait_group %0;\n" :: "n"(n));
}
__device__ __forceinline__ uint32_t cvta_smem(const void* p) {
    uint32_t a;
    asm("{ .reg .u64 t; cvta.to.shared.u64 t, %1; cvt.u32.u64 %0, t; }" : "=r"(a) : "l"(p));
    return a;
}
__device__ __forceinline__ void ldsm_x4(uint32_t& r0, uint32_t& r1, uint32_t& r2, uint32_t& r3,
                                        uint32_t addr) {
    asm volatile("ldmatrix.sync.aligned.m8n8.x4.shared.b16 {%0,%1,%2,%3}, [%4];"
                 : "=r"(r0), "=r"(r1), "=r"(r2), "=r"(r3) : "r"(addr));
}
__device__ __forceinline__ void ldsm_x2_trans(uint32_t& r0, uint32_t& r1, uint32_t addr) {
    asm volatile("ldmatrix.sync.aligned.m8n8.x2.trans.shared.b16 {%0,%1}, [%2];"
                 : "=r"(r0), "=r"(r1) : "r"(addr));
}

// ---------------- fp16 NT GEMM: C(M,N) = A(M,K) @ B(N,K)^T ----------------------
// 128x256x64 tiles, 512 threads (2 warps on M x 8 on N, warp tile 64x32),
// row pad 72 halves, 4-stage cp.async ring, ldmatrix fragment loads.
// EPI==1: add resid + gate[(row/rows_per_b)*gate_ld+col]*acc (float out)
// OH: 0 = float out, 1 = half out, 2 = silu-pair: h[row][col/2] = silu(even)*odd
template<int EPI,int OH>
__global__ void __launch_bounds__(512, 1)
gemm_f16(const __half* __restrict__ A, const __half* __restrict__ Bg, void* __restrict__ Cv,
         int K, int lda, int ldb, int ldc,
         const float* __restrict__ resid, const float* __restrict__ gate,
         int gate_ld, int rows_per_b)
{
    constexpr int BM = 128, BN = 256, BK = 64, LDH = 72, ST = 4;

    extern __shared__ __half hsm[];
    __half* As = hsm;                    // ST * BM * LDH
    __half* Bs = hsm + ST * BM * LDH;    // ST * BN * LDH

    const int tid = threadIdx.x, wid = tid >> 5, lane = tid & 31;
    const int g = lane >> 2, c4 = lane & 3;
    const int q8 = lane >> 3, r8 = lane & 7;
    const int wm = wid & 1, wn = wid >> 1;
    const int row0 = blockIdx.y * BM, col0 = blockIdx.x * BN;

    const __half* Arow = A  + (size_t)row0 * lda;
    const __half* Brow = Bg + (size_t)col0 * ldb;

    const uint32_t sA = cvta_smem(As);
    const uint32_t sB = cvta_smem(Bs);
    const int ldRow = tid >> 3;
    const int ldCol = (tid & 7) * 8;

    const int rowA = wm * 64 + (q8 & 1) * 8 + r8;
    const int colA = (q8 >> 1) * 8;
    const int rowB = wn * 32 + (q8 >> 1) * 8 + r8;
    const int colB = (q8 & 1) * 8;

    auto load_tile = [&](int t) {
        const int st = t % ST;
        const int kt = t * BK;
        #pragma unroll
        for (int i = 0; i < 2; i++) {
            int r = i * 64 + ldRow;
            cpasync16(sA + (uint32_t)((st * BM + r) * LDH + ldCol) * 2,
                      Arow + (size_t)r * lda + kt + ldCol);
        }
        #pragma unroll
        for (int i = 0; i < 4; i++) {
            int r = i * 64 + ldRow;
            cpasync16(sB + (uint32_t)((st * BN + r) * LDH + ldCol) * 2,
                      Brow + (size_t)r * ldb + kt + ldCol);
        }
    };

    const int nT = K / BK;              // >= 16 for all our shapes
    load_tile(0); cp_commit();
    load_tile(1); cp_commit();
    load_tile(2); cp_commit();
    cp_wait<2>();
    __syncthreads();

    float acc[4][4][4];
    #pragma unroll
    for (int i = 0; i < 4; i++)
        #pragma unroll
        for (int j = 0; j < 4; j++)
            #pragma unroll
            for (int r = 0; r < 4; r++) acc[i][j][r] = 0.f;

    for (int t = 0; t < nT; t++) {
        const uint32_t aBase = sA + (uint32_t)((t % ST) * BM * LDH) * 2;
        const uint32_t bBase = sB + (uint32_t)((t % ST) * BN * LDH) * 2;

        #pragma unroll
        for (int ks = 0; ks < 4; ks++) {
            uint32_t af[4][4], bf[4][2];
            #pragma unroll
            for (int i = 0; i < 4; i++)
                ldsm_x4(af[i][0], af[i][1], af[i][2], af[i][3],
                        aBase + (uint32_t)((rowA + 16 * i) * LDH + colA + ks * 16) * 2);
            #pragma unroll
            for (int p = 0; p < 2; p++) {
                uint32_t b0, b1, b2, b3;
                ldsm_x4(b0, b1, b2, b3,
                        bBase + (uint32_t)((rowB + 16 * p) * LDH + colB + ks * 16) * 2);
                bf[2*p][0] = b0; bf[2*p][1] = b1;
                bf[2*p+1][0] = b2; bf[2*p+1][1] = b3;
            }
            #pragma unroll
            for (int i = 0; i < 4; i++)
                #pragma unroll
                for (int j = 0; j < 4; j++)
                    mma_f16(acc[i][j], af[i], bf[j]);
        }

        if (t + 3 < nT) load_tile(t + 3);
        cp_commit();
        cp_wait<2>();
        __syncthreads();
    }

    #pragma unroll
    for (int i = 0; i < 4; i++) {
        #pragma unroll
        for (int j = 0; j < 4; j++) {
            int col = col0 + wn * 32 + 8 * j + 2 * c4;
            #pragma unroll
            for (int h = 0; h < 2; h++) {
                int row = row0 + wm * 64 + 16 * i + g + 8 * h;
                float v0 = acc[i][j][2 * h + 0];
                float v1 = acc[i][j][2 * h + 1];
                if (EPI == 1) {
                    const float* rr = resid + (size_t)row * ldc + col;
                    const float* gg = gate + (size_t)(row / rows_per_b) * gate_ld + col;
                    v0 = rr[0] + gg[0] * v0;
                    v1 = rr[1] + gg[1] * v1;
                }
                if (OH == 1) {
                    *(__half2*)((__half*)Cv + (size_t)row * ldc + col) =
                        __floats2half2_rn(v0, v1);
                } else if (OH == 0) {
                    *(float2*)((float*)Cv + (size_t)row * ldc + col) = make_float2(v0, v1);
                } else {
                    // v0 = gate (even col), v1 = up (odd col)
                    float sv = (v0 / (1.0f + __expf(-v0))) * v1;
                    ((__half*)Cv)[(size_t)row * (ldc >> 1) + (col >> 1)] = __float2half_rn(sv);
                }
            }
        }
    }
}

// ---------------- fused flash attention (fp16 mma, online softmax) ---------------
__global__ void __launch_bounds__(256, 2)
flash_kernel(const __half* __restrict__ Qg, const __half* __restrict__ Kg,
             const __half* __restrict__ Vg, __half* __restrict__ Og,
             int Skv, int ldq, int ldkv)
{
    const int h = blockIdx.y, b = blockIdx.z;
    const int n0 = blockIdx.x * 128;
    const __half* Qb = Qg + (size_t)b * Nn * ldq + (size_t)n0 * ldq + h * HDh;
    const __half* Kb = Kg + (size_t)b * Skv * ldkv + h * HDh;
    const __half* Vb = Vg + (size_t)b * Skv * ldkv + h * HDh;
    __half* Ob = Og + (size_t)b * Nn * INNER + (size_t)n0 * INNER + h * HDh;

    extern __shared__ __half fsm[];
    __half* Qs = fsm;                      // [128][72]
    __half* Ks = Qs + 128 * 72;            // [2][64][72]
    __half* Vs = Ks + 2 * 64 * 72;         // [2][64][72]
    __half* Ps = Vs + 2 * 64 * 72;         // [8 warps][16][72]

    const int tid = threadIdx.x, wid = tid >> 5, lane = tid & 31;
    const int g = lane >> 2, c4 = lane & 3;
    const int q8 = lane >> 3, r8 = lane & 7;

    const uint32_t sK = cvta_smem(Ks);
    const uint32_t sV = cvta_smem(Vs);

    {
        const __half2 sc2 = __floats2half2_rn(0.125f, 0.125f);
        #pragma unroll
        for (int it = 0; it < 4; it++) {
            int idx = it * 256 + tid;
            int r = idx >> 3, c = (idx & 7) * 8;
            uint4 qv = *(const uint4*)(Qb + (size_t)r * ldq + c);
            __half2* hp = (__half2*)&qv;
            hp[0] = __hmul2(hp[0], sc2);
            hp[1] = __hmul2(hp[1], sc2);
            hp[2] = __hmul2(hp[2], sc2);
            hp[3] = __hmul2(hp[3], sc2);
            *(uint4*)(Qs + r * 72 + c) = qv;
        }
    }

    auto loadKV = [&](int t, int buf) {
        const __half* Ksrc = Kb + (size_t)(t * 64) * ldkv;
        const __half* Vsrc = Vb + (size_t)(t * 64) * ldkv;
        #pragma unroll
        for (int it = 0; it < 2; it++) {
            int idx = it * 256 + tid;
            int r = idx >> 3, c = (idx & 7) * 8;
            cpasync16(sK + (uint32_t)((buf * 64 + r) * 72 + c) * 2, Ksrc + (size_t)r * ldkv + c);
            cpasync16(sV + (uint32_t)((buf * 64 + r) * 72 + c) * 2, Vsrc + (size_t)r * ldkv + c);
        }
    };
    loadKV(0, 0);
    cp_commit();
    cp_wait<0>();
    __syncthreads();

    uint32_t qf[4][4];
    {
        const uint32_t* Qw = (const uint32_t*)(Qs + wid * 16 * 72);
        #pragma unroll
        for (int ks = 0; ks < 4; ks++) {
            qf[ks][0] = Qw[(g    ) * 36 + 8 * ks + c4];
            qf[ks][1] = Qw[(g + 8) * 36 + 8 * ks + c4];
            qf[ks][2] = Qw[(g    ) * 36 + 8 * ks + c4 + 4];
            qf[ks][3] = Qw[(g + 8) * 36 + 8 * ks + c4 + 4];
        }
    }

    float o[8][4];
    #pragma unroll
    for (int j = 0; j < 8; j++)
        #pragma unroll
        for (int r = 0; r < 4; r++) o[j][r] = 0.f;
    float m0 = -1e30f, m1 = -1e30f, l0 = 0.f, l1 = 0.f;

    const int nT = Skv / 64;
    int buf = 0;

    __half* Pw = Ps + wid * 16 * 72;
    const uint32_t* Pww = (const uint32_t*)Pw;

    const int rowK = (q8 >> 1) * 8 + r8;
    const int colK = (q8 & 1) * 8;

    for (int t = 0; t < nT; t++) {
        if (t + 1 < nT) loadKV(t + 1, buf ^ 1);
        cp_commit();

        float s[8][4];
        #pragma unroll
        for (int j = 0; j < 8; j++)
            #pragma unroll
            for (int r = 0; r < 4; r++) s[j][r] = 0.f;

        const uint32_t sKb = sK + (uint32_t)(buf * 64 * 72) * 2;
        #pragma unroll
        for (int ks = 0; ks < 4; ks++) {
            #pragma unroll
            for (int p = 0; p < 4; p++) {
                uint32_t b0, b1, b2, b3;
                ldsm_x4(b0, b1, b2, b3,
                        sKb + (uint32_t)((16 * p + rowK) * 72 + colK + ks * 16) * 2);
                uint32_t f0[2] = {b0, b1}, f1[2] = {b2, b3};
                mma_f16(s[2*p],   qf[ks], f0);
                mma_f16(s[2*p+1], qf[ks], f1);
            }
        }

        float rm0 = -1e30f, rm1 = -1e30f;
        #pragma unroll
        for (int j = 0; j < 8; j++) {
            rm0 = fmaxf(rm0, fmaxf(s[j][0], s[j][1]));
            rm1 = fmaxf(rm1, fmaxf(s[j][2], s[j][3]));
        }
        rm0 = fmaxf(rm0, __shfl_xor_sync(0xffffffff, rm0, 1));
        rm0 = fmaxf(rm0, __shfl_xor_sync(0xffffffff, rm0, 2));
        rm1 = fmaxf(rm1, __shfl_xor_sync(0xffffffff, rm1, 1));
        rm1 = fmaxf(rm1, __shfl_xor_sync(0xffffffff, rm1, 2));

        float mn0 = fmaxf(m0, rm0), mn1 = fmaxf(m1, rm1);
        float f0 = __expf(m0 - mn0), f1 = __expf(m1 - mn1);
        m0 = mn0; m1 = mn1;

        float sum0 = 0.f, sum1 = 0.f;
        #pragma unroll
        for (int j = 0; j < 8; j++) {
            float p0 = __expf(s[j][0] - mn0);
            float p1 = __expf(s[j][1] - mn0);
            float p2 = __expf(s[j][2] - mn1);
            float p3 = __expf(s[j][3] - mn1);
            sum0 += p0 + p1;
            sum1 += p2 + p3;
            *(__half2*)(Pw + (g    ) * 72 + 8 * j + 2 * c4) = __floats2half2_rn(p0, p1);
            *(__half2*)(Pw + (g + 8) * 72 + 8 * j + 2 * c4) = __floats2half2_rn(p2, p3);
        }
        sum0 += __shfl_xor_sync(0xffffffff, sum0, 1);
        sum0 += __shfl_xor_sync(0xffffffff, sum0, 2);
        sum1 += __shfl_xor_sync(0xffffffff, sum1, 1);
        sum1 += __shfl_xor_sync(0xffffffff, sum1, 2);
        l0 = l0 * f0 + sum0;
        l1 = l1 * f1 + sum1;

        #pragma unroll
        for (int j = 0; j < 8; j++) {
            o[j][0] *= f0; o[j][1] *= f0;
            o[j][2] *= f1; o[j][3] *= f1;
        }

        __syncwarp();

        const uint32_t sVb = sV + (uint32_t)(buf * 64 * 72) * 2;
        #pragma unroll
        for (int jk = 0; jk < 4; jk++) {
            uint32_t af[4];
            af[0] = Pww[(g    ) * 36 + 8 * jk + c4];
            af[1] = Pww[(g + 8) * 36 + 8 * jk + c4];
            af[2] = Pww[(g    ) * 36 + 8 * jk + c4 + 4];
            af[3] = Pww[(g + 8) * 36 + 8 * jk + c4 + 4];
            const uint32_t rowa = sVb + (uint32_t)((16 * jk + (lane & 15)) * 72) * 2;
            #pragma unroll
            for (int j = 0; j < 8; j++) {
                uint32_t b0, b1;
                ldsm_x2_trans(b0, b1, rowa + (uint32_t)(8 * j) * 2);
                uint32_t bfr[2] = {b0, b1};
                mma_f16(o[j], af, bfr);
            }
        }

        cp_wait<0>();
        __syncthreads();
        buf ^= 1;
    }

    float inv0 = 1.0f / l0, inv1 = 1.0f / l1;
    #pragma unroll
    for (int j = 0; j < 8; j++) {
        int col = 8 * j + 2 * c4;
        *(__half2*)(Ob + (size_t)(wid * 16 + g    ) * INNER + col) =
            __floats2half2_rn(o[j][0] * inv0, o[j][1] * inv0);
        *(__half2*)(Ob + (size_t)(wid * 16 + g + 8) * INNER + col) =
            __floats2half2_rn(o[j][2] * inv1, o[j][3] * inv1);
    }
}

// ---------------- fp32 -> fp16 conversion ----------------------------------------
__device__ __forceinline__ uint2 cvt4(float4 t) {
    __half2 lo = __floats2half2_rn(t.x, t.y);
    __half2 hi = __floats2half2_rn(t.z, t.w);
    uint2 o;
    o.x = *(uint32_t*)&lo;
    o.y = *(uint32_t*)&hi;
    return o;
}
__global__ void f32_to_f16_kernel(const float4* __restrict__ in, uint2* __restrict__ out, int n4)
{
    int i = blockIdx.x * blockDim.x + threadIdx.x;
    if (i < n4) out[i] = cvt4(in[i]);
}
// interleave gate/up rows: out row 2r = gate r, out row 2r+1 = up r
__global__ void f32_to_f16_ileave(const float4* __restrict__ gsrc, const float4* __restrict__ usrc,
                                  uint2* __restrict__ out, int n4, int cols4)
{
    int i = blockIdx.x * blockDim.x + threadIdx.x;
    if (i < n4) {
        int r = i / cols4, c = i - r * cols4;
        out[(size_t)(2 * r) * cols4 + c]     = cvt4(gsrc[i]);
        out[(size_t)(2 * r + 1) * cols4 + c] = cvt4(usrc[i]);
    }
}

// ---------------- modulation (fp32) ----------------------------------------------
__global__ void mod_kernel(const float* __restrict__ cond,
                           const float* __restrict__ mw0, const float* __restrict__ mb0,
                           const float* __restrict__ mw1, const float* __restrict__ mb1,
                           const float* __restrict__ mw2, const float* __restrict__ mb2,
                           float* __restrict__ mods)
{
    __shared__ float cs[Bb * Dm];
    for (int i = threadIdx.x; i < Bb * Dm; i += blockDim.x) cs[i] = cond[i];
    __syncthreads();

    int warp = threadIdx.x >> 5, lane = threadIdx.x & 31;
    int j = blockIdx.x * 8 + warp;
    int norm = j / (3*Dm), jj = j - norm * (3*Dm);
    const float* mw = (norm == 0) ? mw0 : (norm == 1) ? mw1 : mw2;
    const float* mb = (norm == 0) ? mb0 : (norm == 1) ? mb1 : mb2;

    float acc[Bb];
    #pragma unroll
    for (int b = 0; b < Bb; b++) acc[b] = 0.f;
    const float* wrow = mw + (size_t)jj * Dm;
    for (int d = lane; d < Dm; d += 32) {
        float w = wrow[d];
        #pragma unroll
        for (int b = 0; b < Bb; b++) acc[b] = fmaf(w, cs[b*Dm + d], acc[b]);
    }
    #pragma unroll
    for (int b = 0; b < Bb; b++)
        #pragma unroll
        for (int off = 16; off > 0; off >>= 1)
            acc[b] += __shfl_xor_sync(0xffffffff, acc[b], off);
    if (lane < Bb)
        mods[(size_t)norm * Bb * 3*Dm + lane * 3*Dm + jj] = acc[lane] + mb[jj];
}

// ---------------- adaRMS norm (fp16 output) --------------------------------------
__global__ void rmsnorm_kernel(const float* __restrict__ x, const float* __restrict__ w,
                               const float* __restrict__ mod_base,
                               __half* __restrict__ out)
{
    int row = blockIdx.x;
    int b   = row / Nn;
    const float* xr = x + (size_t)row * Dm;
    const float* ms = mod_base + b * 3*Dm;

    float ss = 0.f;
    for (int i = threadIdx.x; i < Dm; i += blockDim.x) { float t = xr[i]; ss = fmaf(t,t,ss); }
    #pragma unroll
    for (int off = 16; off > 0; off >>= 1) ss += __shfl_xor_sync(0xffffffff, ss, off);
    __shared__ float red[8];
    if ((threadIdx.x & 31) == 0) red[threadIdx.x >> 5] = ss;
    __syncthreads();
    if (threadIdx.x < 8) {
        float v = red[threadIdx.x];
        #pragma unroll
        for (int off = 4; off > 0; off >>= 1) v += __shfl_xor_sync(0xff, v, off);
        if (threadIdx.x == 0) red[0] = v;
    }
    __syncthreads();
    float rn = rsqrtf(red[0] * (1.0f/Dm) + EPSf);

    __half* orow = out + (size_t)row * Dm;
    for (int i = threadIdx.x; i < Dm/2; i += blockDim.x) {
        int i2 = 2 * i;
        float a = xr[i2]   * rn * w[i2]   * (1.0f + ms[i2])   + ms[Dm + i2];
        float c = xr[i2+1] * rn * w[i2+1] * (1.0f + ms[i2+1]) + ms[Dm + i2+1];
        *(__half2*)(orow + i2) = __floats2half2_rn(a, c);
    }
}

// ---------------- host orchestration -------------------------------------------
static void* symv(const void* s) { void* p = nullptr; cudaGetSymbolAddress(&p, s); return p; }

template<int EPI,int OH>
static void gemm_h(cudaStream_t st, const __half* A, const __half* W, void* C,
                   int M, int N, int K,
                   const float* resid, const float* gate, int gate_ld, int rpb)
{
    size_t sm = (size_t)4 * (128 + 256) * 72 * sizeof(__half);   // 221184
    cudaFuncSetAttribute(gemm_f16<EPI,OH>,
                         cudaFuncAttributeMaxDynamicSharedMemorySize, (int)sm);
    gemm_f16<EPI,OH><<<dim3(N/256, M/128), 512, sm, st>>>(
        A, W, C, K, K, K, N, resid, gate, gate_ld, rpb);
}

static void cvt_to(cudaStream_t st, __half* dst, const float* src, int n)
{
    f32_to_f16_kernel<<<(n/4 + 255)/256, 256, 0, st>>>((const float4*)src, (uint2*)dst, n/4);
}

static void launch_flash(const __half* q, const __half* k, const __half* v, __half* o,
                         int Skv, int ldq, int ldkv)
{
    size_t sm = (size_t)(128*72 + 2*64*72 + 2*64*72 + 8*16*72) * sizeof(__half);  // 73728
    cudaFuncSetAttribute(flash_kernel, cudaFuncAttributeMaxDynamicSharedMemorySize, (int)sm);
    flash_kernel<<<dim3(Nn/128, Hh, Bb), 256, sm>>>(q, k, v, o, Skv, ldq, ldkv);
}

extern "C" void kernel_launch(void* const* d_in, const int* in_sizes, int n_in,
                              void* d_out, int out_size)
{
    const float* x       = (const float*)d_in[0];
    const float* context = (const float*)d_in[1];
    const float* cond    = (const float*)d_in[2];
    const float* n1_w  = (const float*)d_in[3];
    const float* n1_mw = (const float*)d_in[4];
    const float* n1_mb = (const float*)d_in[5];
    const float* n2_w  = (const float*)d_in[6];
    const float* n2_mw = (const float*)d_in[7];
    const float* n2_mb = (const float*)d_in[8];
    const float* n3_w  = (const float*)d_in[9];
    const float* n3_mw = (const float*)d_in[10];
    const float* n3_mb = (const float*)d_in[11];
    const float* sa_q  = (const float*)d_in[12];
    const float* sa_k  = (const float*)d_in[13];
    const float* sa_v  = (const float*)d_in[14];
    const float* sa_o  = (const float*)d_in[15];
    const float* ca_q  = (const float*)d_in[16];
    const float* ca_k  = (const float*)d_in[17];
    const float* ca_v  = (const float*)d_in[18];
    const float* ca_o  = (const float*)d_in[19];
    const float* ff_gate = (const float*)d_in[20];
    const float* ff_up   = (const float*)d_in[21];
    const float* ff_down = (const float*)d_in[22];
    float* out = (float*)d_out;

    float*  mods   = (float*)symv(d_mods);
    __half* normed = (__half*)symv(d_normed);
    __half* qkv    = (__half*)symv(d_qkv);
    __half* kv     = (__half*)symv(d_kv);
    __half* ao     = (__half*)symv(d_attno);
    float*  x1     = (float*)symv(d_x1);
    float*  x2     = (float*)symv(d_x2);
    __half* hb     = (__half*)symv(d_hbuf);
    __half* ctx    = (__half*)symv(d_ctx);
    __half* wr     = (__half*)symv(d_wrnd);

    const int MQ = Bb * Nn;

    // side stream + events, created once (resources only; per-call work identical)
    static cudaStream_t s2 = nullptr;
    static cudaEvent_t evFork = nullptr, evJoin = nullptr;
    if (s2 == nullptr) {
        cudaStreamCreateWithFlags(&s2, cudaStreamNonBlocking);
        cudaEventCreateWithFlags(&evFork, cudaEventDisableTiming);
        cudaEventCreateWithFlags(&evJoin, cudaEventDisableTiming);
    }

    // ---- fork: CA K/V branch runs on s2, independent of the SA chain ----
    cudaEventRecord(evFork, 0);
    cudaStreamWaitEvent(s2, evFork, 0);

    // s2: context + CA K/V weights conversion, then the big CA KV GEMM
    cvt_to(s2, wr + W_CAK,             ca_k, INNER*Cm);
    cvt_to(s2, wr + W_CAK + 2048*1024, ca_v, INNER*Cm);
    cvt_to(s2, ctx, context, Bb*Ss*Cm);
    gemm_h<0,1>(s2, ctx, wr + W_CAK, kv, Bb*Ss, 2*INNER, Cm, nullptr, nullptr, 0, 1);
    cudaEventRecord(evJoin, s2);

    // default stream: everything else
    cvt_to(0, wr + W_SAQ,             sa_q, INNER*Dm);
    cvt_to(0, wr + W_SAQ + 1024*1024, sa_k, INNER*Dm);
    cvt_to(0, wr + W_SAQ + 2048*1024, sa_v, INNER*Dm);
    cvt_to(0, wr + W_SAO, sa_o, Dm*INNER);
    cvt_to(0, wr + W_CAQ, ca_q, INNER*Dm);
    cvt_to(0, wr + W_CAO, ca_o, Dm*INNER);
    f32_to_f16_ileave<<<(MLPm*Dm/4 + 255)/256, 256>>>(
        (const float4*)ff_gate, (const float4*)ff_up,
        (uint2*)(wr + W_FFGU), MLPm*Dm/4, Dm/4);
    cvt_to(0, wr + W_FFD, ff_down, Dm*MLPm);

    mod_kernel<<<(3*3*Dm)/8, 256>>>(cond, n1_mw, n1_mb, n2_mw, n2_mb, n3_mw, n3_mb, mods);

    // ===================== Self attention =====================
    rmsnorm_kernel<<<MQ, 256>>>(x, n1_w, mods + 0*Bb*3*Dm, normed);
    gemm_h<0,1>(0, normed, wr + W_SAQ, qkv, MQ, 3*INNER, Dm, nullptr, nullptr, 0, 1);
    launch_flash(qkv, qkv + INNER, qkv + 2*INNER, ao, Nn, 3*INNER, 3*INNER);
    gemm_h<1,0>(0, ao, wr + W_SAO, x1, MQ, Dm, INNER, x, mods + 0*Bb*3*Dm + 2*Dm, 3*Dm, Nn);

    // ===================== Cross attention =====================
    rmsnorm_kernel<<<MQ, 256>>>(x1, n2_w, mods + 1*Bb*3*Dm, normed);
    gemm_h<0,1>(0, normed, wr + W_CAQ, qkv, MQ, INNER, Dm, nullptr, nullptr, 0, 1);
    cudaStreamWaitEvent(0, evJoin, 0);   // join: kv ready
    launch_flash(qkv, kv, kv + INNER, ao, Ss, INNER, 2*INNER);
    gemm_h<1,0>(0, ao, wr + W_CAO, x2, MQ, Dm, INNER, x1, mods + 1*Bb*3*Dm + 2*Dm, 3*Dm, Nn);

    // ===================== FFN =====================
    rmsnorm_kernel<<<MQ, 256>>>(x2, n3_w, mods + 2*Bb*3*Dm, normed);
    // fused gate|up (interleaved weights) with silu epilogue -> hb directly
    gemm_h<0,2>(0, normed, wr + W_FFGU, hb, MQ, 2*MLPm, Dm, nullptr, nullptr, 0, 1);
    gemm_h<1,0>(0, hb, wr + W_FFD, out, MQ, Dm, MLPm, x2, mods + 2*Bb*3*Dm + 2*Dm, 3*Dm, Nn);
}

// round 11
// speedup vs baseline: 8.7914x; 1.0258x over previous
#include <cuda_runtime.h>
#include <cuda_fp16.h>
#include <math.h>
#include <stdint.h>

// Problem dims
#define Dm    1024
#define Cm    2048
#define MLPm  4096
#define Hh    16
#define HDh   64
#define Bb    8
#define Nn    512
#define Ss    2048
#define INNER (Hh*HDh)   // 1024
#define EPSf  1e-6f

// ---------------- scratch (static device allocations) ---------------------------
__device__ __align__(16) float  d_mods  [3 * Bb * 3 * Dm];
__device__ __align__(16) __half d_normed[Bb * Nn * Dm];
__device__ __align__(16) __half d_qkv   [Bb * Nn * 3 * INNER];
__device__ __align__(16) __half d_kv    [(size_t)Bb * Ss * 2 * INNER];
__device__ __align__(16) __half d_attno [Bb * Nn * INNER];
__device__ __align__(16) float  d_x1    [Bb * Nn * Dm];
__device__ __align__(16) float  d_x2    [Bb * Nn * Dm];
__device__ __align__(16) __half d_hbuf  [Bb * Nn * MLPm];
__device__ __align__(16) __half d_ctx   [(size_t)Bb * Ss * Cm];
__device__ __align__(16) __half d_wrnd  [22 * 1024 * 1024];

// weight offsets (elements); adjacency is load-bearing for fused GEMMs:
// [SAQ|SAK|SAV] 3072x1024, [CAK|CAV] 2048x2048, FFGU interleaved 8192x1024
#define W_SAQ  (0)
#define W_SAO  (3*1024*1024)
#define W_CAQ  (4*1024*1024)
#define W_CAK  (5*1024*1024)
#define W_CAO  (9*1024*1024)
#define W_FFGU (10*1024*1024)
#define W_FFD  (18*1024*1024)

// ---------------- helpers ---------------------------------------------------------
__device__ __forceinline__ void mma_f16(float* c, const uint32_t* a, const uint32_t* b) {
    asm volatile(
        "mma.sync.aligned.m16n8k16.row.col.f32.f16.f16.f32 "
        "{%0,%1,%2,%3}, {%4,%5,%6,%7}, {%8,%9}, {%0,%1,%2,%3};\n"
        : "+f"(c[0]), "+f"(c[1]), "+f"(c[2]), "+f"(c[3])
        : "r"(a[0]), "r"(a[1]), "r"(a[2]), "r"(a[3]), "r"(b[0]), "r"(b[1]));
}

__device__ __forceinline__ void cpasync16(uint32_t saddr, const void* gptr) {
    asm volatile("cp.async.cg.shared.global [%0], [%1], 16;\n" :: "r"(saddr), "l"(gptr));
}
__device__ __forceinline__ void cp_commit() { asm volatile("cp.async.commit_group;\n"); }
template<int n> __device__ __forceinline__ void cp_wait() {
    asm volatile("cp.async.wait_group %0;\n" :: "n"(n));
}
__device__ __forceinline__ uint32_t cvta_smem(const void* p) {
    uint32_t a;
    asm("{ .reg .u64 t; cvta.to.shared.u64 t, %1; cvt.u32.u64 %0, t; }" : "=r"(a) : "l"(p));
    return a;
}
__device__ __forceinline__ void ldsm_x4(uint32_t& r0, uint32_t& r1, uint32_t& r2, uint32_t& r3,
                                        uint32_t addr) {
    asm volatile("ldmatrix.sync.aligned.m8n8.x4.shared.b16 {%0,%1,%2,%3}, [%4];"
                 : "=r"(r0), "=r"(r1), "=r"(r2), "=r"(r3) : "r"(addr));
}
__device__ __forceinline__ void ldsm_x2_trans(uint32_t& r0, uint32_t& r1, uint32_t addr) {
    asm volatile("ldmatrix.sync.aligned.m8n8.x2.trans.shared.b16 {%0,%1}, [%2];"
                 : "=r"(r0), "=r"(r1) : "r"(addr));
}
__device__ __forceinline__ uint32_t pack_h2(float a, float b) {
    __half2 h = __floats2half2_rn(a, b);
    return *(uint32_t*)&h;
}

// ---------------- fp16 NT GEMM: C(M,N) = A(M,K) @ B(N,K)^T ----------------------
// 128x256x64 tiles, 512 threads (2 warps on M x 8 on N, warp tile 64x32),
// row pad 72 halves, 4-stage cp.async ring, ldmatrix fragment loads.
// EPI==1: add resid + gate[(row/rows_per_b)*gate_ld+col]*acc (float out)
// OH: 0 = float out, 1 = half out, 2 = silu-pair: h[row][col/2] = silu(even)*odd
template<int EPI,int OH>
__global__ void __launch_bounds__(512, 1)
gemm_f16(const __half* __restrict__ A, const __half* __restrict__ Bg, void* __restrict__ Cv,
         int K, int lda, int ldb, int ldc,
         const float* __restrict__ resid, const float* __restrict__ gate,
         int gate_ld, int rows_per_b)
{
    constexpr int BM = 128, BN = 256, BK = 64, LDH = 72, ST = 4;

    extern __shared__ __half hsm[];
    __half* As = hsm;
    __half* Bs = hsm + ST * BM * LDH;

    const int tid = threadIdx.x, wid = tid >> 5, lane = tid & 31;
    const int g = lane >> 2, c4 = lane & 3;
    const int q8 = lane >> 3, r8 = lane & 7;
    const int wm = wid & 1, wn = wid >> 1;
    const int row0 = blockIdx.y * BM, col0 = blockIdx.x * BN;

    const __half* Arow = A  + (size_t)row0 * lda;
    const __half* Brow = Bg + (size_t)col0 * ldb;

    const uint32_t sA = cvta_smem(As);
    const uint32_t sB = cvta_smem(Bs);
    const int ldRow = tid >> 3;
    const int ldCol = (tid & 7) * 8;

    const int rowA = wm * 64 + (q8 & 1) * 8 + r8;
    const int colA = (q8 >> 1) * 8;
    const int rowB = wn * 32 + (q8 >> 1) * 8 + r8;
    const int colB = (q8 & 1) * 8;

    auto load_tile = [&](int t) {
        const int st = t % ST;
        const int kt = t * BK;
        #pragma unroll
        for (int i = 0; i < 2; i++) {
            int r = i * 64 + ldRow;
            cpasync16(sA + (uint32_t)((st * BM + r) * LDH + ldCol) * 2,
                      Arow + (size_t)r * lda + kt + ldCol);
        }
        #pragma unroll
        for (int i = 0; i < 4; i++) {
            int r = i * 64 + ldRow;
            cpasync16(sB + (uint32_t)((st * BN + r) * LDH + ldCol) * 2,
                      Brow + (size_t)r * ldb + kt + ldCol);
        }
    };

    const int nT = K / BK;
    load_tile(0); cp_commit();
    load_tile(1); cp_commit();
    load_tile(2); cp_commit();
    cp_wait<2>();
    __syncthreads();

    float acc[4][4][4];
    #pragma unroll
    for (int i = 0; i < 4; i++)
        #pragma unroll
        for (int j = 0; j < 4; j++)
            #pragma unroll
            for (int r = 0; r < 4; r++) acc[i][j][r] = 0.f;

    for (int t = 0; t < nT; t++) {
        const uint32_t aBase = sA + (uint32_t)((t % ST) * BM * LDH) * 2;
        const uint32_t bBase = sB + (uint32_t)((t % ST) * BN * LDH) * 2;

        #pragma unroll
        for (int ks = 0; ks < 4; ks++) {
            uint32_t af[4][4], bf[4][2];
            #pragma unroll
            for (int i = 0; i < 4; i++)
                ldsm_x4(af[i][0], af[i][1], af[i][2], af[i][3],
                        aBase + (uint32_t)((rowA + 16 * i) * LDH + colA + ks * 16) * 2);
            #pragma unroll
            for (int p = 0; p < 2; p++) {
                uint32_t b0, b1, b2, b3;
                ldsm_x4(b0, b1, b2, b3,
                        bBase + (uint32_t)((rowB + 16 * p) * LDH + colB + ks * 16) * 2);
                bf[2*p][0] = b0; bf[2*p][1] = b1;
                bf[2*p+1][0] = b2; bf[2*p+1][1] = b3;
            }
            #pragma unroll
            for (int i = 0; i < 4; i++)
                #pragma unroll
                for (int j = 0; j < 4; j++)
                    mma_f16(acc[i][j], af[i], bf[j]);
        }

        if (t + 3 < nT) load_tile(t + 3);
        cp_commit();
        cp_wait<2>();
        __syncthreads();
    }

    #pragma unroll
    for (int i = 0; i < 4; i++) {
        #pragma unroll
        for (int j = 0; j < 4; j++) {
            int col = col0 + wn * 32 + 8 * j + 2 * c4;
            #pragma unroll
            for (int h = 0; h < 2; h++) {
                int row = row0 + wm * 64 + 16 * i + g + 8 * h;
                float v0 = acc[i][j][2 * h + 0];
                float v1 = acc[i][j][2 * h + 1];
                if (EPI == 1) {
                    const float* rr = resid + (size_t)row * ldc + col;
                    const float* gg = gate + (size_t)(row / rows_per_b) * gate_ld + col;
                    v0 = rr[0] + gg[0] * v0;
                    v1 = rr[1] + gg[1] * v1;
                }
                if (OH == 1) {
                    *(__half2*)((__half*)Cv + (size_t)row * ldc + col) =
                        __floats2half2_rn(v0, v1);
                } else if (OH == 0) {
                    *(float2*)((float*)Cv + (size_t)row * ldc + col) = make_float2(v0, v1);
                } else {
                    float sv = (v0 / (1.0f + __expf(-v0))) * v1;
                    ((__half*)Cv)[(size_t)row * (ldc >> 1) + (col >> 1)] = __float2half_rn(sv);
                }
            }
        }
    }
}

// ---------------- fused flash attention (fp16 mma, register-resident P) ----------
// S-fragment IS the PV A-fragment after exp: no smem round trip for P.
__global__ void __launch_bounds__(256, 2)
flash_kernel(const __half* __restrict__ Qg, const __half* __restrict__ Kg,
             const __half* __restrict__ Vg, __half* __restrict__ Og,
             int Skv, int ldq, int ldkv)
{
    const int h = blockIdx.y, b = blockIdx.z;
    const int n0 = blockIdx.x * 128;
    const __half* Qb = Qg + (size_t)b * Nn * ldq + (size_t)n0 * ldq + h * HDh;
    const __half* Kb = Kg + (size_t)b * Skv * ldkv + h * HDh;
    const __half* Vb = Vg + (size_t)b * Skv * ldkv + h * HDh;
    __half* Ob = Og + (size_t)b * Nn * INNER + (size_t)n0 * INNER + h * HDh;

    extern __shared__ __half fsm[];
    __half* Qs = fsm;                      // [128][72]
    __half* Ks = Qs + 128 * 72;            // [2][64][72]
    __half* Vs = Ks + 2 * 64 * 72;         // [2][64][72]

    const int tid = threadIdx.x, wid = tid >> 5, lane = tid & 31;
    const int g = lane >> 2, c4 = lane & 3;
    const int q8 = lane >> 3, r8 = lane & 7;

    const uint32_t sK = cvta_smem(Ks);
    const uint32_t sV = cvta_smem(Vs);

    {
        const __half2 sc2 = __floats2half2_rn(0.125f, 0.125f);
        #pragma unroll
        for (int it = 0; it < 4; it++) {
            int idx = it * 256 + tid;
            int r = idx >> 3, c = (idx & 7) * 8;
            uint4 qv = *(const uint4*)(Qb + (size_t)r * ldq + c);
            __half2* hp = (__half2*)&qv;
            hp[0] = __hmul2(hp[0], sc2);
            hp[1] = __hmul2(hp[1], sc2);
            hp[2] = __hmul2(hp[2], sc2);
            hp[3] = __hmul2(hp[3], sc2);
            *(uint4*)(Qs + r * 72 + c) = qv;
        }
    }

    auto loadKV = [&](int t, int buf) {
        const __half* Ksrc = Kb + (size_t)(t * 64) * ldkv;
        const __half* Vsrc = Vb + (size_t)(t * 64) * ldkv;
        #pragma unroll
        for (int it = 0; it < 2; it++) {
            int idx = it * 256 + tid;
            int r = idx >> 3, c = (idx & 7) * 8;
            cpasync16(sK + (uint32_t)((buf * 64 + r) * 72 + c) * 2, Ksrc + (size_t)r * ldkv + c);
            cpasync16(sV + (uint32_t)((buf * 64 + r) * 72 + c) * 2, Vsrc + (size_t)r * ldkv + c);
        }
    };
    loadKV(0, 0);
    cp_commit();
    cp_wait<0>();
    __syncthreads();

    uint32_t qf[4][4];
    {
        const uint32_t* Qw = (const uint32_t*)(Qs + wid * 16 * 72);
        #pragma unroll
        for (int ks = 0; ks < 4; ks++) {
            qf[ks][0] = Qw[(g    ) * 36 + 8 * ks + c4];
            qf[ks][1] = Qw[(g + 8) * 36 + 8 * ks + c4];
            qf[ks][2] = Qw[(g    ) * 36 + 8 * ks + c4 + 4];
            qf[ks][3] = Qw[(g + 8) * 36 + 8 * ks + c4 + 4];
        }
    }

    float o[8][4];
    #pragma unroll
    for (int j = 0; j < 8; j++)
        #pragma unroll
        for (int r = 0; r < 4; r++) o[j][r] = 0.f;
    float m0 = -1e30f, m1 = -1e30f, l0 = 0.f, l1 = 0.f;

    const int nT = Skv / 64;
    int buf = 0;

    const int rowK = (q8 >> 1) * 8 + r8;
    const int colK = (q8 & 1) * 8;

    for (int t = 0; t < nT; t++) {
        if (t + 1 < nT) loadKV(t + 1, buf ^ 1);
        cp_commit();

        float s[8][4];
        #pragma unroll
        for (int j = 0; j < 8; j++)
            #pragma unroll
            for (int r = 0; r < 4; r++) s[j][r] = 0.f;

        const uint32_t sKb = sK + (uint32_t)(buf * 64 * 72) * 2;
        #pragma unroll
        for (int ks = 0; ks < 4; ks++) {
            #pragma unroll
            for (int p = 0; p < 4; p++) {
                uint32_t b0, b1, b2, b3;
                ldsm_x4(b0, b1, b2, b3,
                        sKb + (uint32_t)((16 * p + rowK) * 72 + colK + ks * 16) * 2);
                uint32_t f0[2] = {b0, b1}, f1[2] = {b2, b3};
                mma_f16(s[2*p],   qf[ks], f0);
                mma_f16(s[2*p+1], qf[ks], f1);
            }
        }

        // online softmax (rows g, g+8); p kept in registers (overwrite s)
        float rm0 = -1e30f, rm1 = -1e30f;
        #pragma unroll
        for (int j = 0; j < 8; j++) {
            rm0 = fmaxf(rm0, fmaxf(s[j][0], s[j][1]));
            rm1 = fmaxf(rm1, fmaxf(s[j][2], s[j][3]));
        }
        rm0 = fmaxf(rm0, __shfl_xor_sync(0xffffffff, rm0, 1));
        rm0 = fmaxf(rm0, __shfl_xor_sync(0xffffffff, rm0, 2));
        rm1 = fmaxf(rm1, __shfl_xor_sync(0xffffffff, rm1, 1));
        rm1 = fmaxf(rm1, __shfl_xor_sync(0xffffffff, rm1, 2));

        float mn0 = fmaxf(m0, rm0), mn1 = fmaxf(m1, rm1);
        float f0 = __expf(m0 - mn0), f1 = __expf(m1 - mn1);
        m0 = mn0; m1 = mn1;

        float sum0 = 0.f, sum1 = 0.f;
        #pragma unroll
        for (int j = 0; j < 8; j++) {
            s[j][0] = __expf(s[j][0] - mn0);
            s[j][1] = __expf(s[j][1] - mn0);
            s[j][2] = __expf(s[j][2] - mn1);
            s[j][3] = __expf(s[j][3] - mn1);
            sum0 += s[j][0] + s[j][1];
            sum1 += s[j][2] + s[j][3];
        }
        sum0 += __shfl_xor_sync(0xffffffff, sum0, 1);
        sum0 += __shfl_xor_sync(0xffffffff, sum0, 2);
        sum1 += __shfl_xor_sync(0xffffffff, sum1, 1);
        sum1 += __shfl_xor_sync(0xffffffff, sum1, 2);
        l0 = l0 * f0 + sum0;
        l1 = l1 * f1 + sum1;

        #pragma unroll
        for (int j = 0; j < 8; j++) {
            o[j][0] *= f0; o[j][1] *= f0;
            o[j][2] *= f1; o[j][3] *= f1;
        }

        // O += P @ V ; A-fragment = packed exp(S) registers (no smem)
        const uint32_t sVb = sV + (uint32_t)(buf * 64 * 72) * 2;
        #pragma unroll
        for (int jk = 0; jk < 4; jk++) {
            uint32_t af[4];
            af[0] = pack_h2(s[2*jk][0],   s[2*jk][1]);
            af[1] = pack_h2(s[2*jk][2],   s[2*jk][3]);
            af[2] = pack_h2(s[2*jk+1][0], s[2*jk+1][1]);
            af[3] = pack_h2(s[2*jk+1][2], s[2*jk+1][3]);
            const uint32_t rowa = sVb + (uint32_t)((16 * jk + (lane & 15)) * 72) * 2;
            #pragma unroll
            for (int j = 0; j < 8; j++) {
                uint32_t b0, b1;
                ldsm_x2_trans(b0, b1, rowa + (uint32_t)(8 * j) * 2);
                uint32_t bfr[2] = {b0, b1};
                mma_f16(o[j], af, bfr);
            }
        }

        cp_wait<0>();
        __syncthreads();
        buf ^= 1;
    }

    float inv0 = 1.0f / l0, inv1 = 1.0f / l1;
    #pragma unroll
    for (int j = 0; j < 8; j++) {
        int col = 8 * j + 2 * c4;
        *(__half2*)(Ob + (size_t)(wid * 16 + g    ) * INNER + col) =
            __floats2half2_rn(o[j][0] * inv0, o[j][1] * inv0);
        *(__half2*)(Ob + (size_t)(wid * 16 + g + 8) * INNER + col) =
            __floats2half2_rn(o[j][2] * inv1, o[j][3] * inv1);
    }
}

// ---------------- fp32 -> fp16 conversion ----------------------------------------
__device__ __forceinline__ uint2 cvt4(float4 t) {
    __half2 lo = __floats2half2_rn(t.x, t.y);
    __half2 hi = __floats2half2_rn(t.z, t.w);
    uint2 o;
    o.x = *(uint32_t*)&lo;
    o.y = *(uint32_t*)&hi;
    return o;
}
__global__ void f32_to_f16_kernel(const float4* __restrict__ in, uint2* __restrict__ out, int n4)
{
    int i = blockIdx.x * blockDim.x + threadIdx.x;
    if (i < n4) out[i] = cvt4(in[i]);
}
__global__ void f32_to_f16_ileave(const float4* __restrict__ gsrc, const float4* __restrict__ usrc,
                                  uint2* __restrict__ out, int n4, int cols4)
{
    int i = blockIdx.x * blockDim.x + threadIdx.x;
    if (i < n4) {
        int r = i / cols4, c = i - r * cols4;
        out[(size_t)(2 * r) * cols4 + c]     = cvt4(gsrc[i]);
        out[(size_t)(2 * r + 1) * cols4 + c] = cvt4(usrc[i]);
    }
}

// ---------------- modulation (fp32) ----------------------------------------------
__global__ void mod_kernel(const float* __restrict__ cond,
                           const float* __restrict__ mw0, const float* __restrict__ mb0,
                           const float* __restrict__ mw1, const float* __restrict__ mb1,
                           const float* __restrict__ mw2, const float* __restrict__ mb2,
                           float* __restrict__ mods)
{
    __shared__ float cs[Bb * Dm];
    for (int i = threadIdx.x; i < Bb * Dm; i += blockDim.x) cs[i] = cond[i];
    __syncthreads();

    int warp = threadIdx.x >> 5, lane = threadIdx.x & 31;
    int j = blockIdx.x * 8 + warp;
    int norm = j / (3*Dm), jj = j - norm * (3*Dm);
    const float* mw = (norm == 0) ? mw0 : (norm == 1) ? mw1 : mw2;
    const float* mb = (norm == 0) ? mb0 : (norm == 1) ? mb1 : mb2;

    float acc[Bb];
    #pragma unroll
    for (int b = 0; b < Bb; b++) acc[b] = 0.f;
    const float* wrow = mw + (size_t)jj * Dm;
    for (int d = lane; d < Dm; d += 32) {
        float w = wrow[d];
        #pragma unroll
        for (int b = 0; b < Bb; b++) acc[b] = fmaf(w, cs[b*Dm + d], acc[b]);
    }
    #pragma unroll
    for (int b = 0; b < Bb; b++)
        #pragma unroll
        for (int off = 16; off > 0; off >>= 1)
            acc[b] += __shfl_xor_sync(0xffffffff, acc[b], off);
    if (lane < Bb)
        mods[(size_t)norm * Bb * 3*Dm + lane * 3*Dm + jj] = acc[lane] + mb[jj];
}

// ---------------- adaRMS norm (fp16 output) --------------------------------------
__global__ void rmsnorm_kernel(const float* __restrict__ x, const float* __restrict__ w,
                               const float* __restrict__ mod_base,
                               __half* __restrict__ out)
{
    int row = blockIdx.x;
    int b   = row / Nn;
    const float* xr = x + (size_t)row * Dm;
    const float* ms = mod_base + b * 3*Dm;

    float ss = 0.f;
    for (int i = threadIdx.x; i < Dm; i += blockDim.x) { float t = xr[i]; ss = fmaf(t,t,ss); }
    #pragma unroll
    for (int off = 16; off > 0; off >>= 1) ss += __shfl_xor_sync(0xffffffff, ss, off);
    __shared__ float red[8];
    if ((threadIdx.x & 31) == 0) red[threadIdx.x >> 5] = ss;
    __syncthreads();
    if (threadIdx.x < 8) {
        float v = red[threadIdx.x];
        #pragma unroll
        for (int off = 4; off > 0; off >>= 1) v += __shfl_xor_sync(0xff, v, off);
        if (threadIdx.x == 0) red[0] = v;
    }
    __syncthreads();
    float rn = rsqrtf(red[0] * (1.0f/Dm) + EPSf);

    __half* orow = out + (size_t)row * Dm;
    for (int i = threadIdx.x; i < Dm/2; i += blockDim.x) {
        int i2 = 2 * i;
        float a = xr[i2]   * rn * w[i2]   * (1.0f + ms[i2])   + ms[Dm + i2];
        float c = xr[i2+1] * rn * w[i2+1] * (1.0f + ms[i2+1]) + ms[Dm + i2+1];
        *(__half2*)(orow + i2) = __floats2half2_rn(a, c);
    }
}

// ---------------- host orchestration -------------------------------------------
static void* symv(const void* s) { void* p = nullptr; cudaGetSymbolAddress(&p, s); return p; }

template<int EPI,int OH>
static void gemm_h(cudaStream_t st, const __half* A, const __half* W, void* C,
                   int M, int N, int K,
                   const float* resid, const float* gate, int gate_ld, int rpb)
{
    size_t sm = (size_t)4 * (128 + 256) * 72 * sizeof(__half);   // 221184
    cudaFuncSetAttribute(gemm_f16<EPI,OH>,
                         cudaFuncAttributeMaxDynamicSharedMemorySize, (int)sm);
    gemm_f16<EPI,OH><<<dim3(N/256, M/128), 512, sm, st>>>(
        A, W, C, K, K, K, N, resid, gate, gate_ld, rpb);
}

static void cvt_to(cudaStream_t st, __half* dst, const float* src, int n)
{
    f32_to_f16_kernel<<<(n/4 + 255)/256, 256, 0, st>>>((const float4*)src, (uint2*)dst, n/4);
}

static void launch_flash(const __half* q, const __half* k, const __half* v, __half* o,
                         int Skv, int ldq, int ldkv)
{
    size_t sm = (size_t)(128*72 + 2*64*72 + 2*64*72) * sizeof(__half);  // 55296
    cudaFuncSetAttribute(flash_kernel, cudaFuncAttributeMaxDynamicSharedMemorySize, (int)sm);
    flash_kernel<<<dim3(Nn/128, Hh, Bb), 256, sm>>>(q, k, v, o, Skv, ldq, ldkv);
}

extern "C" void kernel_launch(void* const* d_in, const int* in_sizes, int n_in,
                              void* d_out, int out_size)
{
    const float* x       = (const float*)d_in[0];
    const float* context = (const float*)d_in[1];
    const float* cond    = (const float*)d_in[2];
    const float* n1_w  = (const float*)d_in[3];
    const float* n1_mw = (const float*)d_in[4];
    const float* n1_mb = (const float*)d_in[5];
    const float* n2_w  = (const float*)d_in[6];
    const float* n2_mw = (const float*)d_in[7];
    const float* n2_mb = (const float*)d_in[8];
    const float* n3_w  = (const float*)d_in[9];
    const float* n3_mw = (const float*)d_in[10];
    const float* n3_mb = (const float*)d_in[11];
    const float* sa_q  = (const float*)d_in[12];
    const float* sa_k  = (const float*)d_in[13];
    const float* sa_v  = (const float*)d_in[14];
    const float* sa_o  = (const float*)d_in[15];
    const float* ca_q  = (const float*)d_in[16];
    const float* ca_k  = (const float*)d_in[17];
    const float* ca_v  = (const float*)d_in[18];
    const float* ca_o  = (const float*)d_in[19];
    const float* ff_gate = (const float*)d_in[20];
    const float* ff_up   = (const float*)d_in[21];
    const float* ff_down = (const float*)d_in[22];
    float* out = (float*)d_out;

    float*  mods   = (float*)symv(d_mods);
    __half* normed = (__half*)symv(d_normed);
    __half* qkv    = (__half*)symv(d_qkv);
    __half* kv     = (__half*)symv(d_kv);
    __half* ao     = (__half*)symv(d_attno);
    float*  x1     = (float*)symv(d_x1);
    float*  x2     = (float*)symv(d_x2);
    __half* hb     = (__half*)symv(d_hbuf);
    __half* ctx    = (__half*)symv(d_ctx);
    __half* wr     = (__half*)symv(d_wrnd);

    const int MQ = Bb * Nn;

    // side streams + events, created once (resources only; per-call work identical)
    static cudaStream_t s2 = nullptr, s3 = nullptr;
    static cudaEvent_t evFork = nullptr, evKV = nullptr, evW3 = nullptr;
    if (s2 == nullptr) {
        cudaStreamCreateWithFlags(&s2, cudaStreamNonBlocking);
        cudaStreamCreateWithFlags(&s3, cudaStreamNonBlocking);
        cudaEventCreateWithFlags(&evFork, cudaEventDisableTiming);
        cudaEventCreateWithFlags(&evKV, cudaEventDisableTiming);
        cudaEventCreateWithFlags(&evW3, cudaEventDisableTiming);
    }

    // ---- fork ----
    cudaEventRecord(evFork, 0);
    cudaStreamWaitEvent(s2, evFork, 0);
    cudaStreamWaitEvent(s3, evFork, 0);

    // s2: CA K/V branch (converts + the big KV GEMM)
    cvt_to(s2, wr + W_CAK,             ca_k, INNER*Cm);
    cvt_to(s2, wr + W_CAK + 2048*1024, ca_v, INNER*Cm);
    cvt_to(s2, ctx, context, Bb*Ss*Cm);
    gemm_h<0,1>(s2, ctx, wr + W_CAK, kv, Bb*Ss, 2*INNER, Cm, nullptr, nullptr, 0, 1);
    cudaEventRecord(evKV, s2);

    // s3: non-critical weight converts (needed from SA O-proj onward)
    cvt_to(s3, wr + W_SAO, sa_o, Dm*INNER);
    cvt_to(s3, wr + W_CAQ, ca_q, INNER*Dm);
    cvt_to(s3, wr + W_CAO, ca_o, Dm*INNER);
    f32_to_f16_ileave<<<(MLPm*Dm/4 + 255)/256, 256, 0, s3>>>(
        (const float4*)ff_gate, (const float4*)ff_up,
        (uint2*)(wr + W_FFGU), MLPm*Dm/4, Dm/4);
    cvt_to(s3, wr + W_FFD, ff_down, Dm*MLPm);
    cudaEventRecord(evW3, s3);

    // main stream: minimal prefix
    cvt_to(0, wr + W_SAQ,             sa_q, INNER*Dm);
    cvt_to(0, wr + W_SAQ + 1024*1024, sa_k, INNER*Dm);
    cvt_to(0, wr + W_SAQ + 2048*1024, sa_v, INNER*Dm);
    mod_kernel<<<(3*3*Dm)/8, 256>>>(cond, n1_mw, n1_mb, n2_mw, n2_mb, n3_mw, n3_mb, mods);

    // ===================== Self attention =====================
    rmsnorm_kernel<<<MQ, 256>>>(x, n1_w, mods + 0*Bb*3*Dm, normed);
    gemm_h<0,1>(0, normed, wr + W_SAQ, qkv, MQ, 3*INNER, Dm, nullptr, nullptr, 0, 1);
    launch_flash(qkv, qkv + INNER, qkv + 2*INNER, ao, Nn, 3*INNER, 3*INNER);
    cudaStreamWaitEvent(0, evW3, 0);     // join: s3 weight converts ready
    gemm_h<1,0>(0, ao, wr + W_SAO, x1, MQ, Dm, INNER, x, mods + 0*Bb*3*Dm + 2*Dm, 3*Dm, Nn);

    // ===================== Cross attention =====================
    rmsnorm_kernel<<<MQ, 256>>>(x1, n2_w, mods + 1*Bb*3*Dm, normed);
    gemm_h<0,1>(0, normed, wr + W_CAQ, qkv, MQ, INNER, Dm, nullptr, nullptr, 0, 1);
    cudaStreamWaitEvent(0, evKV, 0);     // join: kv ready
    launch_flash(qkv, kv, kv + INNER, ao, Ss, INNER, 2*INNER);
    gemm_h<1,0>(0, ao, wr + W_CAO, x2, MQ, Dm, INNER, x1, mods + 1*Bb*3*Dm + 2*Dm, 3*Dm, Nn);

    // ===================== FFN =====================
    rmsnorm_kernel<<<MQ, 256>>>(x2, n3_w, mods + 2*Bb*3*Dm, normed);
    gemm_h<0,2>(0, normed, wr + W_FFGU, hb, MQ, 2*MLPm, Dm, nullptr, nullptr, 0, 1);
    gemm_h<1,0>(0, hb, wr + W_FFD, out, MQ, Dm, MLPm, x2, mods + 2*Bb*3*Dm + 2*Dm, 3*Dm, Nn);
}

// round 12
// speedup vs baseline: 8.9904x; 1.0226x over previous
#include <cuda_runtime.h>
#include <cuda_fp16.h>
#include <math.h>
#include <stdint.h>

// Problem dims
#define Dm    1024
#define Cm    2048
#define MLPm  4096
#define Hh    16
#define HDh   64
#define Bb    8
#define Nn    512
#define Ss    2048
#define INNER (Hh*HDh)   // 1024
#define EPSf  1e-6f

// ---------------- scratch (static device allocations) ---------------------------
__device__ __align__(16) float  d_mods  [3 * Bb * 3 * Dm];
__device__ __align__(16) __half d_normed[Bb * Nn * Dm];
__device__ __align__(16) __half d_qkv   [Bb * Nn * 3 * INNER];
__device__ __align__(16) __half d_kv    [(size_t)Bb * Ss * 2 * INNER];
__device__ __align__(16) __half d_attno [Bb * Nn * INNER];
__device__ __align__(16) float  d_x1    [Bb * Nn * Dm];
__device__ __align__(16) float  d_x2    [Bb * Nn * Dm];
__device__ __align__(16) __half d_hbuf  [Bb * Nn * MLPm];
__device__ __align__(16) __half d_ctx   [(size_t)Bb * Ss * Cm];
__device__ __align__(16) __half d_wrnd  [22 * 1024 * 1024];

// weight offsets (elements); adjacency is load-bearing for fused GEMMs:
// [SAQ|SAK|SAV] 3072x1024, [CAK|CAV] 2048x2048, FFGU interleaved 8192x1024
#define W_SAQ  (0)
#define W_SAO  (3*1024*1024)
#define W_CAQ  (4*1024*1024)
#define W_CAK  (5*1024*1024)
#define W_CAO  (9*1024*1024)
#define W_FFGU (10*1024*1024)
#define W_FFD  (18*1024*1024)

// ---------------- helpers ---------------------------------------------------------
__device__ __forceinline__ void mma_f16(float* c, const uint32_t* a, const uint32_t* b) {
    asm volatile(
        "mma.sync.aligned.m16n8k16.row.col.f32.f16.f16.f32 "
        "{%0,%1,%2,%3}, {%4,%5,%6,%7}, {%8,%9}, {%0,%1,%2,%3};\n"
        : "+f"(c[0]), "+f"(c[1]), "+f"(c[2]), "+f"(c[3])
        : "r"(a[0]), "r"(a[1]), "r"(a[2]), "r"(a[3]), "r"(b[0]), "r"(b[1]));
}

__device__ __forceinline__ void cpasync16(uint32_t saddr, const void* gptr) {
    asm volatile("cp.async.cg.shared.global [%0], [%1], 16;\n" :: "r"(saddr), "l"(gptr));
}
__device__ __forceinline__ void cp_commit() { asm volatile("cp.async.commit_group;\n"); }
template<int n> __device__ __forceinline__ void cp_wait() {
    asm volatile("cp.async.wait_group %0;\n" :: "n"(n));
}
__device__ __forceinline__ uint32_t cvta_smem(const void* p) {
    uint32_t a;
    asm("{ .reg .u64 t; cvta.to.shared.u64 t, %1; cvt.u32.u64 %0, t; }" : "=r"(a) : "l"(p));
    return a;
}
__device__ __forceinline__ void ldsm_x4(uint32_t& r0, uint32_t& r1, uint32_t& r2, uint32_t& r3,
                                        uint32_t addr) {
    asm volatile("ldmatrix.sync.aligned.m8n8.x4.shared.b16 {%0,%1,%2,%3}, [%4];"
                 : "=r"(r0), "=r"(r1), "=r"(r2), "=r"(r3) : "r"(addr));
}
__device__ __forceinline__ void ldsm_x4_trans(uint32_t& r0, uint32_t& r1, uint32_t& r2, uint32_t& r3,
                                              uint32_t addr) {
    asm volatile("ldmatrix.sync.aligned.m8n8.x4.trans.shared.b16 {%0,%1,%2,%3}, [%4];"
                 : "=r"(r0), "=r"(r1), "=r"(r2), "=r"(r3) : "r"(addr));
}
__device__ __forceinline__ uint32_t pack_h2(float a, float b) {
    __half2 h = __floats2half2_rn(a, b);
    return *(uint32_t*)&h;
}

// ---------------- fp16 NT GEMM: C(M,N) = A(M,K) @ B(N,K)^T ----------------------
// 128x128 CTA tile, 128 threads (4 warps in 2x2, warp tile 64x64), BK=64,
// row pad 72 halves, 3-stage cp.async ring, ldmatrix fragment loads, 2 CTAs/SM.
// A/B smem re-read factor is 2x each (vs 8x with thin warp tiles).
// EPI==1: add resid + gate[(row/rows_per_b)*gate_ld+col]*acc (float out)
// OH: 0 = float out, 1 = half out, 2 = silu-pair: h[row][col/2] = silu(even)*odd
template<int EPI,int OH>
__global__ void __launch_bounds__(128, 2)
gemm_f16(const __half* __restrict__ A, const __half* __restrict__ Bg, void* __restrict__ Cv,
         int K, int lda, int ldb, int ldc,
         const float* __restrict__ resid, const float* __restrict__ gate,
         int gate_ld, int rows_per_b)
{
    constexpr int BM = 128, BN = 128, BK = 64, LDH = 72, ST = 3;

    extern __shared__ __half hsm[];
    __half* As = hsm;                    // ST * BM * LDH
    __half* Bs = hsm + ST * BM * LDH;    // ST * BN * LDH

    const int tid = threadIdx.x, wid = tid >> 5, lane = tid & 31;
    const int g = lane >> 2, c4 = lane & 3;
    const int q8 = lane >> 3, r8 = lane & 7;
    const int wm = wid & 1, wn = wid >> 1;          // 2x2 warp grid
    const int row0 = blockIdx.y * BM, col0 = blockIdx.x * BN;

    const __half* Arow = A  + (size_t)row0 * lda;
    const __half* Brow = Bg + (size_t)col0 * ldb;

    const uint32_t sA = cvta_smem(As);
    const uint32_t sB = cvta_smem(Bs);
    const int ldRow = tid >> 3;          // 0..15
    const int ldCol = (tid & 7) * 8;     // halves (16B)

    // ldmatrix lane offsets
    const int rowA = wm * 64 + (q8 & 1) * 8 + r8;   // + 16*i
    const int colA = (q8 >> 1) * 8;                 // + 16*ks
    const int rowB = wn * 64 + (q8 >> 1) * 8 + r8;  // + 16*p
    const int colB = (q8 & 1) * 8;                  // + 16*ks

    auto load_tile = [&](int t) {
        const int st = t % ST;
        const int kt = t * BK;
        #pragma unroll
        for (int i = 0; i < 8; i++) {
            int r = i * 16 + ldRow;
            cpasync16(sA + (uint32_t)((st * BM + r) * LDH + ldCol) * 2,
                      Arow + (size_t)r * lda + kt + ldCol);
        }
        #pragma unroll
        for (int i = 0; i < 8; i++) {
            int r = i * 16 + ldRow;
            cpasync16(sB + (uint32_t)((st * BN + r) * LDH + ldCol) * 2,
                      Brow + (size_t)r * ldb + kt + ldCol);
        }
    };

    const int nT = K / BK;
    load_tile(0); cp_commit();
    load_tile(1); cp_commit();
    cp_wait<1>();
    __syncthreads();

    float acc[4][8][4];
    #pragma unroll
    for (int i = 0; i < 4; i++)
        #pragma unroll
        for (int j = 0; j < 8; j++)
            #pragma unroll
            for (int r = 0; r < 4; r++) acc[i][j][r] = 0.f;

    for (int t = 0; t < nT; t++) {
        const uint32_t aBase = sA + (uint32_t)((t % ST) * BM * LDH) * 2;
        const uint32_t bBase = sB + (uint32_t)((t % ST) * BN * LDH) * 2;

        #pragma unroll
        for (int ks = 0; ks < 4; ks++) {
            uint32_t af[4][4], bf[8][2];
            #pragma unroll
            for (int i = 0; i < 4; i++)
                ldsm_x4(af[i][0], af[i][1], af[i][2], af[i][3],
                        aBase + (uint32_t)((rowA + 16 * i) * LDH + colA + ks * 16) * 2);
            #pragma unroll
            for (int p = 0; p < 4; p++) {
                uint32_t b0, b1, b2, b3;
                ldsm_x4(b0, b1, b2, b3,
                        bBase + (uint32_t)((rowB + 16 * p) * LDH + colB + ks * 16) * 2);
                bf[2*p][0] = b0; bf[2*p][1] = b1;
                bf[2*p+1][0] = b2; bf[2*p+1][1] = b3;
            }
            #pragma unroll
            for (int i = 0; i < 4; i++)
                #pragma unroll
                for (int j = 0; j < 8; j++)
                    mma_f16(acc[i][j], af[i], bf[j]);
        }

        if (t + 2 < nT) load_tile(t + 2);
        cp_commit();
        cp_wait<1>();
        __syncthreads();
    }

    #pragma unroll
    for (int i = 0; i < 4; i++) {
        #pragma unroll
        for (int j = 0; j < 8; j++) {
            int col = col0 + wn * 64 + 8 * j + 2 * c4;
            #pragma unroll
            for (int h = 0; h < 2; h++) {
                int row = row0 + wm * 64 + 16 * i + g + 8 * h;
                float v0 = acc[i][j][2 * h + 0];
                float v1 = acc[i][j][2 * h + 1];
                if (EPI == 1) {
                    const float* rr = resid + (size_t)row * ldc + col;
                    const float* gg = gate + (size_t)(row / rows_per_b) * gate_ld + col;
                    v0 = rr[0] + gg[0] * v0;
                    v1 = rr[1] + gg[1] * v1;
                }
                if (OH == 1) {
                    *(__half2*)((__half*)Cv + (size_t)row * ldc + col) =
                        __floats2half2_rn(v0, v1);
                } else if (OH == 0) {
                    *(float2*)((float*)Cv + (size_t)row * ldc + col) = make_float2(v0, v1);
                } else {
                    float sv = (v0 / (1.0f + __expf(-v0))) * v1;
                    ((__half*)Cv)[(size_t)row * (ldc >> 1) + (col >> 1)] = __float2half_rn(sv);
                }
            }
        }
    }
}

// ---------------- fused flash attention (fp16 mma, register-resident P) ----------
__global__ void __launch_bounds__(256, 2)
flash_kernel(const __half* __restrict__ Qg, const __half* __restrict__ Kg,
             const __half* __restrict__ Vg, __half* __restrict__ Og,
             int Skv, int ldq, int ldkv)
{
    const int h = blockIdx.y, b = blockIdx.z;
    const int n0 = blockIdx.x * 128;
    const __half* Qb = Qg + (size_t)b * Nn * ldq + (size_t)n0 * ldq + h * HDh;
    const __half* Kb = Kg + (size_t)b * Skv * ldkv + h * HDh;
    const __half* Vb = Vg + (size_t)b * Skv * ldkv + h * HDh;
    __half* Ob = Og + (size_t)b * Nn * INNER + (size_t)n0 * INNER + h * HDh;

    extern __shared__ __half fsm[];
    __half* Qs = fsm;                      // [128][72]
    __half* Ks = Qs + 128 * 72;            // [2][64][72]
    __half* Vs = Ks + 2 * 64 * 72;         // [2][64][72]

    const int tid = threadIdx.x, wid = tid >> 5, lane = tid & 31;
    const int g = lane >> 2, c4 = lane & 3;
    const int q8 = lane >> 3, r8 = lane & 7;

    const uint32_t sK = cvta_smem(Ks);
    const uint32_t sV = cvta_smem(Vs);

    {
        const __half2 sc2 = __floats2half2_rn(0.125f, 0.125f);
        #pragma unroll
        for (int it = 0; it < 4; it++) {
            int idx = it * 256 + tid;
            int r = idx >> 3, c = (idx & 7) * 8;
            uint4 qv = *(const uint4*)(Qb + (size_t)r * ldq + c);
            __half2* hp = (__half2*)&qv;
            hp[0] = __hmul2(hp[0], sc2);
            hp[1] = __hmul2(hp[1], sc2);
            hp[2] = __hmul2(hp[2], sc2);
            hp[3] = __hmul2(hp[3], sc2);
            *(uint4*)(Qs + r * 72 + c) = qv;
        }
    }

    auto loadKV = [&](int t, int buf) {
        const __half* Ksrc = Kb + (size_t)(t * 64) * ldkv;
        const __half* Vsrc = Vb + (size_t)(t * 64) * ldkv;
        #pragma unroll
        for (int it = 0; it < 2; it++) {
            int idx = it * 256 + tid;
            int r = idx >> 3, c = (idx & 7) * 8;
            cpasync16(sK + (uint32_t)((buf * 64 + r) * 72 + c) * 2, Ksrc + (size_t)r * ldkv + c);
            cpasync16(sV + (uint32_t)((buf * 64 + r) * 72 + c) * 2, Vsrc + (size_t)r * ldkv + c);
        }
    };
    loadKV(0, 0);
    cp_commit();
    cp_wait<0>();
    __syncthreads();

    uint32_t qf[4][4];
    {
        const uint32_t* Qw = (const uint32_t*)(Qs + wid * 16 * 72);
        #pragma unroll
        for (int ks = 0; ks < 4; ks++) {
            qf[ks][0] = Qw[(g    ) * 36 + 8 * ks + c4];
            qf[ks][1] = Qw[(g + 8) * 36 + 8 * ks + c4];
            qf[ks][2] = Qw[(g    ) * 36 + 8 * ks + c4 + 4];
            qf[ks][3] = Qw[(g + 8) * 36 + 8 * ks + c4 + 4];
        }
    }

    float o[8][4];
    #pragma unroll
    for (int j = 0; j < 8; j++)
        #pragma unroll
        for (int r = 0; r < 4; r++) o[j][r] = 0.f;
    float m0 = -1e30f, m1 = -1e30f, l0 = 0.f, l1 = 0.f;

    const int nT = Skv / 64;
    int buf = 0;

    const int rowK = (q8 >> 1) * 8 + r8;
    const int colK = (q8 & 1) * 8;
    // PV x4.trans lane offsets: lanes 0-15 -> col 16j', 16-31 -> col 16j'+8
    const int rowV = lane & 15;             // + 16*jk
    const int colV = (lane >> 4) * 8;       // + 16*j'

    for (int t = 0; t < nT; t++) {
        if (t + 1 < nT) loadKV(t + 1, buf ^ 1);
        cp_commit();

        float s[8][4];
        #pragma unroll
        for (int j = 0; j < 8; j++)
            #pragma unroll
            for (int r = 0; r < 4; r++) s[j][r] = 0.f;

        const uint32_t sKb = sK + (uint32_t)(buf * 64 * 72) * 2;
        #pragma unroll
        for (int ks = 0; ks < 4; ks++) {
            #pragma unroll
            for (int p = 0; p < 4; p++) {
                uint32_t b0, b1, b2, b3;
                ldsm_x4(b0, b1, b2, b3,
                        sKb + (uint32_t)((16 * p + rowK) * 72 + colK + ks * 16) * 2);
                uint32_t f0[2] = {b0, b1}, f1[2] = {b2, b3};
                mma_f16(s[2*p],   qf[ks], f0);
                mma_f16(s[2*p+1], qf[ks], f1);
            }
        }

        float rm0 = -1e30f, rm1 = -1e30f;
        #pragma unroll
        for (int j = 0; j < 8; j++) {
            rm0 = fmaxf(rm0, fmaxf(s[j][0], s[j][1]));
            rm1 = fmaxf(rm1, fmaxf(s[j][2], s[j][3]));
        }
        rm0 = fmaxf(rm0, __shfl_xor_sync(0xffffffff, rm0, 1));
        rm0 = fmaxf(rm0, __shfl_xor_sync(0xffffffff, rm0, 2));
        rm1 = fmaxf(rm1, __shfl_xor_sync(0xffffffff, rm1, 1));
        rm1 = fmaxf(rm1, __shfl_xor_sync(0xffffffff, rm1, 2));

        float mn0 = fmaxf(m0, rm0), mn1 = fmaxf(m1, rm1);
        float f0 = __expf(m0 - mn0), f1 = __expf(m1 - mn1);
        m0 = mn0; m1 = mn1;

        float sum0 = 0.f, sum1 = 0.f;
        #pragma unroll
        for (int j = 0; j < 8; j++) {
            s[j][0] = __expf(s[j][0] - mn0);
            s[j][1] = __expf(s[j][1] - mn0);
            s[j][2] = __expf(s[j][2] - mn1);
            s[j][3] = __expf(s[j][3] - mn1);
            sum0 += s[j][0] + s[j][1];
            sum1 += s[j][2] + s[j][3];
        }
        sum0 += __shfl_xor_sync(0xffffffff, sum0, 1);
        sum0 += __shfl_xor_sync(0xffffffff, sum0, 2);
        sum1 += __shfl_xor_sync(0xffffffff, sum1, 1);
        sum1 += __shfl_xor_sync(0xffffffff, sum1, 2);
        l0 = l0 * f0 + sum0;
        l1 = l1 * f1 + sum1;

        #pragma unroll
        for (int j = 0; j < 8; j++) {
            o[j][0] *= f0; o[j][1] *= f0;
            o[j][2] *= f1; o[j][3] *= f1;
        }

        // O += P @ V ; A-fragment = packed exp(S) registers, B via x4.trans (2 j's)
        const uint32_t sVb = sV + (uint32_t)(buf * 64 * 72) * 2;
        #pragma unroll
        for (int jk = 0; jk < 4; jk++) {
            uint32_t af[4];
            af[0] = pack_h2(s[2*jk][0],   s[2*jk][1]);
            af[1] = pack_h2(s[2*jk][2],   s[2*jk][3]);
            af[2] = pack_h2(s[2*jk+1][0], s[2*jk+1][1]);
            af[3] = pack_h2(s[2*jk+1][2], s[2*jk+1][3]);
            const uint32_t base = sVb + (uint32_t)((16 * jk + rowV) * 72 + colV) * 2;
            #pragma unroll
            for (int jp = 0; jp < 4; jp++) {
                uint32_t b0, b1, b2, b3;
                ldsm_x4_trans(b0, b1, b2, b3, base + (uint32_t)(16 * jp) * 2);
                uint32_t f0[2] = {b0, b1}, f1[2] = {b2, b3};
                mma_f16(o[2*jp],   af, f0);
                mma_f16(o[2*jp+1], af, f1);
            }
        }

        cp_wait<0>();
        __syncthreads();
        buf ^= 1;
    }

    float inv0 = 1.0f / l0, inv1 = 1.0f / l1;
    #pragma unroll
    for (int j = 0; j < 8; j++) {
        int col = 8 * j + 2 * c4;
        *(__half2*)(Ob + (size_t)(wid * 16 + g    ) * INNER + col) =
            __floats2half2_rn(o[j][0] * inv0, o[j][1] * inv0);
        *(__half2*)(Ob + (size_t)(wid * 16 + g + 8) * INNER + col) =
            __floats2half2_rn(o[j][2] * inv1, o[j][3] * inv1);
    }
}

// ---------------- fp32 -> fp16 conversion ----------------------------------------
__device__ __forceinline__ uint2 cvt4(float4 t) {
    __half2 lo = __floats2half2_rn(t.x, t.y);
    __half2 hi = __floats2half2_rn(t.z, t.w);
    uint2 o;
    o.x = *(uint32_t*)&lo;
    o.y = *(uint32_t*)&hi;
    return o;
}
__global__ void f32_to_f16_kernel(const float4* __restrict__ in, uint2* __restrict__ out, int n4)
{
    int i = blockIdx.x * blockDim.x + threadIdx.x;
    if (i < n4) out[i] = cvt4(in[i]);
}
__global__ void f32_to_f16_ileave(const float4* __restrict__ gsrc, const float4* __restrict__ usrc,
                                  uint2* __restrict__ out, int n4, int cols4)
{
    int i = blockIdx.x * blockDim.x + threadIdx.x;
    if (i < n4) {
        int r = i / cols4, c = i - r * cols4;
        out[(size_t)(2 * r) * cols4 + c]     = cvt4(gsrc[i]);
        out[(size_t)(2 * r + 1) * cols4 + c] = cvt4(usrc[i]);
    }
}

// ---------------- modulation (fp32) ----------------------------------------------
__global__ void mod_kernel(const float* __restrict__ cond,
                           const float* __restrict__ mw0, const float* __restrict__ mb0,
                           const float* __restrict__ mw1, const float* __restrict__ mb1,
                           const float* __restrict__ mw2, const float* __restrict__ mb2,
                           float* __restrict__ mods)
{
    __shared__ float cs[Bb * Dm];
    for (int i = threadIdx.x; i < Bb * Dm; i += blockDim.x) cs[i] = cond[i];
    __syncthreads();

    int warp = threadIdx.x >> 5, lane = threadIdx.x & 31;
    int j = blockIdx.x * 8 + warp;
    int norm = j / (3*Dm), jj = j - norm * (3*Dm);
    const float* mw = (norm == 0) ? mw0 : (norm == 1) ? mw1 : mw2;
    const float* mb = (norm == 0) ? mb0 : (norm == 1) ? mb1 : mb2;

    float acc[Bb];
    #pragma unroll
    for (int b = 0; b < Bb; b++) acc[b] = 0.f;
    const float* wrow = mw + (size_t)jj * Dm;
    for (int d = lane; d < Dm; d += 32) {
        float w = wrow[d];
        #pragma unroll
        for (int b = 0; b < Bb; b++) acc[b] = fmaf(w, cs[b*Dm + d], acc[b]);
    }
    #pragma unroll
    for (int b = 0; b < Bb; b++)
        #pragma unroll
        for (int off = 16; off > 0; off >>= 1)
            acc[b] += __shfl_xor_sync(0xffffffff, acc[b], off);
    if (lane < Bb)
        mods[(size_t)norm * Bb * 3*Dm + lane * 3*Dm + jj] = acc[lane] + mb[jj];
}

// ---------------- adaRMS norm (fp16 output) --------------------------------------
__global__ void rmsnorm_kernel(const float* __restrict__ x, const float* __restrict__ w,
                               const float* __restrict__ mod_base,
                               __half* __restrict__ out)
{
    int row = blockIdx.x;
    int b   = row / Nn;
    const float* xr = x + (size_t)row * Dm;
    const float* ms = mod_base + b * 3*Dm;

    float ss = 0.f;
    for (int i = threadIdx.x; i < Dm; i += blockDim.x) { float t = xr[i]; ss = fmaf(t,t,ss); }
    #pragma unroll
    for (int off = 16; off > 0; off >>= 1) ss += __shfl_xor_sync(0xffffffff, ss, off);
    __shared__ float red[8];
    if ((threadIdx.x & 31) == 0) red[threadIdx.x >> 5] = ss;
    __syncthreads();
    if (threadIdx.x < 8) {
        float v = red[threadIdx.x];
        #pragma unroll
        for (int off = 4; off > 0; off >>= 1) v += __shfl_xor_sync(0xff, v, off);
        if (threadIdx.x == 0) red[0] = v;
    }
    __syncthreads();
    float rn = rsqrtf(red[0] * (1.0f/Dm) + EPSf);

    __half* orow = out + (size_t)row * Dm;
    for (int i = threadIdx.x; i < Dm/2; i += blockDim.x) {
        int i2 = 2 * i;
        float a = xr[i2]   * rn * w[i2]   * (1.0f + ms[i2])   + ms[Dm + i2];
        float c = xr[i2+1] * rn * w[i2+1] * (1.0f + ms[i2+1]) + ms[Dm + i2+1];
        *(__half2*)(orow + i2) = __floats2half2_rn(a, c);
    }
}

// ---------------- host orchestration -------------------------------------------
static void* symv(const void* s) { void* p = nullptr; cudaGetSymbolAddress(&p, s); return p; }

template<int EPI,int OH>
static void gemm_h(cudaStream_t st, const __half* A, const __half* W, void* C,
                   int M, int N, int K,
                   const float* resid, const float* gate, int gate_ld, int rpb)
{
    size_t sm = (size_t)3 * (128 + 128) * 72 * sizeof(__half);   // 110592
    cudaFuncSetAttribute(gemm_f16<EPI,OH>,
                         cudaFuncAttributeMaxDynamicSharedMemorySize, (int)sm);
    gemm_f16<EPI,OH><<<dim3(N/128, M/128), 128, sm, st>>>(
        A, W, C, K, K, K, N, resid, gate, gate_ld, rpb);
}

static void cvt_to(cudaStream_t st, __half* dst, const float* src, int n)
{
    f32_to_f16_kernel<<<(n/4 + 255)/256, 256, 0, st>>>((const float4*)src, (uint2*)dst, n/4);
}

static void launch_flash(const __half* q, const __half* k, const __half* v, __half* o,
                         int Skv, int ldq, int ldkv)
{
    size_t sm = (size_t)(128*72 + 2*64*72 + 2*64*72) * sizeof(__half);  // 55296
    cudaFuncSetAttribute(flash_kernel, cudaFuncAttributeMaxDynamicSharedMemorySize, (int)sm);
    flash_kernel<<<dim3(Nn/128, Hh, Bb), 256, sm>>>(q, k, v, o, Skv, ldq, ldkv);
}

extern "C" void kernel_launch(void* const* d_in, const int* in_sizes, int n_in,
                              void* d_out, int out_size)
{
    const float* x       = (const float*)d_in[0];
    const float* context = (const float*)d_in[1];
    const float* cond    = (const float*)d_in[2];
    const float* n1_w  = (const float*)d_in[3];
    const float* n1_mw = (const float*)d_in[4];
    const float* n1_mb = (const float*)d_in[5];
    const float* n2_w  = (const float*)d_in[6];
    const float* n2_mw = (const float*)d_in[7];
    const float* n2_mb = (const float*)d_in[8];
    const float* n3_w  = (const float*)d_in[9];
    const float* n3_mw = (const float*)d_in[10];
    const float* n3_mb = (const float*)d_in[11];
    const float* sa_q  = (const float*)d_in[12];
    const float* sa_k  = (const float*)d_in[13];
    const float* sa_v  = (const float*)d_in[14];
    const float* sa_o  = (const float*)d_in[15];
    const float* ca_q  = (const float*)d_in[16];
    const float* ca_k  = (const float*)d_in[17];
    const float* ca_v  = (const float*)d_in[18];
    const float* ca_o  = (const float*)d_in[19];
    const float* ff_gate = (const float*)d_in[20];
    const float* ff_up   = (const float*)d_in[21];
    const float* ff_down = (const float*)d_in[22];
    float* out = (float*)d_out;

    float*  mods   = (float*)symv(d_mods);
    __half* normed = (__half*)symv(d_normed);
    __half* qkv    = (__half*)symv(d_qkv);
    __half* kv     = (__half*)symv(d_kv);
    __half* ao     = (__half*)symv(d_attno);
    float*  x1     = (float*)symv(d_x1);
    float*  x2     = (float*)symv(d_x2);
    __half* hb     = (__half*)symv(d_hbuf);
    __half* ctx    = (__half*)symv(d_ctx);
    __half* wr     = (__half*)symv(d_wrnd);

    const int MQ = Bb * Nn;

    static cudaStream_t s2 = nullptr, s3 = nullptr;
    static cudaEvent_t evFork = nullptr, evKV = nullptr, evW3 = nullptr;
    if (s2 == nullptr) {
        cudaStreamCreateWithFlags(&s2, cudaStreamNonBlocking);
        cudaStreamCreateWithFlags(&s3, cudaStreamNonBlocking);
        cudaEventCreateWithFlags(&evFork, cudaEventDisableTiming);
        cudaEventCreateWithFlags(&evKV, cudaEventDisableTiming);
        cudaEventCreateWithFlags(&evW3, cudaEventDisableTiming);
    }

    // ---- fork ----
    cudaEventRecord(evFork, 0);
    cudaStreamWaitEvent(s2, evFork, 0);
    cudaStreamWaitEvent(s3, evFork, 0);

    // s2: CA K/V branch (converts + the big KV GEMM)
    cvt_to(s2, wr + W_CAK,             ca_k, INNER*Cm);
    cvt_to(s2, wr + W_CAK + 2048*1024, ca_v, INNER*Cm);
    cvt_to(s2, ctx, context, Bb*Ss*Cm);
    gemm_h<0,1>(s2, ctx, wr + W_CAK, kv, Bb*Ss, 2*INNER, Cm, nullptr, nullptr, 0, 1);
    cudaEventRecord(evKV, s2);

    // s3: non-critical weight converts
    cvt_to(s3, wr + W_SAO, sa_o, Dm*INNER);
    cvt_to(s3, wr + W_CAQ, ca_q, INNER*Dm);
    cvt_to(s3, wr + W_CAO, ca_o, Dm*INNER);
    f32_to_f16_ileave<<<(MLPm*Dm/4 + 255)/256, 256, 0, s3>>>(
        (const float4*)ff_gate, (const float4*)ff_up,
        (uint2*)(wr + W_FFGU), MLPm*Dm/4, Dm/4);
    cvt_to(s3, wr + W_FFD, ff_down, Dm*MLPm);
    cudaEventRecord(evW3, s3);

    // main stream: minimal prefix
    cvt_to(0, wr + W_SAQ,             sa_q, INNER*Dm);
    cvt_to(0, wr + W_SAQ + 1024*1024, sa_k, INNER*Dm);
    cvt_to(0, wr + W_SAQ + 2048*1024, sa_v, INNER*Dm);
    mod_kernel<<<(3*3*Dm)/8, 256>>>(cond, n1_mw, n1_mb, n2_mw, n2_mb, n3_mw, n3_mb, mods);

    // ===================== Self attention =====================
    rmsnorm_kernel<<<MQ, 256>>>(x, n1_w, mods + 0*Bb*3*Dm, normed);
    gemm_h<0,1>(0, normed, wr + W_SAQ, qkv, MQ, 3*INNER, Dm, nullptr, nullptr, 0, 1);
    launch_flash(qkv, qkv + INNER, qkv + 2*INNER, ao, Nn, 3*INNER, 3*INNER);
    cudaStreamWaitEvent(0, evW3, 0);
    gemm_h<1,0>(0, ao, wr + W_SAO, x1, MQ, Dm, INNER, x, mods + 0*Bb*3*Dm + 2*Dm, 3*Dm, Nn);

    // ===================== Cross attention =====================
    rmsnorm_kernel<<<MQ, 256>>>(x1, n2_w, mods + 1*Bb*3*Dm, normed);
    gemm_h<0,1>(0, normed, wr + W_CAQ, qkv, MQ, INNER, Dm, nullptr, nullptr, 0, 1);
    cudaStreamWaitEvent(0, evKV, 0);
    launch_flash(qkv, kv, kv + INNER, ao, Ss, INNER, 2*INNER);
    gemm_h<1,0>(0, ao, wr + W_CAO, x2, MQ, Dm, INNER, x1, mods + 1*Bb*3*Dm + 2*Dm, 3*Dm, Nn);

    // ===================== FFN =====================
    rmsnorm_kernel<<<MQ, 256>>>(x2, n3_w, mods + 2*Bb*3*Dm, normed);
    gemm_h<0,2>(0, normed, wr + W_FFGU, hb, MQ, 2*MLPm, Dm, nullptr, nullptr, 0, 1);
    gemm_h<1,0>(0, hb, wr + W_FFD, out, MQ, Dm, MLPm, x2, mods + 2*Bb*3*Dm + 2*Dm, 3*Dm, Nn);
}